// round 10
// baseline (speedup 1.0000x reference)
#include <cuda_runtime.h>
#include <cuda_fp16.h>
#include <cstddef>
#include <cstdint>
#include <math.h>

// ---------------------------------------------------------------------------
// SpatialTranscriptomicsDecoder — GB300 sm_103a. Round 10.
// fp16 2-term split mma GEMMs + NEW: fused GEMM+residual+LayerNorm+split
// epilogue (BN=256 per CTA) removing all standalone LN launches.
// ---------------------------------------------------------------------------

static constexpr int B = 2, P = 196, FD = 1024, G = 2000, D = 256, H = 8, NL = 4, HALF = 128;
static constexpr float ATT_SCALE = 0.17677669529663687f;
static constexpr int MQ = B * G;   // 4000
static constexpr int MP = B * P;   // 392

// ---------------- fp32 workspace ----------------
static constexpr size_t OFF_PATCH = 0;
static constexpr size_t OFF_KV    = OFF_PATCH + (size_t)MP * D;
static constexpr size_t OFF_Q     = OFF_KV    + (size_t)MP * 2 * D;
static constexpr size_t OFF_QB    = OFF_Q     + (size_t)MQ * D;
static constexpr size_t OFF_QP    = OFF_QB    + (size_t)MQ * D;
static constexpr size_t OFF_PP    = OFF_QP    + (size_t)MQ * HALF;
static constexpr size_t WS_TOTAL  = OFF_PP    + (size_t)MP * HALF;
__device__ float g_ws[WS_TOTAL];

// ---------------- fp16 workspace ----------------
static constexpr size_t BQ  = (size_t)MQ * D;
static constexpr size_t HF_QH  = 0;
static constexpr size_t HF_QL  = HF_QH + BQ;
static constexpr size_t HF_L1H = HF_QL + BQ;
static constexpr size_t HF_L1L = HF_L1H + BQ;
static constexpr size_t HF_CXH = HF_L1L + BQ;
static constexpr size_t HF_CXL = HF_CXH + BQ;
static constexpr size_t HF_FH  = HF_CXL + BQ;
static constexpr size_t HF_FL  = HF_FH + (size_t)MQ * 4 * D;
static constexpr size_t HF_PFH = HF_FL + (size_t)MQ * 4 * D;
static constexpr size_t HF_PFL = HF_PFH + (size_t)MP * FD;
static constexpr size_t HF_PEH = HF_PFL + (size_t)MP * FD;
static constexpr size_t HF_PEL = HF_PEH + (size_t)MP * D;
static constexpr size_t HF_PCH = HF_PEL + (size_t)MP * D;
static constexpr size_t HF_PCL = HF_PCH + (size_t)MP * D;
static constexpr size_t HF_WQ  = HF_PCL + (size_t)MP * D;
static constexpr size_t HF_WO  = HF_WQ  + (size_t)NL * D * D;
static constexpr size_t HF_F1  = HF_WO  + (size_t)NL * D * D;
static constexpr size_t HF_F2  = HF_F1  + (size_t)NL * 4 * D * D;
static constexpr size_t HF_HD  = HF_F2  + (size_t)NL * 4 * D * D;
static constexpr size_t HF_WP  = HF_HD  + (size_t)HALF * D;
static constexpr size_t HF_WE  = HF_WP  + (size_t)D * FD;
static constexpr size_t HF_WK  = HF_WE  + (size_t)D * D;
static constexpr size_t HF_TOTAL = HF_WK + (size_t)NL * 2 * D * D;
__device__ __half g_hf[HF_TOTAL];

// ---------------- helpers ----------------
__device__ __forceinline__ float geluf(float x) {
    return 0.5f * x * (1.0f + erff(x * 0.7071067811865476f));
}
__device__ __forceinline__ float softplusf(float x) {
    return fmaxf(x, 0.0f) + __logf(1.0f + __expf(-fabsf(x)));
}
__device__ __forceinline__ void splith(float v, __half& h, __half& l) {
    h = __float2half_rn(v);
    l = __float2half_rn(v - __half2float(h));
}
__device__ __forceinline__ void cpa16(unsigned int dst, const void* src, bool ok) {
    asm volatile("cp.async.ca.shared.global [%0], [%1], 16, %2;"
                 :: "r"(dst), "l"(src), "r"(ok ? 16 : 0) : "memory");
}
__device__ __forceinline__ void cpa_commit() {
    asm volatile("cp.async.commit_group;" ::: "memory");
}
template<int Ng> __device__ __forceinline__ void cpa_waitg() {
    asm volatile("cp.async.wait_group %0;" :: "n"(Ng) : "memory");
}
__device__ __forceinline__ void ldm4(unsigned& r0, unsigned& r1, unsigned& r2, unsigned& r3,
                                     unsigned addr) {
    asm volatile("ldmatrix.sync.aligned.m8n8.x4.shared.b16 {%0,%1,%2,%3}, [%4];"
                 : "=r"(r0), "=r"(r1), "=r"(r2), "=r"(r3) : "r"(addr));
}
__device__ __forceinline__ void mma16816(float* d, const unsigned* a, unsigned b0, unsigned b1) {
    asm volatile(
        "mma.sync.aligned.m16n8k16.row.col.f32.f16.f16.f32 "
        "{%0,%1,%2,%3}, {%4,%5,%6,%7}, {%8,%9}, {%0,%1,%2,%3};"
        : "+f"(d[0]), "+f"(d[1]), "+f"(d[2]), "+f"(d[3])
        : "r"(a[0]), "r"(a[1]), "r"(a[2]), "r"(a[3]), "r"(b0), "r"(b1));
}

// ---------------------------------------------------------------------------
// Standard mma GEMM (BN=64): C = act( (Ah+Al)@Bh^T + bias + R )
// ---------------------------------------------------------------------------
template<int BM>
__global__ void __launch_bounds__(256) mma_gemm_kernel(
    const __half* __restrict__ Ah, const __half* __restrict__ Al,
    const __half* __restrict__ Wh,
    const float* __restrict__ bias, const float* __restrict__ R,
    float* __restrict__ Cf, __half* __restrict__ Ch, __half* __restrict__ Cl,
    int M, int N, int K, int act)
{
    constexpr int STR = 24;
    constexpr int szA = BM * STR * 2;
    constexpr int szW = 64 * STR * 2;
    constexpr int STG = 2 * szA + szW;
    constexpr int MT  = 2;
    constexpr int WMASK  = (BM == 128) ? 3 : 1;
    constexpr int WSHIFT = (BM == 128) ? 2 : 1;
    constexpr int NT8 = (BM == 128) ? 4 : 2;
    constexpr int NP  = NT8 / 2;

    extern __shared__ char smem[];
    const unsigned sb = (unsigned)__cvta_generic_to_shared(smem);

    const int tid = threadIdx.x;
    const int lane = tid & 31, wid = tid >> 5;
    const int wm = wid & WMASK, wn = wid >> WSHIFT;
    const int bm = blockIdx.y * BM;
    const int bn = blockIdx.x * 64;
    const int NC = K >> 4;

    unsigned offA = 0, offW = 0;
    const __half* srcA = nullptr;
    const __half* srcW = nullptr;
    bool aok = false, doA = false, doW = false;
    if (BM == 128) {
        const int rowA = tid >> 1, segA = tid & 1;
        doA = true;
        aok = (bm + rowA) < M;
        offA = (unsigned)((rowA * STR + segA * 8) * 2);
        srcA = Ah + (size_t)(bm + rowA) * K + segA * 8;
        if (tid < 128) {
            const int rowW = tid >> 1, segW = tid & 1;
            doW = true;
            offW = (unsigned)(2 * szA + (rowW * STR + segW * 8) * 2);
            srcW = Wh + (size_t)(bn + rowW) * K + segW * 8;
        }
    } else {
        if (tid < 128) {
            const int rowA = tid >> 1, segA = tid & 1;
            doA = true;
            aok = (bm + rowA) < M;
            offA = (unsigned)((rowA * STR + segA * 8) * 2);
            srcA = Ah + (size_t)(bm + rowA) * K + segA * 8;
        } else {
            const int rowW = (tid - 128) >> 1, segW = tid & 1;
            doW = true;
            offW = (unsigned)(2 * szA + (rowW * STR + segW * 8) * 2);
            srcW = Wh + (size_t)(bn + rowW) * K + segW * 8;
        }
    }
    const ptrdiff_t alDelta = Al - Ah;

    auto loadChunk = [&](int kc, int s) {
        const int o = kc << 4;
        const unsigned base = sb + s * STG;
        if (doA) {
            cpa16(base + offA, srcA + o, aok);
            cpa16(base + szA + offA, srcA + alDelta + o, aok);
        }
        if (doW) cpa16(base + offW, srcW + o, true);
        cpa_commit();
    };

    unsigned aoffH[MT], boffH[NP];
    {
        const int ar = wm * 32 + (lane & 15);
        const int ak = (lane >> 4) * 8;
        const int br = wn * (NT8 * 8) + (lane & 7) + ((lane >> 4) << 3);
        const int bk = ((lane >> 3) & 1) * 8;
#pragma unroll
        for (int t = 0; t < MT; t++) aoffH[t] = (unsigned)(((ar + t * 16) * STR + ak) * 2);
#pragma unroll
        for (int p = 0; p < NP; p++) boffH[p] = (unsigned)(2 * szA + ((br + p * 16) * STR + bk) * 2);
    }

    loadChunk(0, 0);
    loadChunk(1, 1);
    loadChunk(2, 2);

    float acc[MT][NT8][4];
#pragma unroll
    for (int i = 0; i < MT; i++)
#pragma unroll
        for (int j = 0; j < NT8; j++)
#pragma unroll
            for (int k = 0; k < 4; k++) acc[i][j][k] = 0.f;

    for (int kc = 0; kc < NC; kc++) {
        cpa_waitg<2>();
        __syncthreads();
        const int s = kc & 3;
        const int nk = kc + 3;
        if (nk < NC) loadChunk(nk, nk & 3);
        else cpa_commit();

        const unsigned stg = sb + s * STG;
        unsigned ah[MT][4], al[MT][4], bh[NP][4];
#pragma unroll
        for (int t = 0; t < MT; t++) {
            ldm4(ah[t][0], ah[t][1], ah[t][2], ah[t][3], stg + aoffH[t]);
            ldm4(al[t][0], al[t][1], al[t][2], al[t][3], stg + aoffH[t] + szA);
        }
#pragma unroll
        for (int p = 0; p < NP; p++)
            ldm4(bh[p][0], bh[p][1], bh[p][2], bh[p][3], stg + boffH[p]);
#pragma unroll
        for (int mt = 0; mt < MT; mt++) {
#pragma unroll
            for (int nt = 0; nt < NT8; nt++) {
                const int p = nt >> 1, nh = (nt & 1) << 1;
                mma16816(acc[mt][nt], ah[mt], bh[p][nh], bh[p][nh + 1]);
                mma16816(acc[mt][nt], al[mt], bh[p][nh], bh[p][nh + 1]);
            }
        }
    }

    const int rowb = bm + wm * 32 + (lane >> 2);
    const int colb = bn + wn * (NT8 * 8) + 2 * (lane & 3);
#pragma unroll
    for (int mt = 0; mt < MT; mt++) {
#pragma unroll
        for (int nt = 0; nt < NT8; nt++) {
            const int col = colb + nt * 8;
            float2 b2 = make_float2(0.f, 0.f);
            if (bias) b2 = *(const float2*)(bias + col);
#pragma unroll
            for (int hh = 0; hh < 2; hh++) {
                const int row = rowb + mt * 16 + hh * 8;
                if (row >= M) continue;
                float v0 = acc[mt][nt][hh * 2 + 0] + b2.x;
                float v1 = acc[mt][nt][hh * 2 + 1] + b2.y;
                if (R) {
                    float2 r2 = *(const float2*)(R + (size_t)row * N + col);
                    v0 += r2.x; v1 += r2.y;
                }
                if (act == 1) { v0 = geluf(v0); v1 = geluf(v1); }
                if (Cf) *(float2*)(Cf + (size_t)row * N + col) = make_float2(v0, v1);
                if (Ch) {
                    __half h0, l0, h1, l1;
                    splith(v0, h0, l0);
                    splith(v1, h1, l1);
                    *(__half2*)(Ch + (size_t)row * N + col) = __halves2half2(h0, h1);
                    *(__half2*)(Cl + (size_t)row * N + col) = __halves2half2(l0, l1);
                }
            }
        }
    }
}

static constexpr int MMASM128 = 4 * (2 * 128 * 24 * 2 + 64 * 24 * 2);  // 61440
static constexpr int MMASM64  = 4 * (2 * 64 * 24 * 2 + 64 * 24 * 2);   // 36864

// ---------------------------------------------------------------------------
// Fused GEMM + residual + LayerNorm + split. BM=64, BN=N=256 fixed.
// Y = LN( (Ah+Al)@Wh^T + bias + R ) * gamma + beta
// Outputs: fp32 Yf (always), optional fp16 split Yh/Yl.
// grid (1, ceil(M/64)), 256 threads, 8 warps (wm=wid&1, wn=wid>>1), tile 32x64.
// ---------------------------------------------------------------------------
__global__ void __launch_bounds__(256) mma_gemm_ln_kernel(
    const __half* __restrict__ Ah, const __half* __restrict__ Al,
    const __half* __restrict__ Wh,
    const float* __restrict__ bias, const float* __restrict__ R,
    const float* __restrict__ gamma, const float* __restrict__ beta,
    float* __restrict__ Yf, __half* __restrict__ Yh, __half* __restrict__ Yl,
    int M, int K)
{
    constexpr int STR = 24;
    constexpr int szA = 64 * STR * 2;       // 3072 B
    constexpr int szW = 256 * STR * 2;      // 12288 B
    constexpr int STG = 2 * szA + szW;      // 18432 B
    constexpr int MT = 2, NT8 = 8, NP = 4;

    extern __shared__ char smem[];
    const unsigned sb = (unsigned)__cvta_generic_to_shared(smem);

    const int tid = threadIdx.x;
    const int lane = tid & 31, wid = tid >> 5;
    const int wm = wid & 1, wn = wid >> 1;
    const int bm = blockIdx.y * 64;
    const int NC = K >> 4;

    // loaders: A (h or l by tid<128): slot=tid&127 -> row,seg; W: row=tid, segs 0,1
    const int rowA = (tid & 127) >> 1, segA = tid & 1;
    const bool aok = (bm + rowA) < M;
    const unsigned offA = (unsigned)((tid < 128 ? 0 : szA) + (rowA * STR + segA * 8) * 2);
    const __half* srcA = (tid < 128 ? Ah : Al) + (size_t)(bm + rowA) * K + segA * 8;
    const unsigned offW0 = (unsigned)(2 * szA + (tid * STR) * 2);
    const unsigned offW1 = (unsigned)(2 * szA + (tid * STR + 8) * 2);
    const __half* srcW = Wh + (size_t)tid * K;

    auto loadChunk = [&](int kc, int s) {
        const int o = kc << 4;
        const unsigned base = sb + s * STG;
        cpa16(base + offA, srcA + o, aok);
        cpa16(base + offW0, srcW + o, true);
        cpa16(base + offW1, srcW + o + 8, true);
        cpa_commit();
    };

    unsigned aoffH[MT], boffH[NP];
    {
        const int ar = wm * 32 + (lane & 15);
        const int ak = (lane >> 4) * 8;
        const int br = wn * 64 + (lane & 7) + ((lane >> 4) << 3);
        const int bk = ((lane >> 3) & 1) * 8;
#pragma unroll
        for (int t = 0; t < MT; t++) aoffH[t] = (unsigned)(((ar + t * 16) * STR + ak) * 2);
#pragma unroll
        for (int p = 0; p < NP; p++) boffH[p] = (unsigned)(2 * szA + ((br + p * 16) * STR + bk) * 2);
    }

    loadChunk(0, 0);
    loadChunk(1, 1);
    loadChunk(2, 2);

    float acc[MT][NT8][4];
#pragma unroll
    for (int i = 0; i < MT; i++)
#pragma unroll
        for (int j = 0; j < NT8; j++)
#pragma unroll
            for (int k = 0; k < 4; k++) acc[i][j][k] = 0.f;

    for (int kc = 0; kc < NC; kc++) {
        cpa_waitg<2>();
        __syncthreads();
        const int s = kc & 3;
        const int nk = kc + 3;
        if (nk < NC) loadChunk(nk, nk & 3);
        else cpa_commit();

        const unsigned stg = sb + s * STG;
        unsigned ah[MT][4], al[MT][4], bh[NP][4];
#pragma unroll
        for (int t = 0; t < MT; t++) {
            ldm4(ah[t][0], ah[t][1], ah[t][2], ah[t][3], stg + aoffH[t]);
            ldm4(al[t][0], al[t][1], al[t][2], al[t][3], stg + aoffH[t] + szA);
        }
#pragma unroll
        for (int p = 0; p < NP; p++)
            ldm4(bh[p][0], bh[p][1], bh[p][2], bh[p][3], stg + boffH[p]);
#pragma unroll
        for (int mt = 0; mt < MT; mt++) {
#pragma unroll
            for (int nt = 0; nt < NT8; nt++) {
                const int p = nt >> 1, nh = (nt & 1) << 1;
                mma16816(acc[mt][nt], ah[mt], bh[p][nh], bh[p][nh + 1]);
                mma16816(acc[mt][nt], al[mt], bh[p][nh], bh[p][nh + 1]);
            }
        }
    }

    // ---- fused epilogue: +bias +R, LN over 256 cols, write fp32 (+split) ----
    cpa_waitg<0>();
    __syncthreads();                      // stage smem now reusable as scratch
    float2* part = (float2*)smem;         // part[wn*64 + localrow], 4*64*8B = 2KB

    const int lrow0 = wm * 32 + (lane >> 2);     // local row base (within 64)
    const int colb = wn * 64 + 2 * (lane & 3);

    // add bias + residual in place; accumulate per-row partial sums
    float ps[MT][2], pq[MT][2];
#pragma unroll
    for (int mt = 0; mt < MT; mt++)
#pragma unroll
        for (int hh = 0; hh < 2; hh++) { ps[mt][hh] = 0.f; pq[mt][hh] = 0.f; }

#pragma unroll
    for (int nt = 0; nt < NT8; nt++) {
        const int col = colb + nt * 8;
        float2 b2 = make_float2(0.f, 0.f);
        if (bias) b2 = *(const float2*)(bias + col);
#pragma unroll
        for (int mt = 0; mt < MT; mt++) {
#pragma unroll
            for (int hh = 0; hh < 2; hh++) {
                const int row = bm + lrow0 + mt * 16 + hh * 8;
                float v0 = acc[mt][nt][hh * 2 + 0] + b2.x;
                float v1 = acc[mt][nt][hh * 2 + 1] + b2.y;
                if (R && row < M) {
                    float2 r2 = *(const float2*)(R + (size_t)row * 256 + col);
                    v0 += r2.x; v1 += r2.y;
                }
                acc[mt][nt][hh * 2 + 0] = v0;
                acc[mt][nt][hh * 2 + 1] = v1;
                ps[mt][hh] += v0 + v1;
                pq[mt][hh] += v0 * v0 + v1 * v1;
            }
        }
    }
    // reduce across the 4 lanes sharing each row (lane&3 varies)
#pragma unroll
    for (int mt = 0; mt < MT; mt++)
#pragma unroll
        for (int hh = 0; hh < 2; hh++) {
            ps[mt][hh] += __shfl_xor_sync(0xffffffffu, ps[mt][hh], 1);
            ps[mt][hh] += __shfl_xor_sync(0xffffffffu, ps[mt][hh], 2);
            pq[mt][hh] += __shfl_xor_sync(0xffffffffu, pq[mt][hh], 1);
            pq[mt][hh] += __shfl_xor_sync(0xffffffffu, pq[mt][hh], 2);
        }
    if ((lane & 3) == 0) {
#pragma unroll
        for (int mt = 0; mt < MT; mt++)
#pragma unroll
            for (int hh = 0; hh < 2; hh++) {
                const int lr = lrow0 + mt * 16 + hh * 8;
                part[wn * 64 + lr] = make_float2(ps[mt][hh], pq[mt][hh]);
            }
    }
    __syncthreads();

    float mean[MT][2], rstd[MT][2];
#pragma unroll
    for (int mt = 0; mt < MT; mt++)
#pragma unroll
        for (int hh = 0; hh < 2; hh++) {
            const int lr = lrow0 + mt * 16 + hh * 8;
            float s = 0.f, qq = 0.f;
#pragma unroll
            for (int w = 0; w < 4; w++) {
                float2 p = part[w * 64 + lr];
                s += p.x; qq += p.y;
            }
            float m = s * (1.f / 256.f);
            float v = qq * (1.f / 256.f) - m * m;
            mean[mt][hh] = m;
            rstd[mt][hh] = rsqrtf(v + 1e-5f);
        }

#pragma unroll
    for (int nt = 0; nt < NT8; nt++) {
        const int col = colb + nt * 8;
        float2 g2 = *(const float2*)(gamma + col);
        float2 be2 = *(const float2*)(beta + col);
#pragma unroll
        for (int mt = 0; mt < MT; mt++) {
#pragma unroll
            for (int hh = 0; hh < 2; hh++) {
                const int row = bm + lrow0 + mt * 16 + hh * 8;
                if (row >= M) continue;
                float v0 = (acc[mt][nt][hh * 2 + 0] - mean[mt][hh]) * rstd[mt][hh] * g2.x + be2.x;
                float v1 = (acc[mt][nt][hh * 2 + 1] - mean[mt][hh]) * rstd[mt][hh] * g2.y + be2.y;
                *(float2*)(Yf + (size_t)row * 256 + col) = make_float2(v0, v1);
                if (Yh) {
                    __half h0, l0, h1, l1;
                    splith(v0, h0, l0);
                    splith(v1, h1, l1);
                    *(__half2*)(Yh + (size_t)row * 256 + col) = __halves2half2(h0, h1);
                    *(__half2*)(Yl + (size_t)row * 256 + col) = __halves2half2(l0, l1);
                }
            }
        }
    }
}
static constexpr int MMASMLN = 4 * (2 * 64 * 24 * 2 + 256 * 24 * 2);   // 73728

// ---------------------------------------------------------------------------
// weight convert: fp32 -> fp16, 23 segments
// ---------------------------------------------------------------------------
struct CSeg { const float* src; __half* h; int blk_off; };
struct CTable { CSeg seg[23]; };
__global__ void __launch_bounds__(256) wconv_kernel(CTable t)
{
    const int bt = blockIdx.x;
    int s = 0;
#pragma unroll
    for (int i = 1; i < 23; i++) if (t.seg[i].blk_off <= bt) s = i;
    const CSeg sg = t.seg[s];
    const int idx = (bt - sg.blk_off) * 1024 + threadIdx.x * 4;
    float4 v = *(const float4*)(sg.src + idx);
    *(__half2*)(sg.h + idx)     = __halves2half2(__float2half_rn(v.x), __float2half_rn(v.y));
    *(__half2*)(sg.h + idx + 2) = __halves2half2(__float2half_rn(v.z), __float2half_rn(v.w));
}

__global__ void __launch_bounds__(256) asplit_kernel(
    const float* __restrict__ src, __half* __restrict__ h,
    __half* __restrict__ l, int n)
{
    int idx = (blockIdx.x * 256 + threadIdx.x) * 4;
    if (idx >= n) return;
    float4 v = *(const float4*)(src + idx);
    __half hh, ll;
    splith(v.x, hh, ll); h[idx + 0] = hh; l[idx + 0] = ll;
    splith(v.y, hh, ll); h[idx + 1] = hh; l[idx + 1] = ll;
    splith(v.z, hh, ll); h[idx + 2] = hh; l[idx + 2] = ll;
    splith(v.w, hh, ll); h[idx + 3] = hh; l[idx + 3] = ll;
}

__global__ void pe_kernel(const int* __restrict__ coords, const float* __restrict__ re,
                          const float* __restrict__ ce,
                          __half* __restrict__ peh, __half* __restrict__ pel)
{
    int idx = blockIdx.x * blockDim.x + threadIdx.x;
    if (idx >= B * P * D) return;
    int d = idx & 255;
    int bp = idx >> 8;
    int r = coords[bp * 2 + 0];
    int c = coords[bp * 2 + 1];
    r = min(max(r, 0), 255);
    c = min(max(c, 0), 255);
    float v = (d < 128) ? re[r * 128 + d] : ce[c * 128 + (d - 128)];
    __half h, l;
    splith(v, h, l);
    peh[idx] = h;
    pel[idx] = l;
}

__global__ void qinit_kernel(const float* __restrict__ gq, float* __restrict__ q,
                             __half* __restrict__ qh, __half* __restrict__ ql)
{
    int idx = blockIdx.x * blockDim.x + threadIdx.x;
    if (idx >= B * G * D) return;
    float v = gq[idx % (G * D)];
    q[idx] = v;
    __half h, l;
    splith(v, h, l);
    qh[idx] = h;
    ql[idx] = l;
}

// ---------------------------------------------------------------------------
// Cross-attention; outputs fp16 hi/lo context.
// ---------------------------------------------------------------------------
__global__ void __launch_bounds__(256) attn_kernel(
    const float* __restrict__ Q, const float* __restrict__ KV,
    __half* __restrict__ cxh, __half* __restrict__ cxl)
{
    __shared__ float Kt[32][196];
    const int bh = blockIdx.x;
    const int b = bh >> 3, h = bh & 7;
    const int tid = threadIdx.x;
    const int lane = tid & 31, w = tid >> 5;

    const float* KVb = KV + (size_t)b * P * 512;
    for (int i = tid; i < P * 32; i += 256) {
        int p = i >> 5, d = i & 31;
        Kt[d][p] = KVb[(size_t)p * 512 + h * 32 + d] * ATT_SCALE;
    }
    __syncthreads();

    const int g0 = (blockIdx.y * 8 + w) * 4;
    if (g0 >= G) return;

    float qr[4];
#pragma unroll
    for (int i = 0; i < 4; i++)
        qr[i] = Q[(size_t)(b * G + g0 + i) * 256 + h * 32 + lane];

    float sc[4][7];
#pragma unroll
    for (int i = 0; i < 4; i++)
#pragma unroll
        for (int j = 0; j < 7; j++) sc[i][j] = 0.f;

#pragma unroll 4
    for (int d = 0; d < 32; d++) {
        float k0 = Kt[d][lane];
        float k1 = Kt[d][32 + lane];
        float k2 = Kt[d][64 + lane];
        float k3 = Kt[d][96 + lane];
        float k4 = Kt[d][128 + lane];
        float k5 = Kt[d][160 + lane];
        float k6 = (lane < 4) ? Kt[d][192 + lane] : 0.f;
#pragma unroll
        for (int i = 0; i < 4; i++) {
            float qd = __shfl_sync(0xffffffffu, qr[i], d);
            sc[i][0] = fmaf(qd, k0, sc[i][0]);
            sc[i][1] = fmaf(qd, k1, sc[i][1]);
            sc[i][2] = fmaf(qd, k2, sc[i][2]);
            sc[i][3] = fmaf(qd, k3, sc[i][3]);
            sc[i][4] = fmaf(qd, k4, sc[i][4]);
            sc[i][5] = fmaf(qd, k5, sc[i][5]);
            sc[i][6] = fmaf(qd, k6, sc[i][6]);
        }
    }

#pragma unroll
    for (int i = 0; i < 4; i++) {
        if (lane >= 4) sc[i][6] = -1e30f;
        float m = sc[i][0];
#pragma unroll
        for (int j = 1; j < 7; j++) m = fmaxf(m, sc[i][j]);
#pragma unroll
        for (int o = 16; o; o >>= 1) m = fmaxf(m, __shfl_xor_sync(0xffffffffu, m, o));
        float s = 0.f;
#pragma unroll
        for (int j = 0; j < 7; j++) { float e = __expf(sc[i][j] - m); sc[i][j] = e; s += e; }
#pragma unroll
        for (int o = 16; o; o >>= 1) s += __shfl_xor_sync(0xffffffffu, s, o);
        float inv = 1.0f / s;
#pragma unroll
        for (int j = 0; j < 7; j++) sc[i][j] *= inv;
    }

    float cx[4] = {0.f, 0.f, 0.f, 0.f};
    const float* Vb = KVb + 256 + h * 32 + lane;
#pragma unroll
    for (int jj = 0; jj < 7; jj++) {
        const int kmax = (jj == 6) ? 4 : 32;
        for (int src = 0; src < kmax; src++) {
            float v = Vb[(size_t)(jj * 32 + src) * 512];
#pragma unroll
            for (int i = 0; i < 4; i++) {
                float a = __shfl_sync(0xffffffffu, sc[i][jj], src);
                cx[i] = fmaf(a, v, cx[i]);
            }
        }
    }
#pragma unroll
    for (int i = 0; i < 4; i++) {
        size_t off = (size_t)(b * G + g0 + i) * 256 + h * 32 + lane;
        __half hh, ll;
        splith(cx[i], hh, ll);
        cxh[off] = hh;
        cxl[off] = ll;
    }
}

__global__ void __launch_bounds__(256) head_kernel(
    const float* __restrict__ qp, const float* __restrict__ pp, float* __restrict__ out)
{
    const int bp = blockIdx.y;
    const int b = (bp >= P) ? 1 : 0;
    const int g = blockIdx.x * 8 + (threadIdx.x >> 5);
    const int hh = (threadIdx.x & 31) << 2;
    float4 pv = *(const float4*)(pp + (size_t)bp * HALF + hh);
    float4 qv = *(const float4*)(qp + (size_t)(b * G + g) * HALF + hh);
    float4 o;
    o.x = softplusf(pv.x + qv.x);
    o.y = softplusf(pv.y + qv.y);
    o.z = softplusf(pv.z + qv.z);
    o.w = softplusf(pv.w + qv.w);
    *(float4*)(out + ((size_t)bp * G + g) * HALF + hh) = o;
}

// ---------------------------------------------------------------------------
extern "C" void kernel_launch(void* const* d_in, const int* in_sizes, int n_in,
                              void* d_out, int out_size)
{
    (void)in_sizes; (void)n_in; (void)out_size;
    const float* patch_features = (const float*)d_in[0];
    const int*   patch_coords   = (const int*)d_in[1];
    const float* patch_proj_w   = (const float*)d_in[2];
    const float* patch_proj_b   = (const float*)d_in[3];
    const float* patch_ln_g     = (const float*)d_in[4];
    const float* patch_ln_b     = (const float*)d_in[5];
    const float* row_embed      = (const float*)d_in[6];
    const float* col_embed      = (const float*)d_in[7];
    const float* pe_proj_w      = (const float*)d_in[8];
    const float* pe_proj_b      = (const float*)d_in[9];
    const float* gene_queries   = (const float*)d_in[10];
    const float* in_proj_w      = (const float*)d_in[11];
    const float* in_proj_b      = (const float*)d_in[12];
    const float* out_w          = (const float*)d_in[13];
    const float* out_b          = (const float*)d_in[14];
    const float* ff1_w          = (const float*)d_in[15];
    const float* ff1_b          = (const float*)d_in[16];
    const float* ff2_w          = (const float*)d_in[17];
    const float* ff2_b          = (const float*)d_in[18];
    const float* ln1_g          = (const float*)d_in[19];
    const float* ln1_b          = (const float*)d_in[20];
    const float* ln2_g          = (const float*)d_in[21];
    const float* ln2_b          = (const float*)d_in[22];
    const float* head_w1        = (const float*)d_in[23];
    const float* head_b1        = (const float*)d_in[24];
    float* out = (float*)d_out;

    cudaFuncSetAttribute(mma_gemm_kernel<128>, cudaFuncAttributeMaxDynamicSharedMemorySize, MMASM128);
    cudaFuncSetAttribute(mma_gemm_kernel<64>,  cudaFuncAttributeMaxDynamicSharedMemorySize, MMASM64);
    cudaFuncSetAttribute(mma_gemm_ln_kernel,   cudaFuncAttributeMaxDynamicSharedMemorySize, MMASMLN);

    float* ws = nullptr;
    cudaGetSymbolAddress((void**)&ws, g_ws);
    __half* hf = nullptr;
    cudaGetSymbolAddress((void**)&hf, g_hf);

    float* patch_emb = ws + OFF_PATCH;
    float* kv        = ws + OFF_KV;
    float* q         = ws + OFF_Q;
    float* Qb        = ws + OFF_QB;
    float* qproj     = ws + OFF_QP;
    float* pproj     = ws + OFF_PP;

    __half* qh  = hf + HF_QH;
    __half* ql  = hf + HF_QL;
    __half* l1h = hf + HF_L1H;
    __half* l1l = hf + HF_L1L;
    __half* cxh = hf + HF_CXH;
    __half* cxl = hf + HF_CXL;
    __half* fh  = hf + HF_FH;
    __half* fl  = hf + HF_FL;
    __half* pfh = hf + HF_PFH;
    __half* pfl = hf + HF_PFL;
    __half* peh = hf + HF_PEH;
    __half* pel = hf + HF_PEL;
    __half* pch = hf + HF_PCH;
    __half* pcl = hf + HF_PCL;

    // ---- one-time weight convert ----
    CTable ct;
    int total_blk;
    {
        int seg = 0, boff = 0;
        auto add = [&](const float* src, size_t ho, int count) {
            ct.seg[seg] = { src, hf + ho, boff };
            boff += count / 1024;
            seg++;
        };
        for (int l = 0; l < NL; l++)
            add(in_proj_w + (size_t)l * 3 * D * D, HF_WQ + (size_t)l * D * D, D * D);
        for (int l = 0; l < NL; l++)
            add(out_w + (size_t)l * D * D, HF_WO + (size_t)l * D * D, D * D);
        for (int l = 0; l < NL; l++)
            add(ff1_w + (size_t)l * 4 * D * D, HF_F1 + (size_t)l * 4 * D * D, 4 * D * D);
        for (int l = 0; l < NL; l++)
            add(ff2_w + (size_t)l * 4 * D * D, HF_F2 + (size_t)l * 4 * D * D, 4 * D * D);
        add(head_w1, HF_HD, HALF * D);
        add(patch_proj_w, HF_WP, D * FD);
        add(pe_proj_w, HF_WE, D * D);
        for (int l = 0; l < NL; l++)
            add(in_proj_w + (size_t)l * 3 * D * D + D * D, HF_WK + (size_t)l * 2 * D * D, 2 * D * D);
        total_blk = boff;
    }
    wconv_kernel<<<total_blk, 256>>>(ct);
    asplit_kernel<<<(MP * FD / 4 + 255) / 256, 256>>>(patch_features, pfh, pfl, MP * FD);

    const int MT64  = (MQ + 63) / 64;     // 63
    const int MT128 = (MQ + 127) / 128;   // 32
    const int MTP   = (MP + 63) / 64;     // 7

    // ---- Stage A: patch proj + LN fused; PE gather; PE proj (+residual) ----
    mma_gemm_ln_kernel<<<dim3(1, MTP), 256, MMASMLN>>>(
        pfh, pfl, hf + HF_WP, patch_proj_b, nullptr, patch_ln_g, patch_ln_b,
        patch_emb, nullptr, nullptr, MP, FD);
    pe_kernel<<<(B * P * D + 255) / 256, 256>>>(patch_coords, row_embed, col_embed, peh, pel);
    mma_gemm_kernel<64><<<dim3(D / 64, MTP), 256, MMASM64>>>(
        peh, pel, hf + HF_WE, pe_proj_b, patch_emb,
        nullptr, pch, pcl, MP, D, D, 0);
    qinit_kernel<<<(MQ * D + 255) / 256, 256>>>(gene_queries, q, qh, ql);

    // ---- Stage B: decoder layers (6 launches/layer) ----
    for (int l = 0; l < NL; l++) {
        const float* bq  = in_proj_b + (size_t)l * 3 * D;
        const float* bkv = bq + D;
        mma_gemm_kernel<64><<<dim3(D / 64, MT64), 256, MMASM64>>>(
            qh, ql, hf + HF_WQ + (size_t)l * D * D,
            bq, nullptr, Qb, nullptr, nullptr, MQ, D, D, 0);
        mma_gemm_kernel<64><<<dim3(2 * D / 64, MTP), 256, MMASM64>>>(
            pch, pcl, hf + HF_WK + (size_t)l * 2 * D * D,
            bkv, nullptr, kv, nullptr, nullptr, MP, 2 * D, D, 0);
        attn_kernel<<<dim3(B * H, (G + 31) / 32), 256>>>(Qb, kv, cxh, cxl);
        // out-proj + residual(q) + ln1 fused -> new q + l1 split
        mma_gemm_ln_kernel<<<dim3(1, MT64), 256, MMASMLN>>>(
            cxh, cxl, hf + HF_WO + (size_t)l * D * D,
            out_b + (size_t)l * D, q, ln1_g + (size_t)l * D, ln1_b + (size_t)l * D,
            q, l1h, l1l, MQ, D);
        mma_gemm_kernel<128><<<dim3(4 * D / 64, MT128), 256, MMASM128>>>(
            l1h, l1l, hf + HF_F1 + (size_t)l * 4 * D * D,
            ff1_b + (size_t)l * 4 * D, nullptr, nullptr, fh, fl, MQ, 4 * D, D, 1);
        // ff2 + residual(q) + ln2 fused -> new q + q split
        mma_gemm_ln_kernel<<<dim3(1, MT64), 256, MMASMLN>>>(
            fh, fl, hf + HF_F2 + (size_t)l * 4 * D * D,
            ff2_b + (size_t)l * D, q, ln2_g + (size_t)l * D, ln2_b + (size_t)l * D,
            q, qh, ql, MQ, 4 * D);
    }

    // ---- Stage C ----
    mma_gemm_kernel<64><<<dim3(HALF / 64, MT64), 256, MMASM64>>>(
        qh, ql, hf + HF_HD, head_b1, nullptr,
        qproj, nullptr, nullptr, MQ, HALF, D, 0);
    mma_gemm_kernel<64><<<dim3(HALF / 64, MTP), 256, MMASM64>>>(
        pch, pcl, hf + HF_HD, nullptr, nullptr,
        pproj, nullptr, nullptr, MP, HALF, D, 0);
    head_kernel<<<dim3(G / 8, B * P), 256>>>(qproj, pproj, out);
}

// round 11
// speedup vs baseline: 1.1288x; 1.1288x over previous
#include <cuda_runtime.h>
#include <cuda_fp16.h>
#include <cstddef>
#include <cstdint>
#include <math.h>

// ---------------------------------------------------------------------------
// SpatialTranscriptomicsDecoder — GB300 sm_103a. Round 11.
// R9 base (fp16 2-term split mma GEMMs) + launch-count reduction:
// dual-GEMM kernel (Qproj+KV merged, head GEMMs merged) + merged prep kernel.
// ---------------------------------------------------------------------------

static constexpr int B = 2, P = 196, FD = 1024, G = 2000, D = 256, H = 8, NL = 4, HALF = 128;
static constexpr float ATT_SCALE = 0.17677669529663687f;
static constexpr int MQ = B * G;   // 4000
static constexpr int MP = B * P;   // 392

// ---------------- fp32 workspace ----------------
static constexpr size_t OFF_PATCH = 0;
static constexpr size_t OFF_TMP   = OFF_PATCH + (size_t)MP * D;
static constexpr size_t OFF_KV    = OFF_TMP   + (size_t)MP * D;
static constexpr size_t OFF_Q     = OFF_KV    + (size_t)MP * 2 * D;
static constexpr size_t OFF_QB    = OFF_Q     + (size_t)MQ * D;
static constexpr size_t OFF_ATT   = OFF_QB    + (size_t)MQ * D;
static constexpr size_t OFF_QP    = OFF_ATT   + (size_t)MQ * D;
static constexpr size_t OFF_PP    = OFF_QP    + (size_t)MQ * HALF;
static constexpr size_t WS_TOTAL  = OFF_PP    + (size_t)MP * HALF;
__device__ float g_ws[WS_TOTAL];

// ---------------- fp16 workspace ----------------
static constexpr size_t BQ  = (size_t)MQ * D;
static constexpr size_t HF_QH  = 0;
static constexpr size_t HF_QL  = HF_QH + BQ;
static constexpr size_t HF_L1H = HF_QL + BQ;
static constexpr size_t HF_L1L = HF_L1H + BQ;
static constexpr size_t HF_CXH = HF_L1L + BQ;
static constexpr size_t HF_CXL = HF_CXH + BQ;
static constexpr size_t HF_FH  = HF_CXL + BQ;
static constexpr size_t HF_FL  = HF_FH + (size_t)MQ * 4 * D;
static constexpr size_t HF_PFH = HF_FL + (size_t)MQ * 4 * D;
static constexpr size_t HF_PFL = HF_PFH + (size_t)MP * FD;
static constexpr size_t HF_PEH = HF_PFL + (size_t)MP * FD;
static constexpr size_t HF_PEL = HF_PEH + (size_t)MP * D;
static constexpr size_t HF_PCH = HF_PEL + (size_t)MP * D;
static constexpr size_t HF_PCL = HF_PCH + (size_t)MP * D;
static constexpr size_t HF_WQ  = HF_PCL + (size_t)MP * D;
static constexpr size_t HF_WO  = HF_WQ  + (size_t)NL * D * D;
static constexpr size_t HF_F1  = HF_WO  + (size_t)NL * D * D;
static constexpr size_t HF_F2  = HF_F1  + (size_t)NL * 4 * D * D;
static constexpr size_t HF_HD  = HF_F2  + (size_t)NL * 4 * D * D;
static constexpr size_t HF_WP  = HF_HD  + (size_t)HALF * D;
static constexpr size_t HF_WE  = HF_WP  + (size_t)D * FD;
static constexpr size_t HF_WK  = HF_WE  + (size_t)D * D;
static constexpr size_t HF_TOTAL = HF_WK + (size_t)NL * 2 * D * D;
__device__ __half g_hf[HF_TOTAL];

// ---------------- helpers ----------------
__device__ __forceinline__ float geluf(float x) {
    return 0.5f * x * (1.0f + erff(x * 0.7071067811865476f));
}
__device__ __forceinline__ float softplusf(float x) {
    return fmaxf(x, 0.0f) + __logf(1.0f + __expf(-fabsf(x)));
}
__device__ __forceinline__ void splith(float v, __half& h, __half& l) {
    h = __float2half_rn(v);
    l = __float2half_rn(v - __half2float(h));
}
__device__ __forceinline__ void cpa16(unsigned int dst, const void* src, bool ok) {
    asm volatile("cp.async.ca.shared.global [%0], [%1], 16, %2;"
                 :: "r"(dst), "l"(src), "r"(ok ? 16 : 0) : "memory");
}
__device__ __forceinline__ void cpa_commit() {
    asm volatile("cp.async.commit_group;" ::: "memory");
}
template<int Ng> __device__ __forceinline__ void cpa_waitg() {
    asm volatile("cp.async.wait_group %0;" :: "n"(Ng) : "memory");
}
__device__ __forceinline__ void ldm4(unsigned& r0, unsigned& r1, unsigned& r2, unsigned& r3,
                                     unsigned addr) {
    asm volatile("ldmatrix.sync.aligned.m8n8.x4.shared.b16 {%0,%1,%2,%3}, [%4];"
                 : "=r"(r0), "=r"(r1), "=r"(r2), "=r"(r3) : "r"(addr));
}
__device__ __forceinline__ void mma16816(float* d, const unsigned* a, unsigned b0, unsigned b1) {
    asm volatile(
        "mma.sync.aligned.m16n8k16.row.col.f32.f16.f16.f32 "
        "{%0,%1,%2,%3}, {%4,%5,%6,%7}, {%8,%9}, {%0,%1,%2,%3};"
        : "+f"(d[0]), "+f"(d[1]), "+f"(d[2]), "+f"(d[3])
        : "r"(a[0]), "r"(a[1]), "r"(a[2]), "r"(a[3]), "r"(b0), "r"(b1));
}

// ---------------------------------------------------------------------------
// GEMM argument bundle + device impl (fp16 2-term split):
// C[M,N] = act( (Ah+Al) @ Wh^T + bias + R )
// ---------------------------------------------------------------------------
struct GArgs {
    const __half* Ah; const __half* Al; const __half* Wh;
    const float* bias; const float* R;
    float* Cf; __half* Ch; __half* Cl;
    int M, N, K, act, ntx;   // ntx = N/64
};

template<int BM>
__device__ __forceinline__ void mma_gemm_impl(const GArgs& g, int bx, int by)
{
    constexpr int STR = 24;
    constexpr int szA = BM * STR * 2;
    constexpr int szW = 64 * STR * 2;
    constexpr int STG = 2 * szA + szW;
    constexpr int MT  = 2;
    constexpr int WMASK  = (BM == 128) ? 3 : 1;
    constexpr int WSHIFT = (BM == 128) ? 2 : 1;
    constexpr int NT8 = (BM == 128) ? 4 : 2;
    constexpr int NP  = NT8 / 2;

    extern __shared__ char smem[];
    const unsigned sb = (unsigned)__cvta_generic_to_shared(smem);

    const int tid = threadIdx.x;
    const int lane = tid & 31, wid = tid >> 5;
    const int wm = wid & WMASK, wn = wid >> WSHIFT;
    const int bm = by * BM;
    const int bn = bx * 64;
    const int NC = g.K >> 4;
    const int M = g.M, N = g.N, K = g.K;

    unsigned offA = 0, offW = 0;
    const __half* srcA = nullptr;
    const __half* srcW = nullptr;
    bool aok = false, doA = false, doW = false;
    if (BM == 128) {
        const int rowA = tid >> 1, segA = tid & 1;
        doA = true;
        aok = (bm + rowA) < M;
        offA = (unsigned)((rowA * STR + segA * 8) * 2);
        srcA = g.Ah + (size_t)(bm + rowA) * K + segA * 8;
        if (tid < 128) {
            const int rowW = tid >> 1, segW = tid & 1;
            doW = true;
            offW = (unsigned)(2 * szA + (rowW * STR + segW * 8) * 2);
            srcW = g.Wh + (size_t)(bn + rowW) * K + segW * 8;
        }
    } else {
        if (tid < 128) {
            const int rowA = tid >> 1, segA = tid & 1;
            doA = true;
            aok = (bm + rowA) < M;
            offA = (unsigned)((rowA * STR + segA * 8) * 2);
            srcA = g.Ah + (size_t)(bm + rowA) * K + segA * 8;
        } else {
            const int rowW = (tid - 128) >> 1, segW = tid & 1;
            doW = true;
            offW = (unsigned)(2 * szA + (rowW * STR + segW * 8) * 2);
            srcW = g.Wh + (size_t)(bn + rowW) * K + segW * 8;
        }
    }
    const ptrdiff_t alDelta = g.Al - g.Ah;

    auto loadChunk = [&](int kc, int s) {
        const int o = kc << 4;
        const unsigned base = sb + s * STG;
        if (doA) {
            cpa16(base + offA, srcA + o, aok);
            cpa16(base + szA + offA, srcA + alDelta + o, aok);
        }
        if (doW) cpa16(base + offW, srcW + o, true);
        cpa_commit();
    };

    unsigned aoffH[MT], boffH[NP];
    {
        const int ar = wm * 32 + (lane & 15);
        const int ak = (lane >> 4) * 8;
        const int br = wn * (NT8 * 8) + (lane & 7) + ((lane >> 4) << 3);
        const int bk = ((lane >> 3) & 1) * 8;
#pragma unroll
        for (int t = 0; t < MT; t++) aoffH[t] = (unsigned)(((ar + t * 16) * STR + ak) * 2);
#pragma unroll
        for (int p = 0; p < NP; p++) boffH[p] = (unsigned)(2 * szA + ((br + p * 16) * STR + bk) * 2);
    }

    loadChunk(0, 0);
    loadChunk(1, 1);
    loadChunk(2, 2);

    float acc[MT][NT8][4];
#pragma unroll
    for (int i = 0; i < MT; i++)
#pragma unroll
        for (int j = 0; j < NT8; j++)
#pragma unroll
            for (int k = 0; k < 4; k++) acc[i][j][k] = 0.f;

    for (int kc = 0; kc < NC; kc++) {
        cpa_waitg<2>();
        __syncthreads();
        const int s = kc & 3;
        const int nk = kc + 3;
        if (nk < NC) loadChunk(nk, nk & 3);
        else cpa_commit();

        const unsigned stg = sb + s * STG;
        unsigned ah[MT][4], al[MT][4], bh[NP][4];
#pragma unroll
        for (int t = 0; t < MT; t++) {
            ldm4(ah[t][0], ah[t][1], ah[t][2], ah[t][3], stg + aoffH[t]);
            ldm4(al[t][0], al[t][1], al[t][2], al[t][3], stg + aoffH[t] + szA);
        }
#pragma unroll
        for (int p = 0; p < NP; p++)
            ldm4(bh[p][0], bh[p][1], bh[p][2], bh[p][3], stg + boffH[p]);
#pragma unroll
        for (int mt = 0; mt < MT; mt++) {
#pragma unroll
            for (int nt = 0; nt < NT8; nt++) {
                const int p = nt >> 1, nh = (nt & 1) << 1;
                mma16816(acc[mt][nt], ah[mt], bh[p][nh], bh[p][nh + 1]);
                mma16816(acc[mt][nt], al[mt], bh[p][nh], bh[p][nh + 1]);
            }
        }
    }

    const int rowb = bm + wm * 32 + (lane >> 2);
    const int colb = bn + wn * (NT8 * 8) + 2 * (lane & 3);
#pragma unroll
    for (int mt = 0; mt < MT; mt++) {
#pragma unroll
        for (int nt = 0; nt < NT8; nt++) {
            const int col = colb + nt * 8;
            float2 b2 = make_float2(0.f, 0.f);
            if (g.bias) b2 = *(const float2*)(g.bias + col);
#pragma unroll
            for (int hh = 0; hh < 2; hh++) {
                const int row = rowb + mt * 16 + hh * 8;
                if (row >= M) continue;
                float v0 = acc[mt][nt][hh * 2 + 0] + b2.x;
                float v1 = acc[mt][nt][hh * 2 + 1] + b2.y;
                if (g.R) {
                    float2 r2 = *(const float2*)(g.R + (size_t)row * N + col);
                    v0 += r2.x; v1 += r2.y;
                }
                if (g.act == 1) { v0 = geluf(v0); v1 = geluf(v1); }
                if (g.Cf) *(float2*)(g.Cf + (size_t)row * N + col) = make_float2(v0, v1);
                if (g.Ch) {
                    __half h0, l0, h1, l1;
                    splith(v0, h0, l0);
                    splith(v1, h1, l1);
                    *(__half2*)(g.Ch + (size_t)row * N + col) = __halves2half2(h0, h1);
                    *(__half2*)(g.Cl + (size_t)row * N + col) = __halves2half2(l0, l1);
                }
            }
        }
    }
}

template<int BM>
__global__ void __launch_bounds__(256) mma_gemm_kernel(GArgs g)
{
    mma_gemm_impl<BM>(g, blockIdx.x, blockIdx.y);
}

// dual: two independent BM=64 GEMMs in one launch; CTA-level dispatch
__global__ void __launch_bounds__(256) mma_gemm_dual_kernel(GArgs g0, GArgs g1, int split)
{
    if ((int)blockIdx.x < split) {
        const int local = blockIdx.x;
        mma_gemm_impl<64>(g0, local % g0.ntx, local / g0.ntx);
    } else {
        const int local = blockIdx.x - split;
        mma_gemm_impl<64>(g1, local % g1.ntx, local / g1.ntx);
    }
}

static constexpr int MMASM128 = 4 * (2 * 128 * 24 * 2 + 64 * 24 * 2);  // 61440
static constexpr int MMASM64  = 4 * (2 * 64 * 24 * 2 + 64 * 24 * 2);   // 36864

// ---------------------------------------------------------------------------
// weight convert: fp32 -> fp16, 23 segments
// ---------------------------------------------------------------------------
struct CSeg { const float* src; __half* h; int blk_off; };
struct CTable { CSeg seg[23]; };
__global__ void __launch_bounds__(256) wconv_kernel(CTable t)
{
    const int bt = blockIdx.x;
    int s = 0;
#pragma unroll
    for (int i = 1; i < 23; i++) if (t.seg[i].blk_off <= bt) s = i;
    const CSeg sg = t.seg[s];
    const int idx = (bt - sg.blk_off) * 1024 + threadIdx.x * 4;
    float4 v = *(const float4*)(sg.src + idx);
    *(__half2*)(sg.h + idx)     = __halves2half2(__float2half_rn(v.x), __float2half_rn(v.y));
    *(__half2*)(sg.h + idx + 2) = __halves2half2(__float2half_rn(v.z), __float2half_rn(v.w));
}

// ---------------------------------------------------------------------------
// merged prep: asplit(patch_features) | pe gather | qinit, by block range
// blocks [0,392): asplit; [392,784): pe; [784,4784): qinit
// ---------------------------------------------------------------------------
__global__ void __launch_bounds__(256) prep_kernel(
    const float* __restrict__ pf, const int* __restrict__ coords,
    const float* __restrict__ re, const float* __restrict__ ce,
    const float* __restrict__ gq,
    __half* __restrict__ pfh, __half* __restrict__ pfl,
    __half* __restrict__ peh, __half* __restrict__ pel,
    float* __restrict__ q, __half* __restrict__ qh, __half* __restrict__ ql)
{
    const int bid = blockIdx.x;
    if (bid < 392) {
        // asplit: MP*FD = 401408 elems, 392 blocks x 256 thr x 4
        int idx = (bid * 256 + threadIdx.x) * 4;
        float4 v = *(const float4*)(pf + idx);
        __half hh, ll;
        splith(v.x, hh, ll); pfh[idx + 0] = hh; pfl[idx + 0] = ll;
        splith(v.y, hh, ll); pfh[idx + 1] = hh; pfl[idx + 1] = ll;
        splith(v.z, hh, ll); pfh[idx + 2] = hh; pfl[idx + 2] = ll;
        splith(v.w, hh, ll); pfh[idx + 3] = hh; pfl[idx + 3] = ll;
    } else if (bid < 784) {
        // pe gather: B*P*D = 100352 elems
        int idx = (bid - 392) * 256 + threadIdx.x;
        if (idx < B * P * D) {
            int d = idx & 255;
            int bp = idx >> 8;
            int r = coords[bp * 2 + 0];
            int c = coords[bp * 2 + 1];
            r = min(max(r, 0), 255);
            c = min(max(c, 0), 255);
            float v = (d < 128) ? re[r * 128 + d] : ce[c * 128 + (d - 128)];
            __half h, l;
            splith(v, h, l);
            peh[idx] = h;
            pel[idx] = l;
        }
    } else {
        // qinit: MQ*D = 1024000 elems, 4000 blocks
        int idx = (bid - 784) * 256 + threadIdx.x;
        float v = gq[idx % (G * D)];
        q[idx] = v;
        __half h, l;
        splith(v, h, l);
        qh[idx] = h;
        ql[idx] = l;
    }
}

// ---------------------------------------------------------------------------
// LN (+optional vectorized fp16 hi/lo emit)
// ---------------------------------------------------------------------------
__global__ void ln_kernel(const float* __restrict__ x, const float* __restrict__ r,
                          const float* __restrict__ gg, const float* __restrict__ bb,
                          float* __restrict__ y,
                          __half* __restrict__ yh, __half* __restrict__ yl,
                          int rows)
{
    int gid = blockIdx.x * blockDim.x + threadIdx.x;
    int row = gid >> 5;
    int lane = gid & 31;
    if (row >= rows) return;
    const float* xp = x + (size_t)row * 256;
    float4 a = *(const float4*)(xp + lane * 4);
    float4 c = *(const float4*)(xp + 128 + lane * 4);
    if (r) {
        const float* rp = r + (size_t)row * 256;
        float4 ra = *(const float4*)(rp + lane * 4);
        float4 rc = *(const float4*)(rp + 128 + lane * 4);
        a.x += ra.x; a.y += ra.y; a.z += ra.z; a.w += ra.w;
        c.x += rc.x; c.y += rc.y; c.z += rc.z; c.w += rc.w;
    }
    float s = a.x + a.y + a.z + a.w + c.x + c.y + c.z + c.w;
    float q = a.x * a.x + a.y * a.y + a.z * a.z + a.w * a.w
            + c.x * c.x + c.y * c.y + c.z * c.z + c.w * c.w;
#pragma unroll
    for (int o = 16; o; o >>= 1) {
        s += __shfl_xor_sync(0xffffffffu, s, o);
        q += __shfl_xor_sync(0xffffffffu, q, o);
    }
    float mean = s * (1.f / 256.f);
    float var = q * (1.f / 256.f) - mean * mean;
    float rstd = rsqrtf(var + 1e-5f);
    float4 g0 = *(const float4*)(gg + lane * 4);
    float4 g1 = *(const float4*)(gg + 128 + lane * 4);
    float4 b0 = *(const float4*)(bb + lane * 4);
    float4 b1 = *(const float4*)(bb + 128 + lane * 4);
    float4 o0, o1;
    o0.x = (a.x - mean) * rstd * g0.x + b0.x;
    o0.y = (a.y - mean) * rstd * g0.y + b0.y;
    o0.z = (a.z - mean) * rstd * g0.z + b0.z;
    o0.w = (a.w - mean) * rstd * g0.w + b0.w;
    o1.x = (c.x - mean) * rstd * g1.x + b1.x;
    o1.y = (c.y - mean) * rstd * g1.y + b1.y;
    o1.z = (c.z - mean) * rstd * g1.z + b1.z;
    o1.w = (c.w - mean) * rstd * g1.w + b1.w;
    float* yp = y + (size_t)row * 256;
    *(float4*)(yp + lane * 4) = o0;
    *(float4*)(yp + 128 + lane * 4) = o1;
    if (yh) {
        const float ov[8] = {o0.x, o0.y, o0.z, o0.w, o1.x, o1.y, o1.z, o1.w};
        __half hv[8], lv[8];
#pragma unroll
        for (int i = 0; i < 8; i++) splith(ov[i], hv[i], lv[i]);
        const size_t b0o = (size_t)row * 256 + lane * 4;
        *(__half2*)(yh + b0o)       = __halves2half2(hv[0], hv[1]);
        *(__half2*)(yh + b0o + 2)   = __halves2half2(hv[2], hv[3]);
        *(__half2*)(yh + b0o + 128) = __halves2half2(hv[4], hv[5]);
        *(__half2*)(yh + b0o + 130) = __halves2half2(hv[6], hv[7]);
        *(__half2*)(yl + b0o)       = __halves2half2(lv[0], lv[1]);
        *(__half2*)(yl + b0o + 2)   = __halves2half2(lv[2], lv[3]);
        *(__half2*)(yl + b0o + 128) = __halves2half2(lv[4], lv[5]);
        *(__half2*)(yl + b0o + 130) = __halves2half2(lv[6], lv[7]);
    }
}

// ---------------------------------------------------------------------------
// Cross-attention; outputs fp16 hi/lo context.
// ---------------------------------------------------------------------------
__global__ void __launch_bounds__(256) attn_kernel(
    const float* __restrict__ Q, const float* __restrict__ KV,
    __half* __restrict__ cxh, __half* __restrict__ cxl)
{
    __shared__ float Kt[32][196];
    const int bh = blockIdx.x;
    const int b = bh >> 3, h = bh & 7;
    const int tid = threadIdx.x;
    const int lane = tid & 31, w = tid >> 5;

    const float* KVb = KV + (size_t)b * P * 512;
    for (int i = tid; i < P * 32; i += 256) {
        int p = i >> 5, d = i & 31;
        Kt[d][p] = KVb[(size_t)p * 512 + h * 32 + d] * ATT_SCALE;
    }
    __syncthreads();

    const int g0 = (blockIdx.y * 8 + w) * 4;
    if (g0 >= G) return;

    float qr[4];
#pragma unroll
    for (int i = 0; i < 4; i++)
        qr[i] = Q[(size_t)(b * G + g0 + i) * 256 + h * 32 + lane];

    float sc[4][7];
#pragma unroll
    for (int i = 0; i < 4; i++)
#pragma unroll
        for (int j = 0; j < 7; j++) sc[i][j] = 0.f;

#pragma unroll 4
    for (int d = 0; d < 32; d++) {
        float k0 = Kt[d][lane];
        float k1 = Kt[d][32 + lane];
        float k2 = Kt[d][64 + lane];
        float k3 = Kt[d][96 + lane];
        float k4 = Kt[d][128 + lane];
        float k5 = Kt[d][160 + lane];
        float k6 = (lane < 4) ? Kt[d][192 + lane] : 0.f;
#pragma unroll
        for (int i = 0; i < 4; i++) {
            float qd = __shfl_sync(0xffffffffu, qr[i], d);
            sc[i][0] = fmaf(qd, k0, sc[i][0]);
            sc[i][1] = fmaf(qd, k1, sc[i][1]);
            sc[i][2] = fmaf(qd, k2, sc[i][2]);
            sc[i][3] = fmaf(qd, k3, sc[i][3]);
            sc[i][4] = fmaf(qd, k4, sc[i][4]);
            sc[i][5] = fmaf(qd, k5, sc[i][5]);
            sc[i][6] = fmaf(qd, k6, sc[i][6]);
        }
    }

#pragma unroll
    for (int i = 0; i < 4; i++) {
        if (lane >= 4) sc[i][6] = -1e30f;
        float m = sc[i][0];
#pragma unroll
        for (int j = 1; j < 7; j++) m = fmaxf(m, sc[i][j]);
#pragma unroll
        for (int o = 16; o; o >>= 1) m = fmaxf(m, __shfl_xor_sync(0xffffffffu, m, o));
        float s = 0.f;
#pragma unroll
        for (int j = 0; j < 7; j++) { float e = __expf(sc[i][j] - m); sc[i][j] = e; s += e; }
#pragma unroll
        for (int o = 16; o; o >>= 1) s += __shfl_xor_sync(0xffffffffu, s, o);
        float inv = 1.0f / s;
#pragma unroll
        for (int j = 0; j < 7; j++) sc[i][j] *= inv;
    }

    float cx[4] = {0.f, 0.f, 0.f, 0.f};
    const float* Vb = KVb + 256 + h * 32 + lane;
#pragma unroll
    for (int jj = 0; jj < 7; jj++) {
        const int kmax = (jj == 6) ? 4 : 32;
        for (int src = 0; src < kmax; src++) {
            float v = Vb[(size_t)(jj * 32 + src) * 512];
#pragma unroll
            for (int i = 0; i < 4; i++) {
                float a = __shfl_sync(0xffffffffu, sc[i][jj], src);
                cx[i] = fmaf(a, v, cx[i]);
            }
        }
    }
#pragma unroll
    for (int i = 0; i < 4; i++) {
        size_t off = (size_t)(b * G + g0 + i) * 256 + h * 32 + lane;
        __half hh, ll;
        splith(cx[i], hh, ll);
        cxh[off] = hh;
        cxl[off] = ll;
    }
}

__global__ void __launch_bounds__(256) head_kernel(
    const float* __restrict__ qp, const float* __restrict__ pp, float* __restrict__ out)
{
    const int bp = blockIdx.y;
    const int b = (bp >= P) ? 1 : 0;
    const int g = blockIdx.x * 8 + (threadIdx.x >> 5);
    const int hh = (threadIdx.x & 31) << 2;
    float4 pv = *(const float4*)(pp + (size_t)bp * HALF + hh);
    float4 qv = *(const float4*)(qp + (size_t)(b * G + g) * HALF + hh);
    float4 o;
    o.x = softplusf(pv.x + qv.x);
    o.y = softplusf(pv.y + qv.y);
    o.z = softplusf(pv.z + qv.z);
    o.w = softplusf(pv.w + qv.w);
    *(float4*)(out + ((size_t)bp * G + g) * HALF + hh) = o;
}

// ---------------------------------------------------------------------------
extern "C" void kernel_launch(void* const* d_in, const int* in_sizes, int n_in,
                              void* d_out, int out_size)
{
    (void)in_sizes; (void)n_in; (void)out_size;
    const float* patch_features = (const float*)d_in[0];
    const int*   patch_coords   = (const int*)d_in[1];
    const float* patch_proj_w   = (const float*)d_in[2];
    const float* patch_proj_b   = (const float*)d_in[3];
    const float* patch_ln_g     = (const float*)d_in[4];
    const float* patch_ln_b     = (const float*)d_in[5];
    const float* row_embed      = (const float*)d_in[6];
    const float* col_embed      = (const float*)d_in[7];
    const float* pe_proj_w      = (const float*)d_in[8];
    const float* pe_proj_b      = (const float*)d_in[9];
    const float* gene_queries   = (const float*)d_in[10];
    const float* in_proj_w      = (const float*)d_in[11];
    const float* in_proj_b      = (const float*)d_in[12];
    const float* out_w          = (const float*)d_in[13];
    const float* out_b          = (const float*)d_in[14];
    const float* ff1_w          = (const float*)d_in[15];
    const float* ff1_b          = (const float*)d_in[16];
    const float* ff2_w          = (const float*)d_in[17];
    const float* ff2_b          = (const float*)d_in[18];
    const float* ln1_g          = (const float*)d_in[19];
    const float* ln1_b          = (const float*)d_in[20];
    const float* ln2_g          = (const float*)d_in[21];
    const float* ln2_b          = (const float*)d_in[22];
    const float* head_w1        = (const float*)d_in[23];
    const float* head_b1        = (const float*)d_in[24];
    float* out = (float*)d_out;

    cudaFuncSetAttribute(mma_gemm_kernel<128>, cudaFuncAttributeMaxDynamicSharedMemorySize, MMASM128);
    cudaFuncSetAttribute(mma_gemm_kernel<64>,  cudaFuncAttributeMaxDynamicSharedMemorySize, MMASM64);
    cudaFuncSetAttribute(mma_gemm_dual_kernel, cudaFuncAttributeMaxDynamicSharedMemorySize, MMASM64);

    float* ws = nullptr;
    cudaGetSymbolAddress((void**)&ws, g_ws);
    __half* hf = nullptr;
    cudaGetSymbolAddress((void**)&hf, g_hf);

    float* patch_emb = ws + OFF_PATCH;
    float* tmp       = ws + OFF_TMP;
    float* kv        = ws + OFF_KV;
    float* q         = ws + OFF_Q;
    float* Qb        = ws + OFF_QB;
    float* att       = ws + OFF_ATT;
    float* qproj     = ws + OFF_QP;
    float* pproj     = ws + OFF_PP;

    __half* qh  = hf + HF_QH;
    __half* ql  = hf + HF_QL;
    __half* l1h = hf + HF_L1H;
    __half* l1l = hf + HF_L1L;
    __half* cxh = hf + HF_CXH;
    __half* cxl = hf + HF_CXL;
    __half* fh  = hf + HF_FH;
    __half* fl  = hf + HF_FL;
    __half* pfh = hf + HF_PFH;
    __half* pfl = hf + HF_PFL;
    __half* peh = hf + HF_PEH;
    __half* pel = hf + HF_PEL;
    __half* pch = hf + HF_PCH;
    __half* pcl = hf + HF_PCL;

    // ---- one-time weight convert ----
    CTable ct;
    int total_blk;
    {
        int seg = 0, boff = 0;
        auto add = [&](const float* src, size_t ho, int count) {
            ct.seg[seg] = { src, hf + ho, boff };
            boff += count / 1024;
            seg++;
        };
        for (int l = 0; l < NL; l++)
            add(in_proj_w + (size_t)l * 3 * D * D, HF_WQ + (size_t)l * D * D, D * D);
        for (int l = 0; l < NL; l++)
            add(out_w + (size_t)l * D * D, HF_WO + (size_t)l * D * D, D * D);
        for (int l = 0; l < NL; l++)
            add(ff1_w + (size_t)l * 4 * D * D, HF_F1 + (size_t)l * 4 * D * D, 4 * D * D);
        for (int l = 0; l < NL; l++)
            add(ff2_w + (size_t)l * 4 * D * D, HF_F2 + (size_t)l * 4 * D * D, 4 * D * D);
        add(head_w1, HF_HD, HALF * D);
        add(patch_proj_w, HF_WP, D * FD);
        add(pe_proj_w, HF_WE, D * D);
        for (int l = 0; l < NL; l++)
            add(in_proj_w + (size_t)l * 3 * D * D + D * D, HF_WK + (size_t)l * 2 * D * D, 2 * D * D);
        total_blk = boff;
    }
    wconv_kernel<<<total_blk, 256>>>(ct);
    prep_kernel<<<4784, 256>>>(patch_features, patch_coords, row_embed, col_embed,
                               gene_queries, pfh, pfl, peh, pel, q, qh, ql);

    const int MT64  = (MQ + 63) / 64;     // 63
    const int MT128 = (MQ + 127) / 128;   // 32
    const int MTP   = (MP + 63) / 64;     // 7

    auto GA = [](const __half* Ah, const __half* Al, const __half* Wh,
                 const float* bias, const float* R,
                 float* Cf, __half* Ch, __half* Cl,
                 int M, int N, int K, int act) {
        GArgs g;
        g.Ah = Ah; g.Al = Al; g.Wh = Wh; g.bias = bias; g.R = R;
        g.Cf = Cf; g.Ch = Ch; g.Cl = Cl;
        g.M = M; g.N = N; g.K = K; g.act = act; g.ntx = N / 64;
        return g;
    };

    // ---- Stage A ----
    mma_gemm_kernel<64><<<dim3(D / 64, MTP), 256, MMASM64>>>(
        GA(pfh, pfl, hf + HF_WP, patch_proj_b, nullptr, tmp, nullptr, nullptr, MP, D, FD, 0));
    ln_kernel<<<(MP + 7) / 8, 256>>>(tmp, nullptr, patch_ln_g, patch_ln_b, patch_emb,
                                     nullptr, nullptr, MP);
    mma_gemm_kernel<64><<<dim3(D / 64, MTP), 256, MMASM64>>>(
        GA(peh, pel, hf + HF_WE, pe_proj_b, patch_emb, nullptr, pch, pcl, MP, D, D, 0));

    // ---- Stage B: decoder layers (7 launches/layer) ----
    for (int l = 0; l < NL; l++) {
        const float* bq  = in_proj_b + (size_t)l * 3 * D;
        const float* bkv = bq + D;
        // Qproj + KVproj fused into one launch
        GArgs gq = GA(qh, ql, hf + HF_WQ + (size_t)l * D * D, bq, nullptr,
                      Qb, nullptr, nullptr, MQ, D, D, 0);
        GArgs gk = GA(pch, pcl, hf + HF_WK + (size_t)l * 2 * D * D, bkv, nullptr,
                      kv, nullptr, nullptr, MP, 2 * D, D, 0);
        const int splitQ = gq.ntx * MT64;           // 4*63 = 252
        const int totQ   = splitQ + gk.ntx * MTP;   // + 8*7 = 308
        mma_gemm_dual_kernel<<<totQ, 256, MMASM64>>>(gq, gk, splitQ);

        attn_kernel<<<dim3(B * H, (G + 31) / 32), 256>>>(Qb, kv, cxh, cxl);
        mma_gemm_kernel<64><<<dim3(D / 64, MT64), 256, MMASM64>>>(
            GA(cxh, cxl, hf + HF_WO + (size_t)l * D * D, out_b + (size_t)l * D, nullptr,
               att, nullptr, nullptr, MQ, D, D, 0));
        ln_kernel<<<(MQ + 7) / 8, 256>>>(q, att, ln1_g + (size_t)l * D, ln1_b + (size_t)l * D,
                                         q, l1h, l1l, MQ);
        mma_gemm_kernel<128><<<dim3(4 * D / 64, MT128), 256, MMASM128>>>(
            GA(l1h, l1l, hf + HF_F1 + (size_t)l * 4 * D * D, ff1_b + (size_t)l * 4 * D, nullptr,
               nullptr, fh, fl, MQ, 4 * D, D, 1));
        mma_gemm_kernel<64><<<dim3(D / 64, MT64), 256, MMASM64>>>(
            GA(fh, fl, hf + HF_F2 + (size_t)l * 4 * D * D, ff2_b + (size_t)l * D, nullptr,
               att, nullptr, nullptr, MQ, D, 4 * D, 0));
        ln_kernel<<<(MQ + 7) / 8, 256>>>(q, att, ln2_g + (size_t)l * D, ln2_b + (size_t)l * D,
                                         q, qh, ql, MQ);
    }

    // ---- Stage C: both head GEMMs in one launch ----
    {
        GArgs gq = GA(qh, ql, hf + HF_HD, head_b1, nullptr,
                      qproj, nullptr, nullptr, MQ, HALF, D, 0);
        GArgs gp = GA(pch, pcl, hf + HF_HD, nullptr, nullptr,
                      pproj, nullptr, nullptr, MP, HALF, D, 0);
        const int splitH = gq.ntx * MT64;           // 2*63 = 126
        const int totH   = splitH + gp.ntx * MTP;   // + 2*7 = 140
        mma_gemm_dual_kernel<<<totH, 256, MMASM64>>>(gq, gp, splitH);
    }
    head_kernel<<<dim3(G / 8, B * P), 256>>>(qproj, pproj, out);
}

// round 12
// speedup vs baseline: 1.3940x; 1.2349x over previous
#include <cuda_runtime.h>
#include <cuda_fp16.h>
#include <cstddef>
#include <cstdint>
#include <math.h>

// ---------------------------------------------------------------------------
// SpatialTranscriptomicsDecoder — GB300 sm_103a. Round 12.
// R11 + tensor-core fused attention (mma S, split-softmax, mma P@V via
// ldmatrix.trans) + residual folded into out-proj/ff2 GEMMs.
// ---------------------------------------------------------------------------

static constexpr int B = 2, P = 196, FD = 1024, G = 2000, D = 256, H = 8, NL = 4, HALF = 128;
static constexpr float ATT_SCALE = 0.17677669529663687f;
static constexpr int MQ = B * G;   // 4000
static constexpr int MP = B * P;   // 392

// ---------------- fp32 workspace ----------------
static constexpr size_t OFF_PATCH = 0;
static constexpr size_t OFF_TMP   = OFF_PATCH + (size_t)MP * D;
static constexpr size_t OFF_Q     = OFF_TMP   + (size_t)MP * D;
static constexpr size_t OFF_ATT   = OFF_Q     + (size_t)MQ * D;
static constexpr size_t OFF_QP    = OFF_ATT   + (size_t)MQ * D;
static constexpr size_t OFF_PP    = OFF_QP    + (size_t)MQ * HALF;
static constexpr size_t WS_TOTAL  = OFF_PP    + (size_t)MP * HALF;
__device__ float g_ws[WS_TOTAL];

// ---------------- fp16 workspace ----------------
static constexpr size_t BQ  = (size_t)MQ * D;
static constexpr size_t HF_QH  = 0;
static constexpr size_t HF_QL  = HF_QH + BQ;
static constexpr size_t HF_L1H = HF_QL + BQ;
static constexpr size_t HF_L1L = HF_L1H + BQ;
static constexpr size_t HF_CXH = HF_L1L + BQ;
static constexpr size_t HF_CXL = HF_CXH + BQ;
static constexpr size_t HF_FH  = HF_CXL + BQ;
static constexpr size_t HF_FL  = HF_FH + (size_t)MQ * 4 * D;
static constexpr size_t HF_QBH = HF_FL + (size_t)MQ * 4 * D;     // Q proj out
static constexpr size_t HF_QBL = HF_QBH + BQ;
static constexpr size_t HF_KVH = HF_QBL + BQ;                     // KV proj out
static constexpr size_t HF_KVL = HF_KVH + (size_t)MP * 2 * D;
static constexpr size_t HF_PFH = HF_KVL + (size_t)MP * 2 * D;
static constexpr size_t HF_PFL = HF_PFH + (size_t)MP * FD;
static constexpr size_t HF_PEH = HF_PFL + (size_t)MP * FD;
static constexpr size_t HF_PEL = HF_PEH + (size_t)MP * D;
static constexpr size_t HF_PCH = HF_PEL + (size_t)MP * D;
static constexpr size_t HF_PCL = HF_PCH + (size_t)MP * D;
static constexpr size_t HF_WQ  = HF_PCL + (size_t)MP * D;
static constexpr size_t HF_WO  = HF_WQ  + (size_t)NL * D * D;
static constexpr size_t HF_F1  = HF_WO  + (size_t)NL * D * D;
static constexpr size_t HF_F2  = HF_F1  + (size_t)NL * 4 * D * D;
static constexpr size_t HF_HD  = HF_F2  + (size_t)NL * 4 * D * D;
static constexpr size_t HF_WP  = HF_HD  + (size_t)HALF * D;
static constexpr size_t HF_WE  = HF_WP  + (size_t)D * FD;
static constexpr size_t HF_WK  = HF_WE  + (size_t)D * D;
static constexpr size_t HF_TOTAL = HF_WK + (size_t)NL * 2 * D * D;
__device__ __half g_hf[HF_TOTAL];

// ---------------- helpers ----------------
__device__ __forceinline__ float geluf(float x) {
    return 0.5f * x * (1.0f + erff(x * 0.7071067811865476f));
}
__device__ __forceinline__ float softplusf(float x) {
    return fmaxf(x, 0.0f) + __logf(1.0f + __expf(-fabsf(x)));
}
__device__ __forceinline__ void splith(float v, __half& h, __half& l) {
    h = __float2half_rn(v);
    l = __float2half_rn(v - __half2float(h));
}
__device__ __forceinline__ void cpa16(unsigned int dst, const void* src, bool ok) {
    asm volatile("cp.async.ca.shared.global [%0], [%1], 16, %2;"
                 :: "r"(dst), "l"(src), "r"(ok ? 16 : 0) : "memory");
}
__device__ __forceinline__ void cpa_commit() {
    asm volatile("cp.async.commit_group;" ::: "memory");
}
template<int Ng> __device__ __forceinline__ void cpa_waitg() {
    asm volatile("cp.async.wait_group %0;" :: "n"(Ng) : "memory");
}
__device__ __forceinline__ void ldm4(unsigned& r0, unsigned& r1, unsigned& r2, unsigned& r3,
                                     unsigned addr) {
    asm volatile("ldmatrix.sync.aligned.m8n8.x4.shared.b16 {%0,%1,%2,%3}, [%4];"
                 : "=r"(r0), "=r"(r1), "=r"(r2), "=r"(r3) : "r"(addr));
}
__device__ __forceinline__ void ldm4t(unsigned& r0, unsigned& r1, unsigned& r2, unsigned& r3,
                                      unsigned addr) {
    asm volatile("ldmatrix.sync.aligned.m8n8.x4.trans.shared.b16 {%0,%1,%2,%3}, [%4];"
                 : "=r"(r0), "=r"(r1), "=r"(r2), "=r"(r3) : "r"(addr));
}
__device__ __forceinline__ void mma16816(float* d, const unsigned* a, unsigned b0, unsigned b1) {
    asm volatile(
        "mma.sync.aligned.m16n8k16.row.col.f32.f16.f16.f32 "
        "{%0,%1,%2,%3}, {%4,%5,%6,%7}, {%8,%9}, {%0,%1,%2,%3};"
        : "+f"(d[0]), "+f"(d[1]), "+f"(d[2]), "+f"(d[3])
        : "r"(a[0]), "r"(a[1]), "r"(a[2]), "r"(a[3]), "r"(b0), "r"(b1));
}

// ---------------------------------------------------------------------------
// GEMM argument bundle + device impl (fp16 2-term split):
// C[M,N] = act( (Ah+Al) @ Wh^T + bias + R )
// ---------------------------------------------------------------------------
struct GArgs {
    const __half* Ah; const __half* Al; const __half* Wh;
    const float* bias; const float* R;
    float* Cf; __half* Ch; __half* Cl;
    int M, N, K, act, ntx;
};

template<int BM>
__device__ __forceinline__ void mma_gemm_impl(const GArgs& g, int bx, int by)
{
    constexpr int STR = 24;
    constexpr int szA = BM * STR * 2;
    constexpr int szW = 64 * STR * 2;
    constexpr int STG = 2 * szA + szW;
    constexpr int MT  = 2;
    constexpr int WMASK  = (BM == 128) ? 3 : 1;
    constexpr int WSHIFT = (BM == 128) ? 2 : 1;
    constexpr int NT8 = (BM == 128) ? 4 : 2;
    constexpr int NP  = NT8 / 2;

    extern __shared__ char smem[];
    const unsigned sb = (unsigned)__cvta_generic_to_shared(smem);

    const int tid = threadIdx.x;
    const int lane = tid & 31, wid = tid >> 5;
    const int wm = wid & WMASK, wn = wid >> WSHIFT;
    const int bm = by * BM;
    const int bn = bx * 64;
    const int NC = g.K >> 4;
    const int M = g.M, N = g.N, K = g.K;

    unsigned offA = 0, offW = 0;
    const __half* srcA = nullptr;
    const __half* srcW = nullptr;
    bool aok = false, doA = false, doW = false;
    if (BM == 128) {
        const int rowA = tid >> 1, segA = tid & 1;
        doA = true;
        aok = (bm + rowA) < M;
        offA = (unsigned)((rowA * STR + segA * 8) * 2);
        srcA = g.Ah + (size_t)(bm + rowA) * K + segA * 8;
        if (tid < 128) {
            const int rowW = tid >> 1, segW = tid & 1;
            doW = true;
            offW = (unsigned)(2 * szA + (rowW * STR + segW * 8) * 2);
            srcW = g.Wh + (size_t)(bn + rowW) * K + segW * 8;
        }
    } else {
        if (tid < 128) {
            const int rowA = tid >> 1, segA = tid & 1;
            doA = true;
            aok = (bm + rowA) < M;
            offA = (unsigned)((rowA * STR + segA * 8) * 2);
            srcA = g.Ah + (size_t)(bm + rowA) * K + segA * 8;
        } else {
            const int rowW = (tid - 128) >> 1, segW = tid & 1;
            doW = true;
            offW = (unsigned)(2 * szA + (rowW * STR + segW * 8) * 2);
            srcW = g.Wh + (size_t)(bn + rowW) * K + segW * 8;
        }
    }
    const ptrdiff_t alDelta = g.Al - g.Ah;

    auto loadChunk = [&](int kc, int s) {
        const int o = kc << 4;
        const unsigned base = sb + s * STG;
        if (doA) {
            cpa16(base + offA, srcA + o, aok);
            cpa16(base + szA + offA, srcA + alDelta + o, aok);
        }
        if (doW) cpa16(base + offW, srcW + o, true);
        cpa_commit();
    };

    unsigned aoffH[MT], boffH[NP];
    {
        const int ar = wm * 32 + (lane & 15);
        const int ak = (lane >> 4) * 8;
        const int br = wn * (NT8 * 8) + (lane & 7) + ((lane >> 4) << 3);
        const int bk = ((lane >> 3) & 1) * 8;
#pragma unroll
        for (int t = 0; t < MT; t++) aoffH[t] = (unsigned)(((ar + t * 16) * STR + ak) * 2);
#pragma unroll
        for (int p = 0; p < NP; p++) boffH[p] = (unsigned)(2 * szA + ((br + p * 16) * STR + bk) * 2);
    }

    loadChunk(0, 0);
    loadChunk(1, 1);
    loadChunk(2, 2);

    float acc[MT][NT8][4];
#pragma unroll
    for (int i = 0; i < MT; i++)
#pragma unroll
        for (int j = 0; j < NT8; j++)
#pragma unroll
            for (int k = 0; k < 4; k++) acc[i][j][k] = 0.f;

    for (int kc = 0; kc < NC; kc++) {
        cpa_waitg<2>();
        __syncthreads();
        const int s = kc & 3;
        const int nk = kc + 3;
        if (nk < NC) loadChunk(nk, nk & 3);
        else cpa_commit();

        const unsigned stg = sb + s * STG;
        unsigned ah[MT][4], al[MT][4], bh[NP][4];
#pragma unroll
        for (int t = 0; t < MT; t++) {
            ldm4(ah[t][0], ah[t][1], ah[t][2], ah[t][3], stg + aoffH[t]);
            ldm4(al[t][0], al[t][1], al[t][2], al[t][3], stg + aoffH[t] + szA);
        }
#pragma unroll
        for (int p = 0; p < NP; p++)
            ldm4(bh[p][0], bh[p][1], bh[p][2], bh[p][3], stg + boffH[p]);
#pragma unroll
        for (int mt = 0; mt < MT; mt++) {
#pragma unroll
            for (int nt = 0; nt < NT8; nt++) {
                const int p = nt >> 1, nh = (nt & 1) << 1;
                mma16816(acc[mt][nt], ah[mt], bh[p][nh], bh[p][nh + 1]);
                mma16816(acc[mt][nt], al[mt], bh[p][nh], bh[p][nh + 1]);
            }
        }
    }

    const int rowb = bm + wm * 32 + (lane >> 2);
    const int colb = bn + wn * (NT8 * 8) + 2 * (lane & 3);
#pragma unroll
    for (int mt = 0; mt < MT; mt++) {
#pragma unroll
        for (int nt = 0; nt < NT8; nt++) {
            const int col = colb + nt * 8;
            float2 b2 = make_float2(0.f, 0.f);
            if (g.bias) b2 = *(const float2*)(g.bias + col);
#pragma unroll
            for (int hh = 0; hh < 2; hh++) {
                const int row = rowb + mt * 16 + hh * 8;
                if (row >= M) continue;
                float v0 = acc[mt][nt][hh * 2 + 0] + b2.x;
                float v1 = acc[mt][nt][hh * 2 + 1] + b2.y;
                if (g.R) {
                    float2 r2 = *(const float2*)(g.R + (size_t)row * N + col);
                    v0 += r2.x; v1 += r2.y;
                }
                if (g.act == 1) { v0 = geluf(v0); v1 = geluf(v1); }
                if (g.Cf) *(float2*)(g.Cf + (size_t)row * N + col) = make_float2(v0, v1);
                if (g.Ch) {
                    __half h0, l0, h1, l1;
                    splith(v0, h0, l0);
                    splith(v1, h1, l1);
                    *(__half2*)(g.Ch + (size_t)row * N + col) = __halves2half2(h0, h1);
                    *(__half2*)(g.Cl + (size_t)row * N + col) = __halves2half2(l0, l1);
                }
            }
        }
    }
}

template<int BM>
__global__ void __launch_bounds__(256) mma_gemm_kernel(GArgs g)
{
    mma_gemm_impl<BM>(g, blockIdx.x, blockIdx.y);
}

__global__ void __launch_bounds__(256) mma_gemm_dual_kernel(GArgs g0, GArgs g1, int split)
{
    if ((int)blockIdx.x < split) {
        const int local = blockIdx.x;
        mma_gemm_impl<64>(g0, local % g0.ntx, local / g0.ntx);
    } else {
        const int local = blockIdx.x - split;
        mma_gemm_impl<64>(g1, local % g1.ntx, local / g1.ntx);
    }
}

static constexpr int MMASM128 = 4 * (2 * 128 * 24 * 2 + 64 * 24 * 2);  // 61440
static constexpr int MMASM64  = 4 * (2 * 64 * 24 * 2 + 64 * 24 * 2);   // 36864

// ---------------------------------------------------------------------------
// Fused tensor-core attention. grid (B*H, 32), 256 threads (8 warps, 4m x 2n).
// smem (halfs): Qh[64x40], Ql[64x40], Kh[224x40], Vh[224x40], Vl[224x40],
//               Ps[64x216]; partial floats after.
// ---------------------------------------------------------------------------
static constexpr int A_QH0 = 0;
static constexpr int A_QL0 = 2560;
static constexpr int A_KH0 = 5120;                 // 224*40 = 8960
static constexpr int A_VH0 = A_KH0 + 8960;        // 14080
static constexpr int A_VL0 = A_VH0 + 8960;        // 23040
static constexpr int A_PS0 = A_VL0 + 8960;        // 32000, 64*216 = 13824
static constexpr int A_PARTB = (A_PS0 + 13824) * 2;   // 91648 bytes
static constexpr int ATTSM = A_PARTB + 2048;          // 93696 bytes

__global__ void __launch_bounds__(256) attn_mma_kernel(
    const __half* __restrict__ Qh_g, const __half* __restrict__ Ql_g,
    const __half* __restrict__ KVh, const __half* __restrict__ KVl,
    __half* __restrict__ cxh, __half* __restrict__ cxl)
{
    extern __shared__ char smem[];
    __half* sm = (__half*)smem;
    float* pm   = (float*)(smem + A_PARTB);   // [2][64]
    float* psum = pm + 128;                    // [2][64]
    const unsigned sb = (unsigned)__cvta_generic_to_shared(smem);

    const int bh = blockIdx.x;
    const int b = bh >> 3, h = bh & 7;
    const int g0 = blockIdx.y * 64;
    const int tid = threadIdx.x;
    const int lane = tid & 31, wid = tid >> 5;
    const int wm = wid & 3, wn = wid >> 2;

    // ---- loads ----
    {   // Q hi/lo: 64 rows x 32 halfs; 2 cp per thread
        const int mat = tid >> 7;
        const int slot = tid & 127;
        const int row = slot >> 1;
        const int sp = (slot & 1) * 16;
        const bool ok = (g0 + row) < G;
        const __half* src = (mat ? Ql_g : Qh_g)
                          + ((size_t)(b * G + g0 + row) * 256 + h * 32 + sp);
        unsigned dst = sb + ((mat ? A_QL0 : A_QH0) + row * 40 + sp) * 2;
        cpa16(dst, src, ok);
        cpa16(dst + 16, src + 8, ok);
    }
    if (tid < 196) {   // K hi, V hi/lo: row tid
        const size_t rb = (size_t)(b * P + tid) * 512 + h * 32;
        const __half* ksrc = KVh + rb;
        unsigned kdst = sb + (A_KH0 + tid * 40) * 2;
        cpa16(kdst,      ksrc,      true);
        cpa16(kdst + 16, ksrc + 8,  true);
        cpa16(kdst + 32, ksrc + 16, true);
        cpa16(kdst + 48, ksrc + 24, true);
        const __half* vh = KVh + rb + 256;
        const __half* vl = KVl + rb + 256;
        unsigned vhd = sb + (A_VH0 + tid * 40) * 2;
        unsigned vld = sb + (A_VL0 + tid * 40) * 2;
        cpa16(vhd,      vh,      true);
        cpa16(vhd + 16, vh + 8,  true);
        cpa16(vhd + 32, vh + 16, true);
        cpa16(vhd + 48, vh + 24, true);
        cpa16(vld,      vl,      true);
        cpa16(vld + 16, vl + 8,  true);
        cpa16(vld + 32, vl + 16, true);
        cpa16(vld + 48, vl + 24, true);
    } else if (tid < 224) {   // zero pad rows 196..223 of Kh, Vh, Vl
        uint4 z = make_uint4(0, 0, 0, 0);
#pragma unroll
        for (int i = 0; i < 5; i++) {
            *(uint4*)(sm + A_KH0 + tid * 40 + i * 8) = z;
            *(uint4*)(sm + A_VH0 + tid * 40 + i * 8) = z;
            *(uint4*)(sm + A_VL0 + tid * 40 + i * 8) = z;
        }
    }
    cpa_commit();
    cpa_waitg<0>();
    __syncthreads();

    // ---- S = (Qh+Ql) @ Kh^T ----
    unsigned aq[2][4], alo[2][4];
    {
        const int ar = wm * 16 + (lane & 15);
        const int ak = (lane >> 4) * 8;
#pragma unroll
        for (int ks = 0; ks < 2; ks++) {
            ldm4(aq[ks][0], aq[ks][1], aq[ks][2], aq[ks][3],
                 sb + (A_QH0 + ar * 40 + ks * 16 + ak) * 2);
            ldm4(alo[ks][0], alo[ks][1], alo[ks][2], alo[ks][3],
                 sb + (A_QL0 + ar * 40 + ks * 16 + ak) * 2);
        }
    }
    float sacc[13][4];
#pragma unroll
    for (int i = 0; i < 13; i++)
#pragma unroll
        for (int j = 0; j < 4; j++) sacc[i][j] = 0.f;

    {
        const int brr = wn * 104 + (lane & 7) + ((lane >> 4) << 3);
        const int bko = ((lane >> 3) & 1) * 8;
#pragma unroll
        for (int gph = 0; gph < 7; gph++) {
            unsigned bk0[4], bk1[4];
            ldm4(bk0[0], bk0[1], bk0[2], bk0[3],
                 sb + (A_KH0 + (brr + gph * 16) * 40 + bko) * 2);
            ldm4(bk1[0], bk1[1], bk1[2], bk1[3],
                 sb + (A_KH0 + (brr + gph * 16) * 40 + 16 + bko) * 2);
#pragma unroll
            for (int hf = 0; hf < 2; hf++) {
                const int nt = gph * 2 + hf;
                if (nt >= 13) break;
                mma16816(sacc[nt], aq[0],  bk0[hf * 2], bk0[hf * 2 + 1]);
                mma16816(sacc[nt], alo[0], bk0[hf * 2], bk0[hf * 2 + 1]);
                mma16816(sacc[nt], aq[1],  bk1[hf * 2], bk1[hf * 2 + 1]);
                mma16816(sacc[nt], alo[1], bk1[hf * 2], bk1[hf * 2 + 1]);
            }
        }
    }

    // ---- softmax (split across wn) ----
#pragma unroll
    for (int nt = 0; nt < 13; nt++)
#pragma unroll
        for (int j = 0; j < 4; j++) sacc[nt][j] *= ATT_SCALE;

    float mx0 = -1e30f, mx1 = -1e30f;
#pragma unroll
    for (int nt = 0; nt < 13; nt++) {
        mx0 = fmaxf(mx0, fmaxf(sacc[nt][0], sacc[nt][1]));
        mx1 = fmaxf(mx1, fmaxf(sacc[nt][2], sacc[nt][3]));
    }
    mx0 = fmaxf(mx0, __shfl_xor_sync(0xffffffffu, mx0, 1));
    mx0 = fmaxf(mx0, __shfl_xor_sync(0xffffffffu, mx0, 2));
    mx1 = fmaxf(mx1, __shfl_xor_sync(0xffffffffu, mx1, 1));
    mx1 = fmaxf(mx1, __shfl_xor_sync(0xffffffffu, mx1, 2));

    float s0 = 0.f, s1 = 0.f;
#pragma unroll
    for (int nt = 0; nt < 13; nt++) {
        const int col = wn * 104 + nt * 8 + 2 * (lane & 3);
        float e0 = (col < 196)     ? __expf(sacc[nt][0] - mx0) : 0.f;
        float e1 = (col + 1 < 196) ? __expf(sacc[nt][1] - mx0) : 0.f;
        float e2 = (col < 196)     ? __expf(sacc[nt][2] - mx1) : 0.f;
        float e3 = (col + 1 < 196) ? __expf(sacc[nt][3] - mx1) : 0.f;
        sacc[nt][0] = e0; sacc[nt][1] = e1; sacc[nt][2] = e2; sacc[nt][3] = e3;
        s0 += e0 + e1; s1 += e2 + e3;
    }
    s0 += __shfl_xor_sync(0xffffffffu, s0, 1);
    s0 += __shfl_xor_sync(0xffffffffu, s0, 2);
    s1 += __shfl_xor_sync(0xffffffffu, s1, 1);
    s1 += __shfl_xor_sync(0xffffffffu, s1, 2);

    const int r0 = wm * 16 + (lane >> 2), r1 = r0 + 8;
    if ((lane & 3) == 0) {
        pm[wn * 64 + r0] = mx0;  pm[wn * 64 + r1] = mx1;
        psum[wn * 64 + r0] = s0; psum[wn * 64 + r1] = s1;
    }
    __syncthreads();

    float f0, f1;
    {
        float ma = pm[r0], mb = pm[64 + r0];
        float mg = fmaxf(ma, mb);
        float sg = psum[r0] * __expf(ma - mg) + psum[64 + r0] * __expf(mb - mg);
        f0 = __expf((wn ? mb : ma) - mg) / sg;
        ma = pm[r1]; mb = pm[64 + r1];
        mg = fmaxf(ma, mb);
        sg = psum[r1] * __expf(ma - mg) + psum[64 + r1] * __expf(mb - mg);
        f1 = __expf((wn ? mb : ma) - mg) / sg;
    }
#pragma unroll
    for (int nt = 0; nt < 13; nt++) {
        const int col = wn * 104 + nt * 8 + 2 * (lane & 3);
        *(__half2*)(sm + A_PS0 + r0 * 216 + col) =
            __halves2half2(__float2half_rn(sacc[nt][0] * f0), __float2half_rn(sacc[nt][1] * f0));
        *(__half2*)(sm + A_PS0 + r1 * 216 + col) =
            __halves2half2(__float2half_rn(sacc[nt][2] * f1), __float2half_rn(sacc[nt][3] * f1));
    }
    __syncthreads();

    // ---- ctx = P @ (Vh + Vl) ----
    float vacc[2][4];
#pragma unroll
    for (int i = 0; i < 2; i++)
#pragma unroll
        for (int j = 0; j < 4; j++) vacc[i][j] = 0.f;
    {
        const int ar = wm * 16 + (lane & 15);
        const int ak = (lane >> 4) * 8;
        const int vr = (lane & 15);
        const int vc = wn * 16 + (lane >> 4) * 8;
#pragma unroll
        for (int ks = 0; ks < 13; ks++) {
            unsigned ap[4], bvh[4], bvl[4];
            ldm4(ap[0], ap[1], ap[2], ap[3],
                 sb + (A_PS0 + ar * 216 + ks * 16 + ak) * 2);
            ldm4t(bvh[0], bvh[1], bvh[2], bvh[3],
                  sb + (A_VH0 + (ks * 16 + vr) * 40 + vc) * 2);
            ldm4t(bvl[0], bvl[1], bvl[2], bvl[3],
                  sb + (A_VL0 + (ks * 16 + vr) * 40 + vc) * 2);
            mma16816(vacc[0], ap, bvh[0], bvh[1]);
            mma16816(vacc[0], ap, bvl[0], bvl[1]);
            mma16816(vacc[1], ap, bvh[2], bvh[3]);
            mma16816(vacc[1], ap, bvl[2], bvl[3]);
        }
    }

    // ---- store ctx hi/lo ----
    {
        const int gr = g0 + wm * 16 + (lane >> 2);
        const int dc = wn * 16 + 2 * (lane & 3);
#pragma unroll
        for (int nt = 0; nt < 2; nt++) {
            const int d = dc + nt * 8;
#pragma unroll
            for (int hh = 0; hh < 2; hh++) {
                const int gene = gr + hh * 8;
                if (gene >= G) continue;
                const size_t off = (size_t)(b * G + gene) * 256 + h * 32 + d;
                __half h0, l0, h1, l1;
                splith(vacc[nt][hh * 2 + 0], h0, l0);
                splith(vacc[nt][hh * 2 + 1], h1, l1);
                *(__half2*)(cxh + off) = __halves2half2(h0, h1);
                *(__half2*)(cxl + off) = __halves2half2(l0, l1);
            }
        }
    }
}

// ---------------------------------------------------------------------------
// weight convert: fp32 -> fp16, 23 segments
// ---------------------------------------------------------------------------
struct CSeg { const float* src; __half* h; int blk_off; };
struct CTable { CSeg seg[23]; };
__global__ void __launch_bounds__(256) wconv_kernel(CTable t)
{
    const int bt = blockIdx.x;
    int s = 0;
#pragma unroll
    for (int i = 1; i < 23; i++) if (t.seg[i].blk_off <= bt) s = i;
    const CSeg sg = t.seg[s];
    const int idx = (bt - sg.blk_off) * 1024 + threadIdx.x * 4;
    float4 v = *(const float4*)(sg.src + idx);
    *(__half2*)(sg.h + idx)     = __halves2half2(__float2half_rn(v.x), __float2half_rn(v.y));
    *(__half2*)(sg.h + idx + 2) = __halves2half2(__float2half_rn(v.z), __float2half_rn(v.w));
}

// merged prep
__global__ void __launch_bounds__(256) prep_kernel(
    const float* __restrict__ pf, const int* __restrict__ coords,
    const float* __restrict__ re, const float* __restrict__ ce,
    const float* __restrict__ gq,
    __half* __restrict__ pfh, __half* __restrict__ pfl,
    __half* __restrict__ peh, __half* __restrict__ pel,
    float* __restrict__ q, __half* __restrict__ qh, __half* __restrict__ ql)
{
    const int bid = blockIdx.x;
    if (bid < 392) {
        int idx = (bid * 256 + threadIdx.x) * 4;
        float4 v = *(const float4*)(pf + idx);
        __half hh, ll;
        splith(v.x, hh, ll); pfh[idx + 0] = hh; pfl[idx + 0] = ll;
        splith(v.y, hh, ll); pfh[idx + 1] = hh; pfl[idx + 1] = ll;
        splith(v.z, hh, ll); pfh[idx + 2] = hh; pfl[idx + 2] = ll;
        splith(v.w, hh, ll); pfh[idx + 3] = hh; pfl[idx + 3] = ll;
    } else if (bid < 784) {
        int idx = (bid - 392) * 256 + threadIdx.x;
        if (idx < B * P * D) {
            int d = idx & 255;
            int bp = idx >> 8;
            int r = coords[bp * 2 + 0];
            int c = coords[bp * 2 + 1];
            r = min(max(r, 0), 255);
            c = min(max(c, 0), 255);
            float v = (d < 128) ? re[r * 128 + d] : ce[c * 128 + (d - 128)];
            __half h, l;
            splith(v, h, l);
            peh[idx] = h;
            pel[idx] = l;
        }
    } else {
        int idx = (bid - 784) * 256 + threadIdx.x;
        float v = gq[idx % (G * D)];
        q[idx] = v;
        __half h, l;
        splith(v, h, l);
        qh[idx] = h;
        ql[idx] = l;
    }
}

// ---------------------------------------------------------------------------
// LN (+optional fp16 hi/lo emit)
// ---------------------------------------------------------------------------
__global__ void ln_kernel(const float* __restrict__ x, const float* __restrict__ r,
                          const float* __restrict__ gg, const float* __restrict__ bb,
                          float* __restrict__ y,
                          __half* __restrict__ yh, __half* __restrict__ yl,
                          int rows)
{
    int gid = blockIdx.x * blockDim.x + threadIdx.x;
    int row = gid >> 5;
    int lane = gid & 31;
    if (row >= rows) return;
    const float* xp = x + (size_t)row * 256;
    float4 a = *(const float4*)(xp + lane * 4);
    float4 c = *(const float4*)(xp + 128 + lane * 4);
    if (r) {
        const float* rp = r + (size_t)row * 256;
        float4 ra = *(const float4*)(rp + lane * 4);
        float4 rc = *(const float4*)(rp + 128 + lane * 4);
        a.x += ra.x; a.y += ra.y; a.z += ra.z; a.w += ra.w;
        c.x += rc.x; c.y += rc.y; c.z += rc.z; c.w += rc.w;
    }
    float s = a.x + a.y + a.z + a.w + c.x + c.y + c.z + c.w;
    float q = a.x * a.x + a.y * a.y + a.z * a.z + a.w * a.w
            + c.x * c.x + c.y * c.y + c.z * c.z + c.w * c.w;
#pragma unroll
    for (int o = 16; o; o >>= 1) {
        s += __shfl_xor_sync(0xffffffffu, s, o);
        q += __shfl_xor_sync(0xffffffffu, q, o);
    }
    float mean = s * (1.f / 256.f);
    float var = q * (1.f / 256.f) - mean * mean;
    float rstd = rsqrtf(var + 1e-5f);
    float4 g0 = *(const float4*)(gg + lane * 4);
    float4 g1 = *(const float4*)(gg + 128 + lane * 4);
    float4 b0 = *(const float4*)(bb + lane * 4);
    float4 b1 = *(const float4*)(bb + 128 + lane * 4);
    float4 o0, o1;
    o0.x = (a.x - mean) * rstd * g0.x + b0.x;
    o0.y = (a.y - mean) * rstd * g0.y + b0.y;
    o0.z = (a.z - mean) * rstd * g0.z + b0.z;
    o0.w = (a.w - mean) * rstd * g0.w + b0.w;
    o1.x = (c.x - mean) * rstd * g1.x + b1.x;
    o1.y = (c.y - mean) * rstd * g1.y + b1.y;
    o1.z = (c.z - mean) * rstd * g1.z + b1.z;
    o1.w = (c.w - mean) * rstd * g1.w + b1.w;
    float* yp = y + (size_t)row * 256;
    *(float4*)(yp + lane * 4) = o0;
    *(float4*)(yp + 128 + lane * 4) = o1;
    if (yh) {
        const float ov[8] = {o0.x, o0.y, o0.z, o0.w, o1.x, o1.y, o1.z, o1.w};
        __half hv[8], lv[8];
#pragma unroll
        for (int i = 0; i < 8; i++) splith(ov[i], hv[i], lv[i]);
        const size_t b0o = (size_t)row * 256 + lane * 4;
        *(__half2*)(yh + b0o)       = __halves2half2(hv[0], hv[1]);
        *(__half2*)(yh + b0o + 2)   = __halves2half2(hv[2], hv[3]);
        *(__half2*)(yh + b0o + 128) = __halves2half2(hv[4], hv[5]);
        *(__half2*)(yh + b0o + 130) = __halves2half2(hv[6], hv[7]);
        *(__half2*)(yl + b0o)       = __halves2half2(lv[0], lv[1]);
        *(__half2*)(yl + b0o + 2)   = __halves2half2(lv[2], lv[3]);
        *(__half2*)(yl + b0o + 128) = __halves2half2(lv[4], lv[5]);
        *(__half2*)(yl + b0o + 130) = __halves2half2(lv[6], lv[7]);
    }
}

__global__ void __launch_bounds__(256) head_kernel(
    const float* __restrict__ qp, const float* __restrict__ pp, float* __restrict__ out)
{
    const int bp = blockIdx.y;
    const int b = (bp >= P) ? 1 : 0;
    const int g = blockIdx.x * 8 + (threadIdx.x >> 5);
    const int hh = (threadIdx.x & 31) << 2;
    float4 pv = *(const float4*)(pp + (size_t)bp * HALF + hh);
    float4 qv = *(const float4*)(qp + (size_t)(b * G + g) * HALF + hh);
    float4 o;
    o.x = softplusf(pv.x + qv.x);
    o.y = softplusf(pv.y + qv.y);
    o.z = softplusf(pv.z + qv.z);
    o.w = softplusf(pv.w + qv.w);
    *(float4*)(out + ((size_t)bp * G + g) * HALF + hh) = o;
}

// ---------------------------------------------------------------------------
extern "C" void kernel_launch(void* const* d_in, const int* in_sizes, int n_in,
                              void* d_out, int out_size)
{
    (void)in_sizes; (void)n_in; (void)out_size;
    const float* patch_features = (const float*)d_in[0];
    const int*   patch_coords   = (const int*)d_in[1];
    const float* patch_proj_w   = (const float*)d_in[2];
    const float* patch_proj_b   = (const float*)d_in[3];
    const float* patch_ln_g     = (const float*)d_in[4];
    const float* patch_ln_b     = (const float*)d_in[5];
    const float* row_embed      = (const float*)d_in[6];
    const float* col_embed      = (const float*)d_in[7];
    const float* pe_proj_w      = (const float*)d_in[8];
    const float* pe_proj_b      = (const float*)d_in[9];
    const float* gene_queries   = (const float*)d_in[10];
    const float* in_proj_w      = (const float*)d_in[11];
    const float* in_proj_b      = (const float*)d_in[12];
    const float* out_w          = (const float*)d_in[13];
    const float* out_b          = (const float*)d_in[14];
    const float* ff1_w          = (const float*)d_in[15];
    const float* ff1_b          = (const float*)d_in[16];
    const float* ff2_w          = (const float*)d_in[17];
    const float* ff2_b          = (const float*)d_in[18];
    const float* ln1_g          = (const float*)d_in[19];
    const float* ln1_b          = (const float*)d_in[20];
    const float* ln2_g          = (const float*)d_in[21];
    const float* ln2_b          = (const float*)d_in[22];
    const float* head_w1        = (const float*)d_in[23];
    const float* head_b1        = (const float*)d_in[24];
    float* out = (float*)d_out;

    cudaFuncSetAttribute(mma_gemm_kernel<128>, cudaFuncAttributeMaxDynamicSharedMemorySize, MMASM128);
    cudaFuncSetAttribute(mma_gemm_kernel<64>,  cudaFuncAttributeMaxDynamicSharedMemorySize, MMASM64);
    cudaFuncSetAttribute(mma_gemm_dual_kernel, cudaFuncAttributeMaxDynamicSharedMemorySize, MMASM64);
    cudaFuncSetAttribute(attn_mma_kernel,      cudaFuncAttributeMaxDynamicSharedMemorySize, ATTSM);

    float* ws = nullptr;
    cudaGetSymbolAddress((void**)&ws, g_ws);
    __half* hf = nullptr;
    cudaGetSymbolAddress((void**)&hf, g_hf);

    float* patch_emb = ws + OFF_PATCH;
    float* tmp       = ws + OFF_TMP;
    float* q         = ws + OFF_Q;
    float* att       = ws + OFF_ATT;
    float* qproj     = ws + OFF_QP;
    float* pproj     = ws + OFF_PP;

    __half* qh  = hf + HF_QH;
    __half* ql  = hf + HF_QL;
    __half* l1h = hf + HF_L1H;
    __half* l1l = hf + HF_L1L;
    __half* cxh = hf + HF_CXH;
    __half* cxl = hf + HF_CXL;
    __half* fh  = hf + HF_FH;
    __half* fl  = hf + HF_FL;
    __half* qbh = hf + HF_QBH;
    __half* qbl = hf + HF_QBL;
    __half* kvh = hf + HF_KVH;
    __half* kvl = hf + HF_KVL;
    __half* pfh = hf + HF_PFH;
    __half* pfl = hf + HF_PFL;
    __half* peh = hf + HF_PEH;
    __half* pel = hf + HF_PEL;
    __half* pch = hf + HF_PCH;
    __half* pcl = hf + HF_PCL;

    // ---- one-time weight convert ----
    CTable ct;
    int total_blk;
    {
        int seg = 0, boff = 0;
        auto add = [&](const float* src, size_t ho, int count) {
            ct.seg[seg] = { src, hf + ho, boff };
            boff += count / 1024;
            seg++;
        };
        for (int l = 0; l < NL; l++)
            add(in_proj_w + (size_t)l * 3 * D * D, HF_WQ + (size_t)l * D * D, D * D);
        for (int l = 0; l < NL; l++)
            add(out_w + (size_t)l * D * D, HF_WO + (size_t)l * D * D, D * D);
        for (int l = 0; l < NL; l++)
            add(ff1_w + (size_t)l * 4 * D * D, HF_F1 + (size_t)l * 4 * D * D, 4 * D * D);
        for (int l = 0; l < NL; l++)
            add(ff2_w + (size_t)l * 4 * D * D, HF_F2 + (size_t)l * 4 * D * D, 4 * D * D);
        add(head_w1, HF_HD, HALF * D);
        add(patch_proj_w, HF_WP, D * FD);
        add(pe_proj_w, HF_WE, D * D);
        for (int l = 0; l < NL; l++)
            add(in_proj_w + (size_t)l * 3 * D * D + D * D, HF_WK + (size_t)l * 2 * D * D, 2 * D * D);
        total_blk = boff;
    }
    wconv_kernel<<<total_blk, 256>>>(ct);
    prep_kernel<<<4784, 256>>>(patch_features, patch_coords, row_embed, col_embed,
                               gene_queries, pfh, pfl, peh, pel, q, qh, ql);

    const int MT64  = (MQ + 63) / 64;     // 63
    const int MT128 = (MQ + 127) / 128;   // 32
    const int MTP   = (MP + 63) / 64;     // 7

    auto GA = [](const __half* Ah, const __half* Al, const __half* Wh,
                 const float* bias, const float* R,
                 float* Cf, __half* Ch, __half* Cl,
                 int M, int N, int K, int act) {
        GArgs g;
        g.Ah = Ah; g.Al = Al; g.Wh = Wh; g.bias = bias; g.R = R;
        g.Cf = Cf; g.Ch = Ch; g.Cl = Cl;
        g.M = M; g.N = N; g.K = K; g.act = act; g.ntx = N / 64;
        return g;
    };

    // ---- Stage A ----
    mma_gemm_kernel<64><<<dim3(D / 64, MTP), 256, MMASM64>>>(
        GA(pfh, pfl, hf + HF_WP, patch_proj_b, nullptr, tmp, nullptr, nullptr, MP, D, FD, 0));
    ln_kernel<<<(MP + 7) / 8, 256>>>(tmp, nullptr, patch_ln_g, patch_ln_b, patch_emb,
                                     nullptr, nullptr, MP);
    mma_gemm_kernel<64><<<dim3(D / 64, MTP), 256, MMASM64>>>(
        GA(peh, pel, hf + HF_WE, pe_proj_b, patch_emb, nullptr, pch, pcl, MP, D, D, 0));

    // ---- Stage B ----
    for (int l = 0; l < NL; l++) {
        const float* bq  = in_proj_b + (size_t)l * 3 * D;
        const float* bkv = bq + D;
        GArgs gq = GA(qh, ql, hf + HF_WQ + (size_t)l * D * D, bq, nullptr,
                      nullptr, qbh, qbl, MQ, D, D, 0);
        GArgs gk = GA(pch, pcl, hf + HF_WK + (size_t)l * 2 * D * D, bkv, nullptr,
                      nullptr, kvh, kvl, MP, 2 * D, D, 0);
        const int splitQ = gq.ntx * MT64;
        const int totQ   = splitQ + gk.ntx * MTP;
        mma_gemm_dual_kernel<<<totQ, 256, MMASM64>>>(gq, gk, splitQ);

        attn_mma_kernel<<<dim3(B * H, 32), 256, ATTSM>>>(qbh, qbl, kvh, kvl, cxh, cxl);

        // out-proj + residual(q) -> att; ln1 reads att only
        mma_gemm_kernel<64><<<dim3(D / 64, MT64), 256, MMASM64>>>(
            GA(cxh, cxl, hf + HF_WO + (size_t)l * D * D, out_b + (size_t)l * D, q,
               att, nullptr, nullptr, MQ, D, D, 0));
        ln_kernel<<<(MQ + 7) / 8, 256>>>(att, nullptr, ln1_g + (size_t)l * D, ln1_b + (size_t)l * D,
                                         q, l1h, l1l, MQ);
        mma_gemm_kernel<128><<<dim3(4 * D / 64, MT128), 256, MMASM128>>>(
            GA(l1h, l1l, hf + HF_F1 + (size_t)l * 4 * D * D, ff1_b + (size_t)l * 4 * D, nullptr,
               nullptr, fh, fl, MQ, 4 * D, D, 1));
        // ff2 + residual(q) -> att; ln2 reads att only
        mma_gemm_kernel<64><<<dim3(D / 64, MT64), 256, MMASM64>>>(
            GA(fh, fl, hf + HF_F2 + (size_t)l * 4 * D * D, ff2_b + (size_t)l * D, q,
               att, nullptr, nullptr, MQ, D, 4 * D, 0));
        ln_kernel<<<(MQ + 7) / 8, 256>>>(att, nullptr, ln2_g + (size_t)l * D, ln2_b + (size_t)l * D,
                                         q, qh, ql, MQ);
    }

    // ---- Stage C ----
    {
        GArgs gq = GA(qh, ql, hf + HF_HD, head_b1, nullptr,
                      qproj, nullptr, nullptr, MQ, HALF, D, 0);
        GArgs gp = GA(pch, pcl, hf + HF_HD, nullptr, nullptr,
                      pproj, nullptr, nullptr, MP, HALF, D, 0);
        const int splitH = gq.ntx * MT64;
        const int totH   = splitH + gp.ntx * MTP;
        mma_gemm_dual_kernel<<<totH, 256, MMASM64>>>(gq, gp, splitH);
    }
    head_kernel<<<dim3(G / 8, B * P), 256>>>(qproj, pproj, out);
}

// round 13
// speedup vs baseline: 1.8127x; 1.3004x over previous
#include <cuda_runtime.h>
#include <cuda_fp16.h>
#include <cstddef>
#include <cstdint>
#include <math.h>

// ---------------------------------------------------------------------------
// SpatialTranscriptomicsDecoder — GB300 sm_103a. Round 13.
// Single-term fp16 mma everywhere (A and B rounded once): halves mma count,
// smem traffic, and all hi/lo producer machinery. TC fused attention kept.
// ---------------------------------------------------------------------------

static constexpr int B = 2, P = 196, FD = 1024, G = 2000, D = 256, H = 8, NL = 4, HALF = 128;
static constexpr float ATT_SCALE = 0.17677669529663687f;
static constexpr int MQ = B * G;   // 4000
static constexpr int MP = B * P;   // 392

// ---------------- fp32 workspace ----------------
static constexpr size_t OFF_PATCH = 0;
static constexpr size_t OFF_TMP   = OFF_PATCH + (size_t)MP * D;
static constexpr size_t OFF_Q     = OFF_TMP   + (size_t)MP * D;
static constexpr size_t OFF_ATT   = OFF_Q     + (size_t)MQ * D;
static constexpr size_t OFF_QP    = OFF_ATT   + (size_t)MQ * D;
static constexpr size_t OFF_PP    = OFF_QP    + (size_t)MQ * HALF;
static constexpr size_t WS_TOTAL  = OFF_PP    + (size_t)MP * HALF;
__device__ float g_ws[WS_TOTAL];

// ---------------- fp16 workspace ----------------
static constexpr size_t BQ  = (size_t)MQ * D;
static constexpr size_t HF_QH  = 0;
static constexpr size_t HF_L1H = HF_QH + BQ;
static constexpr size_t HF_CXH = HF_L1H + BQ;
static constexpr size_t HF_FH  = HF_CXH + BQ;
static constexpr size_t HF_QBH = HF_FH + (size_t)MQ * 4 * D;
static constexpr size_t HF_KVH = HF_QBH + BQ;
static constexpr size_t HF_PFH = HF_KVH + (size_t)MP * 2 * D;
static constexpr size_t HF_PEH = HF_PFH + (size_t)MP * FD;
static constexpr size_t HF_PCH = HF_PEH + (size_t)MP * D;
static constexpr size_t HF_WQ  = HF_PCH + (size_t)MP * D;
static constexpr size_t HF_WO  = HF_WQ  + (size_t)NL * D * D;
static constexpr size_t HF_F1  = HF_WO  + (size_t)NL * D * D;
static constexpr size_t HF_F2  = HF_F1  + (size_t)NL * 4 * D * D;
static constexpr size_t HF_HD  = HF_F2  + (size_t)NL * 4 * D * D;
static constexpr size_t HF_WP  = HF_HD  + (size_t)HALF * D;
static constexpr size_t HF_WE  = HF_WP  + (size_t)D * FD;
static constexpr size_t HF_WK  = HF_WE  + (size_t)D * D;
static constexpr size_t HF_TOTAL = HF_WK + (size_t)NL * 2 * D * D;
__device__ __half g_hf[HF_TOTAL];

// ---------------- helpers ----------------
__device__ __forceinline__ float geluf(float x) {
    return 0.5f * x * (1.0f + erff(x * 0.7071067811865476f));
}
__device__ __forceinline__ float softplusf(float x) {
    return fmaxf(x, 0.0f) + __logf(1.0f + __expf(-fabsf(x)));
}
__device__ __forceinline__ void cpa16(unsigned int dst, const void* src, bool ok) {
    asm volatile("cp.async.ca.shared.global [%0], [%1], 16, %2;"
                 :: "r"(dst), "l"(src), "r"(ok ? 16 : 0) : "memory");
}
__device__ __forceinline__ void cpa_commit() {
    asm volatile("cp.async.commit_group;" ::: "memory");
}
template<int Ng> __device__ __forceinline__ void cpa_waitg() {
    asm volatile("cp.async.wait_group %0;" :: "n"(Ng) : "memory");
}
__device__ __forceinline__ void ldm4(unsigned& r0, unsigned& r1, unsigned& r2, unsigned& r3,
                                     unsigned addr) {
    asm volatile("ldmatrix.sync.aligned.m8n8.x4.shared.b16 {%0,%1,%2,%3}, [%4];"
                 : "=r"(r0), "=r"(r1), "=r"(r2), "=r"(r3) : "r"(addr));
}
__device__ __forceinline__ void ldm4t(unsigned& r0, unsigned& r1, unsigned& r2, unsigned& r3,
                                      unsigned addr) {
    asm volatile("ldmatrix.sync.aligned.m8n8.x4.trans.shared.b16 {%0,%1,%2,%3}, [%4];"
                 : "=r"(r0), "=r"(r1), "=r"(r2), "=r"(r3) : "r"(addr));
}
__device__ __forceinline__ void mma16816(float* d, const unsigned* a, unsigned b0, unsigned b1) {
    asm volatile(
        "mma.sync.aligned.m16n8k16.row.col.f32.f16.f16.f32 "
        "{%0,%1,%2,%3}, {%4,%5,%6,%7}, {%8,%9}, {%0,%1,%2,%3};"
        : "+f"(d[0]), "+f"(d[1]), "+f"(d[2]), "+f"(d[3])
        : "r"(a[0]), "r"(a[1]), "r"(a[2]), "r"(a[3]), "r"(b0), "r"(b1));
}

// ---------------------------------------------------------------------------
// GEMM: C[M,N] = act( A @ W^T + bias + R ); A,W fp16 (rounded), acc fp32.
// ---------------------------------------------------------------------------
struct GArgs {
    const __half* Ah; const __half* Wh;
    const float* bias; const float* R;
    float* Cf; __half* Ch;
    int M, N, K, act, ntx;
};

template<int BM>
__device__ __forceinline__ void mma_gemm_impl(const GArgs& g, int bx, int by)
{
    constexpr int STR = 24;
    constexpr int szA = BM * STR * 2;
    constexpr int szW = 64 * STR * 2;
    constexpr int STG = szA + szW;
    constexpr int MT  = 2;
    constexpr int WMASK  = (BM == 128) ? 3 : 1;
    constexpr int WSHIFT = (BM == 128) ? 2 : 1;
    constexpr int NT8 = (BM == 128) ? 4 : 2;
    constexpr int NP  = NT8 / 2;

    extern __shared__ char smem[];
    const unsigned sb = (unsigned)__cvta_generic_to_shared(smem);

    const int tid = threadIdx.x;
    const int lane = tid & 31, wid = tid >> 5;
    const int wm = wid & WMASK, wn = wid >> WSHIFT;
    const int bm = by * BM;
    const int bn = bx * 64;
    const int NC = g.K >> 4;
    const int M = g.M, N = g.N, K = g.K;

    unsigned off = 0;
    const __half* src = nullptr;
    bool okf = false;
    if (BM == 128) {
        // A: all threads (128 rows x 2 segs); W: tid<128 (64 rows x 2 segs)
        if (tid < 128) {
            const int rowW = tid >> 1, segW = tid & 1;
            off = (unsigned)(szA + (rowW * STR + segW * 8) * 2);
            src = g.Wh + (size_t)(bn + rowW) * K + segW * 8;
            okf = true;
        }
    } else {
        if (tid >= 128) {
            const int rowW = (tid - 128) >> 1, segW = tid & 1;
            off = (unsigned)(szA + (rowW * STR + segW * 8) * 2);
            src = g.Wh + (size_t)(bn + rowW) * K + segW * 8;
            okf = true;
        }
    }
    unsigned offA = 0;
    const __half* srcA = nullptr;
    bool aok = false, doA = false;
    if (BM == 128) {
        const int rowA = tid >> 1, segA = tid & 1;
        doA = true;
        aok = (bm + rowA) < M;
        offA = (unsigned)((rowA * STR + segA * 8) * 2);
        srcA = g.Ah + (size_t)(bm + rowA) * K + segA * 8;
    } else if (tid < 128) {
        const int rowA = tid >> 1, segA = tid & 1;
        doA = true;
        aok = (bm + rowA) < M;
        offA = (unsigned)((rowA * STR + segA * 8) * 2);
        srcA = g.Ah + (size_t)(bm + rowA) * K + segA * 8;
    }

    auto loadChunk = [&](int kc, int s) {
        const int o = kc << 4;
        const unsigned base = sb + s * STG;
        if (doA) cpa16(base + offA, srcA + o, aok);
        if (src) cpa16(base + off, src + o, okf);
        cpa_commit();
    };

    unsigned aoffH[MT], boffH[NP];
    {
        const int ar = wm * 32 + (lane & 15);
        const int ak = (lane >> 4) * 8;
        const int br = wn * (NT8 * 8) + (lane & 7) + ((lane >> 4) << 3);
        const int bk = ((lane >> 3) & 1) * 8;
#pragma unroll
        for (int t = 0; t < MT; t++) aoffH[t] = (unsigned)(((ar + t * 16) * STR + ak) * 2);
#pragma unroll
        for (int p = 0; p < NP; p++) boffH[p] = (unsigned)(szA + ((br + p * 16) * STR + bk) * 2);
    }

    loadChunk(0, 0);
    loadChunk(1, 1);
    loadChunk(2, 2);

    float acc[MT][NT8][4];
#pragma unroll
    for (int i = 0; i < MT; i++)
#pragma unroll
        for (int j = 0; j < NT8; j++)
#pragma unroll
            for (int k = 0; k < 4; k++) acc[i][j][k] = 0.f;

    for (int kc = 0; kc < NC; kc++) {
        cpa_waitg<2>();
        __syncthreads();
        const int s = kc & 3;
        const int nk = kc + 3;
        if (nk < NC) loadChunk(nk, nk & 3);
        else cpa_commit();

        const unsigned stg = sb + s * STG;
        unsigned ah[MT][4], bh[NP][4];
#pragma unroll
        for (int t = 0; t < MT; t++)
            ldm4(ah[t][0], ah[t][1], ah[t][2], ah[t][3], stg + aoffH[t]);
#pragma unroll
        for (int p = 0; p < NP; p++)
            ldm4(bh[p][0], bh[p][1], bh[p][2], bh[p][3], stg + boffH[p]);
#pragma unroll
        for (int mt = 0; mt < MT; mt++) {
#pragma unroll
            for (int nt = 0; nt < NT8; nt++) {
                const int p = nt >> 1, nh = (nt & 1) << 1;
                mma16816(acc[mt][nt], ah[mt], bh[p][nh], bh[p][nh + 1]);
            }
        }
    }

    const int rowb = bm + wm * 32 + (lane >> 2);
    const int colb = bn + wn * (NT8 * 8) + 2 * (lane & 3);
#pragma unroll
    for (int mt = 0; mt < MT; mt++) {
#pragma unroll
        for (int nt = 0; nt < NT8; nt++) {
            const int col = colb + nt * 8;
            float2 b2 = make_float2(0.f, 0.f);
            if (g.bias) b2 = *(const float2*)(g.bias + col);
#pragma unroll
            for (int hh = 0; hh < 2; hh++) {
                const int row = rowb + mt * 16 + hh * 8;
                if (row >= M) continue;
                float v0 = acc[mt][nt][hh * 2 + 0] + b2.x;
                float v1 = acc[mt][nt][hh * 2 + 1] + b2.y;
                if (g.R) {
                    float2 r2 = *(const float2*)(g.R + (size_t)row * N + col);
                    v0 += r2.x; v1 += r2.y;
                }
                if (g.act == 1) { v0 = geluf(v0); v1 = geluf(v1); }
                if (g.Cf) *(float2*)(g.Cf + (size_t)row * N + col) = make_float2(v0, v1);
                if (g.Ch)
                    *(__half2*)(g.Ch + (size_t)row * N + col) =
                        __halves2half2(__float2half_rn(v0), __float2half_rn(v1));
            }
        }
    }
}

template<int BM>
__global__ void __launch_bounds__(256) mma_gemm_kernel(GArgs g)
{
    mma_gemm_impl<BM>(g, blockIdx.x, blockIdx.y);
}

__global__ void __launch_bounds__(256) mma_gemm_dual_kernel(GArgs g0, GArgs g1, int split)
{
    if ((int)blockIdx.x < split) {
        const int local = blockIdx.x;
        mma_gemm_impl<64>(g0, local % g0.ntx, local / g0.ntx);
    } else {
        const int local = blockIdx.x - split;
        mma_gemm_impl<64>(g1, local % g1.ntx, local / g1.ntx);
    }
}

static constexpr int MMASM128 = 4 * (128 * 24 * 2 + 64 * 24 * 2);  // 36864
static constexpr int MMASM64  = 4 * (64 * 24 * 2 + 64 * 24 * 2);   // 24576

// ---------------------------------------------------------------------------
// Fused tensor-core attention (single-term). grid (B*H, 32), 256 thr (4m x 2n).
// smem halfs: Qh[64x40]=2560, Kh[224x40]=8960, Vh[224x40]=8960, Ps[64x216]=13824
// ---------------------------------------------------------------------------
static constexpr int A_QH0 = 0;
static constexpr int A_KH0 = 2560;
static constexpr int A_VH0 = A_KH0 + 8960;      // 11520
static constexpr int A_PS0 = A_VH0 + 8960;      // 20480
static constexpr int A_PARTB = (A_PS0 + 13824) * 2;   // 68608 bytes
static constexpr int ATTSM = A_PARTB + 2048;

__global__ void __launch_bounds__(256) attn_mma_kernel(
    const __half* __restrict__ Qh_g, const __half* __restrict__ KVh,
    __half* __restrict__ cxh)
{
    extern __shared__ char smem[];
    __half* sm = (__half*)smem;
    float* pm   = (float*)(smem + A_PARTB);   // [2][64]
    float* psum = pm + 128;
    const unsigned sb = (unsigned)__cvta_generic_to_shared(smem);

    const int bh = blockIdx.x;
    const int b = bh >> 3, h = bh & 7;
    const int g0 = blockIdx.y * 64;
    const int tid = threadIdx.x;
    const int lane = tid & 31, wid = tid >> 5;
    const int wm = wid & 3, wn = wid >> 2;

    // ---- loads ----
    if (tid < 128) {   // Q: 64 rows x 32 halfs
        const int row = tid >> 1;
        const int sp = (tid & 1) * 16;
        const bool ok = (g0 + row) < G;
        const __half* src = Qh_g + ((size_t)(b * G + g0 + row) * 256 + h * 32 + sp);
        unsigned dst = sb + (A_QH0 + row * 40 + sp) * 2;
        cpa16(dst, src, ok);
        cpa16(dst + 16, src + 8, ok);
    }
    if (tid < 196) {   // K, V row tid
        const size_t rb = (size_t)(b * P + tid) * 512 + h * 32;
        const __half* ksrc = KVh + rb;
        unsigned kdst = sb + (A_KH0 + tid * 40) * 2;
        cpa16(kdst,      ksrc,      true);
        cpa16(kdst + 16, ksrc + 8,  true);
        cpa16(kdst + 32, ksrc + 16, true);
        cpa16(kdst + 48, ksrc + 24, true);
        const __half* vh = KVh + rb + 256;
        unsigned vhd = sb + (A_VH0 + tid * 40) * 2;
        cpa16(vhd,      vh,      true);
        cpa16(vhd + 16, vh + 8,  true);
        cpa16(vhd + 32, vh + 16, true);
        cpa16(vhd + 48, vh + 24, true);
    } else if (tid < 224) {
        uint4 z = make_uint4(0, 0, 0, 0);
#pragma unroll
        for (int i = 0; i < 5; i++) {
            *(uint4*)(sm + A_KH0 + tid * 40 + i * 8) = z;
            *(uint4*)(sm + A_VH0 + tid * 40 + i * 8) = z;
        }
    }
    cpa_commit();
    cpa_waitg<0>();
    __syncthreads();

    // ---- S = Q @ K^T ----
    unsigned aq[2][4];
    {
        const int ar = wm * 16 + (lane & 15);
        const int ak = (lane >> 4) * 8;
#pragma unroll
        for (int ks = 0; ks < 2; ks++)
            ldm4(aq[ks][0], aq[ks][1], aq[ks][2], aq[ks][3],
                 sb + (A_QH0 + ar * 40 + ks * 16 + ak) * 2);
    }
    float sacc[13][4];
#pragma unroll
    for (int i = 0; i < 13; i++)
#pragma unroll
        for (int j = 0; j < 4; j++) sacc[i][j] = 0.f;

    {
        const int brr = wn * 104 + (lane & 7) + ((lane >> 4) << 3);
        const int bko = ((lane >> 3) & 1) * 8;
#pragma unroll
        for (int gph = 0; gph < 7; gph++) {
            unsigned bk0[4], bk1[4];
            ldm4(bk0[0], bk0[1], bk0[2], bk0[3],
                 sb + (A_KH0 + (brr + gph * 16) * 40 + bko) * 2);
            ldm4(bk1[0], bk1[1], bk1[2], bk1[3],
                 sb + (A_KH0 + (brr + gph * 16) * 40 + 16 + bko) * 2);
#pragma unroll
            for (int hf = 0; hf < 2; hf++) {
                const int nt = gph * 2 + hf;
                if (nt >= 13) break;
                mma16816(sacc[nt], aq[0], bk0[hf * 2], bk0[hf * 2 + 1]);
                mma16816(sacc[nt], aq[1], bk1[hf * 2], bk1[hf * 2 + 1]);
            }
        }
    }

    // ---- softmax (split across wn) ----
#pragma unroll
    for (int nt = 0; nt < 13; nt++)
#pragma unroll
        for (int j = 0; j < 4; j++) sacc[nt][j] *= ATT_SCALE;

    float mx0 = -1e30f, mx1 = -1e30f;
#pragma unroll
    for (int nt = 0; nt < 13; nt++) {
        mx0 = fmaxf(mx0, fmaxf(sacc[nt][0], sacc[nt][1]));
        mx1 = fmaxf(mx1, fmaxf(sacc[nt][2], sacc[nt][3]));
    }
    mx0 = fmaxf(mx0, __shfl_xor_sync(0xffffffffu, mx0, 1));
    mx0 = fmaxf(mx0, __shfl_xor_sync(0xffffffffu, mx0, 2));
    mx1 = fmaxf(mx1, __shfl_xor_sync(0xffffffffu, mx1, 1));
    mx1 = fmaxf(mx1, __shfl_xor_sync(0xffffffffu, mx1, 2));

    float s0 = 0.f, s1 = 0.f;
#pragma unroll
    for (int nt = 0; nt < 13; nt++) {
        const int col = wn * 104 + nt * 8 + 2 * (lane & 3);
        float e0 = (col < 196)     ? __expf(sacc[nt][0] - mx0) : 0.f;
        float e1 = (col + 1 < 196) ? __expf(sacc[nt][1] - mx0) : 0.f;
        float e2 = (col < 196)     ? __expf(sacc[nt][2] - mx1) : 0.f;
        float e3 = (col + 1 < 196) ? __expf(sacc[nt][3] - mx1) : 0.f;
        sacc[nt][0] = e0; sacc[nt][1] = e1; sacc[nt][2] = e2; sacc[nt][3] = e3;
        s0 += e0 + e1; s1 += e2 + e3;
    }
    s0 += __shfl_xor_sync(0xffffffffu, s0, 1);
    s0 += __shfl_xor_sync(0xffffffffu, s0, 2);
    s1 += __shfl_xor_sync(0xffffffffu, s1, 1);
    s1 += __shfl_xor_sync(0xffffffffu, s1, 2);

    const int r0 = wm * 16 + (lane >> 2), r1 = r0 + 8;
    if ((lane & 3) == 0) {
        pm[wn * 64 + r0] = mx0;  pm[wn * 64 + r1] = mx1;
        psum[wn * 64 + r0] = s0; psum[wn * 64 + r1] = s1;
    }
    __syncthreads();

    float f0, f1;
    {
        float ma = pm[r0], mb = pm[64 + r0];
        float mg = fmaxf(ma, mb);
        float sg = psum[r0] * __expf(ma - mg) + psum[64 + r0] * __expf(mb - mg);
        f0 = __expf((wn ? mb : ma) - mg) / sg;
        ma = pm[r1]; mb = pm[64 + r1];
        mg = fmaxf(ma, mb);
        sg = psum[r1] * __expf(ma - mg) + psum[64 + r1] * __expf(mb - mg);
        f1 = __expf((wn ? mb : ma) - mg) / sg;
    }
#pragma unroll
    for (int nt = 0; nt < 13; nt++) {
        const int col = wn * 104 + nt * 8 + 2 * (lane & 3);
        *(__half2*)(sm + A_PS0 + r0 * 216 + col) =
            __halves2half2(__float2half_rn(sacc[nt][0] * f0), __float2half_rn(sacc[nt][1] * f0));
        *(__half2*)(sm + A_PS0 + r1 * 216 + col) =
            __halves2half2(__float2half_rn(sacc[nt][2] * f1), __float2half_rn(sacc[nt][3] * f1));
    }
    __syncthreads();

    // ---- ctx = P @ V ----
    float vacc[2][4];
#pragma unroll
    for (int i = 0; i < 2; i++)
#pragma unroll
        for (int j = 0; j < 4; j++) vacc[i][j] = 0.f;
    {
        const int ar = wm * 16 + (lane & 15);
        const int ak = (lane >> 4) * 8;
        const int vr = (lane & 15);
        const int vc = wn * 16 + (lane >> 4) * 8;
#pragma unroll
        for (int ks = 0; ks < 13; ks++) {
            unsigned ap[4], bvh[4];
            ldm4(ap[0], ap[1], ap[2], ap[3],
                 sb + (A_PS0 + ar * 216 + ks * 16 + ak) * 2);
            ldm4t(bvh[0], bvh[1], bvh[2], bvh[3],
                  sb + (A_VH0 + (ks * 16 + vr) * 40 + vc) * 2);
            mma16816(vacc[0], ap, bvh[0], bvh[1]);
            mma16816(vacc[1], ap, bvh[2], bvh[3]);
        }
    }

    // ---- store ctx ----
    {
        const int gr = g0 + wm * 16 + (lane >> 2);
        const int dc = wn * 16 + 2 * (lane & 3);
#pragma unroll
        for (int nt = 0; nt < 2; nt++) {
            const int d = dc + nt * 8;
#pragma unroll
            for (int hh = 0; hh < 2; hh++) {
                const int gene = gr + hh * 8;
                if (gene >= G) continue;
                const size_t off = (size_t)(b * G + gene) * 256 + h * 32 + d;
                *(__half2*)(cxh + off) =
                    __halves2half2(__float2half_rn(vacc[nt][hh * 2 + 0]),
                                   __float2half_rn(vacc[nt][hh * 2 + 1]));
            }
        }
    }
}

// ---------------------------------------------------------------------------
// weight convert: fp32 -> fp16, 23 segments
// ---------------------------------------------------------------------------
struct CSeg { const float* src; __half* h; int blk_off; };
struct CTable { CSeg seg[23]; };
__global__ void __launch_bounds__(256) wconv_kernel(CTable t)
{
    const int bt = blockIdx.x;
    int s = 0;
#pragma unroll
    for (int i = 1; i < 23; i++) if (t.seg[i].blk_off <= bt) s = i;
    const CSeg sg = t.seg[s];
    const int idx = (bt - sg.blk_off) * 1024 + threadIdx.x * 4;
    float4 v = *(const float4*)(sg.src + idx);
    *(__half2*)(sg.h + idx)     = __halves2half2(__float2half_rn(v.x), __float2half_rn(v.y));
    *(__half2*)(sg.h + idx + 2) = __halves2half2(__float2half_rn(v.z), __float2half_rn(v.w));
}

// merged prep
__global__ void __launch_bounds__(256) prep_kernel(
    const float* __restrict__ pf, const int* __restrict__ coords,
    const float* __restrict__ re, const float* __restrict__ ce,
    const float* __restrict__ gq,
    __half* __restrict__ pfh, __half* __restrict__ peh,
    float* __restrict__ q, __half* __restrict__ qh)
{
    const int bid = blockIdx.x;
    if (bid < 392) {
        int idx = (bid * 256 + threadIdx.x) * 4;
        float4 v = *(const float4*)(pf + idx);
        *(__half2*)(pfh + idx)     = __halves2half2(__float2half_rn(v.x), __float2half_rn(v.y));
        *(__half2*)(pfh + idx + 2) = __halves2half2(__float2half_rn(v.z), __float2half_rn(v.w));
    } else if (bid < 784) {
        int idx = (bid - 392) * 256 + threadIdx.x;
        if (idx < B * P * D) {
            int d = idx & 255;
            int bp = idx >> 8;
            int r = coords[bp * 2 + 0];
            int c = coords[bp * 2 + 1];
            r = min(max(r, 0), 255);
            c = min(max(c, 0), 255);
            float v = (d < 128) ? re[r * 128 + d] : ce[c * 128 + (d - 128)];
            peh[idx] = __float2half_rn(v);
        }
    } else {
        int idx = (bid - 784) * 256 + threadIdx.x;
        float v = gq[idx % (G * D)];
        q[idx] = v;
        qh[idx] = __float2half_rn(v);
    }
}

// ---------------------------------------------------------------------------
// LN (+optional fp16 emit)
// ---------------------------------------------------------------------------
__global__ void ln_kernel(const float* __restrict__ x, const float* __restrict__ r,
                          const float* __restrict__ gg, const float* __restrict__ bb,
                          float* __restrict__ y, __half* __restrict__ yh,
                          int rows)
{
    int gid = blockIdx.x * blockDim.x + threadIdx.x;
    int row = gid >> 5;
    int lane = gid & 31;
    if (row >= rows) return;
    const float* xp = x + (size_t)row * 256;
    float4 a = *(const float4*)(xp + lane * 4);
    float4 c = *(const float4*)(xp + 128 + lane * 4);
    if (r) {
        const float* rp = r + (size_t)row * 256;
        float4 ra = *(const float4*)(rp + lane * 4);
        float4 rc = *(const float4*)(rp + 128 + lane * 4);
        a.x += ra.x; a.y += ra.y; a.z += ra.z; a.w += ra.w;
        c.x += rc.x; c.y += rc.y; c.z += rc.z; c.w += rc.w;
    }
    float s = a.x + a.y + a.z + a.w + c.x + c.y + c.z + c.w;
    float q = a.x * a.x + a.y * a.y + a.z * a.z + a.w * a.w
            + c.x * c.x + c.y * c.y + c.z * c.z + c.w * c.w;
#pragma unroll
    for (int o = 16; o; o >>= 1) {
        s += __shfl_xor_sync(0xffffffffu, s, o);
        q += __shfl_xor_sync(0xffffffffu, q, o);
    }
    float mean = s * (1.f / 256.f);
    float var = q * (1.f / 256.f) - mean * mean;
    float rstd = rsqrtf(var + 1e-5f);
    float4 g0 = *(const float4*)(gg + lane * 4);
    float4 g1 = *(const float4*)(gg + 128 + lane * 4);
    float4 b0 = *(const float4*)(bb + lane * 4);
    float4 b1 = *(const float4*)(bb + 128 + lane * 4);
    float4 o0, o1;
    o0.x = (a.x - mean) * rstd * g0.x + b0.x;
    o0.y = (a.y - mean) * rstd * g0.y + b0.y;
    o0.z = (a.z - mean) * rstd * g0.z + b0.z;
    o0.w = (a.w - mean) * rstd * g0.w + b0.w;
    o1.x = (c.x - mean) * rstd * g1.x + b1.x;
    o1.y = (c.y - mean) * rstd * g1.y + b1.y;
    o1.z = (c.z - mean) * rstd * g1.z + b1.z;
    o1.w = (c.w - mean) * rstd * g1.w + b1.w;
    float* yp = y + (size_t)row * 256;
    *(float4*)(yp + lane * 4) = o0;
    *(float4*)(yp + 128 + lane * 4) = o1;
    if (yh) {
        const size_t b0o = (size_t)row * 256 + lane * 4;
        *(__half2*)(yh + b0o)       = __halves2half2(__float2half_rn(o0.x), __float2half_rn(o0.y));
        *(__half2*)(yh + b0o + 2)   = __halves2half2(__float2half_rn(o0.z), __float2half_rn(o0.w));
        *(__half2*)(yh + b0o + 128) = __halves2half2(__float2half_rn(o1.x), __float2half_rn(o1.y));
        *(__half2*)(yh + b0o + 130) = __halves2half2(__float2half_rn(o1.z), __float2half_rn(o1.w));
    }
}

__global__ void __launch_bounds__(256) head_kernel(
    const float* __restrict__ qp, const float* __restrict__ pp, float* __restrict__ out)
{
    const int bp = blockIdx.y;
    const int b = (bp >= P) ? 1 : 0;
    const int g = blockIdx.x * 8 + (threadIdx.x >> 5);
    const int hh = (threadIdx.x & 31) << 2;
    float4 pv = *(const float4*)(pp + (size_t)bp * HALF + hh);
    float4 qv = *(const float4*)(qp + (size_t)(b * G + g) * HALF + hh);
    float4 o;
    o.x = softplusf(pv.x + qv.x);
    o.y = softplusf(pv.y + qv.y);
    o.z = softplusf(pv.z + qv.z);
    o.w = softplusf(pv.w + qv.w);
    *(float4*)(out + ((size_t)bp * G + g) * HALF + hh) = o;
}

// ---------------------------------------------------------------------------
extern "C" void kernel_launch(void* const* d_in, const int* in_sizes, int n_in,
                              void* d_out, int out_size)
{
    (void)in_sizes; (void)n_in; (void)out_size;
    const float* patch_features = (const float*)d_in[0];
    const int*   patch_coords   = (const int*)d_in[1];
    const float* patch_proj_w   = (const float*)d_in[2];
    const float* patch_proj_b   = (const float*)d_in[3];
    const float* patch_ln_g     = (const float*)d_in[4];
    const float* patch_ln_b     = (const float*)d_in[5];
    const float* row_embed      = (const float*)d_in[6];
    const float* col_embed      = (const float*)d_in[7];
    const float* pe_proj_w      = (const float*)d_in[8];
    const float* pe_proj_b      = (const float*)d_in[9];
    const float* gene_queries   = (const float*)d_in[10];
    const float* in_proj_w      = (const float*)d_in[11];
    const float* in_proj_b      = (const float*)d_in[12];
    const float* out_w          = (const float*)d_in[13];
    const float* out_b          = (const float*)d_in[14];
    const float* ff1_w          = (const float*)d_in[15];
    const float* ff1_b          = (const float*)d_in[16];
    const float* ff2_w          = (const float*)d_in[17];
    const float* ff2_b          = (const float*)d_in[18];
    const float* ln1_g          = (const float*)d_in[19];
    const float* ln1_b          = (const float*)d_in[20];
    const float* ln2_g          = (const float*)d_in[21];
    const float* ln2_b          = (const float*)d_in[22];
    const float* head_w1        = (const float*)d_in[23];
    const float* head_b1        = (const float*)d_in[24];
    float* out = (float*)d_out;

    cudaFuncSetAttribute(mma_gemm_kernel<128>, cudaFuncAttributeMaxDynamicSharedMemorySize, MMASM128);
    cudaFuncSetAttribute(mma_gemm_kernel<64>,  cudaFuncAttributeMaxDynamicSharedMemorySize, MMASM64);
    cudaFuncSetAttribute(mma_gemm_dual_kernel, cudaFuncAttributeMaxDynamicSharedMemorySize, MMASM64);
    cudaFuncSetAttribute(attn_mma_kernel,      cudaFuncAttributeMaxDynamicSharedMemorySize, ATTSM);

    float* ws = nullptr;
    cudaGetSymbolAddress((void**)&ws, g_ws);
    __half* hf = nullptr;
    cudaGetSymbolAddress((void**)&hf, g_hf);

    float* patch_emb = ws + OFF_PATCH;
    float* tmp       = ws + OFF_TMP;
    float* q         = ws + OFF_Q;
    float* att       = ws + OFF_ATT;
    float* qproj     = ws + OFF_QP;
    float* pproj     = ws + OFF_PP;

    __half* qh  = hf + HF_QH;
    __half* l1h = hf + HF_L1H;
    __half* cxh = hf + HF_CXH;
    __half* fh  = hf + HF_FH;
    __half* qbh = hf + HF_QBH;
    __half* kvh = hf + HF_KVH;
    __half* pfh = hf + HF_PFH;
    __half* peh = hf + HF_PEH;
    __half* pch = hf + HF_PCH;

    // ---- one-time weight convert ----
    CTable ct;
    int total_blk;
    {
        int seg = 0, boff = 0;
        auto add = [&](const float* src, size_t ho, int count) {
            ct.seg[seg] = { src, hf + ho, boff };
            boff += count / 1024;
            seg++;
        };
        for (int l = 0; l < NL; l++)
            add(in_proj_w + (size_t)l * 3 * D * D, HF_WQ + (size_t)l * D * D, D * D);
        for (int l = 0; l < NL; l++)
            add(out_w + (size_t)l * D * D, HF_WO + (size_t)l * D * D, D * D);
        for (int l = 0; l < NL; l++)
            add(ff1_w + (size_t)l * 4 * D * D, HF_F1 + (size_t)l * 4 * D * D, 4 * D * D);
        for (int l = 0; l < NL; l++)
            add(ff2_w + (size_t)l * 4 * D * D, HF_F2 + (size_t)l * 4 * D * D, 4 * D * D);
        add(head_w1, HF_HD, HALF * D);
        add(patch_proj_w, HF_WP, D * FD);
        add(pe_proj_w, HF_WE, D * D);
        for (int l = 0; l < NL; l++)
            add(in_proj_w + (size_t)l * 3 * D * D + D * D, HF_WK + (size_t)l * 2 * D * D, 2 * D * D);
        total_blk = boff;
    }
    wconv_kernel<<<total_blk, 256>>>(ct);
    prep_kernel<<<4784, 256>>>(patch_features, patch_coords, row_embed, col_embed,
                               gene_queries, pfh, peh, q, qh);

    const int MT64  = (MQ + 63) / 64;     // 63
    const int MT128 = (MQ + 127) / 128;   // 32
    const int MTP   = (MP + 63) / 64;     // 7

    auto GA = [](const __half* Ah, const __half* Wh,
                 const float* bias, const float* R,
                 float* Cf, __half* Ch,
                 int M, int N, int K, int act) {
        GArgs g;
        g.Ah = Ah; g.Wh = Wh; g.bias = bias; g.R = R;
        g.Cf = Cf; g.Ch = Ch;
        g.M = M; g.N = N; g.K = K; g.act = act; g.ntx = N / 64;
        return g;
    };

    // ---- Stage A ----
    mma_gemm_kernel<64><<<dim3(D / 64, MTP), 256, MMASM64>>>(
        GA(pfh, hf + HF_WP, patch_proj_b, nullptr, tmp, nullptr, MP, D, FD, 0));
    ln_kernel<<<(MP + 7) / 8, 256>>>(tmp, nullptr, patch_ln_g, patch_ln_b, patch_emb,
                                     nullptr, MP);
    mma_gemm_kernel<64><<<dim3(D / 64, MTP), 256, MMASM64>>>(
        GA(peh, hf + HF_WE, pe_proj_b, patch_emb, nullptr, pch, MP, D, D, 0));

    // ---- Stage B ----
    for (int l = 0; l < NL; l++) {
        const float* bq  = in_proj_b + (size_t)l * 3 * D;
        const float* bkv = bq + D;
        GArgs gq = GA(qh, hf + HF_WQ + (size_t)l * D * D, bq, nullptr,
                      nullptr, qbh, MQ, D, D, 0);
        GArgs gk = GA(pch, hf + HF_WK + (size_t)l * 2 * D * D, bkv, nullptr,
                      nullptr, kvh, MP, 2 * D, D, 0);
        const int splitQ = gq.ntx * MT64;
        const int totQ   = splitQ + gk.ntx * MTP;
        mma_gemm_dual_kernel<<<totQ, 256, MMASM64>>>(gq, gk, splitQ);

        attn_mma_kernel<<<dim3(B * H, 32), 256, ATTSM>>>(qbh, kvh, cxh);

        mma_gemm_kernel<64><<<dim3(D / 64, MT64), 256, MMASM64>>>(
            GA(cxh, hf + HF_WO + (size_t)l * D * D, out_b + (size_t)l * D, q,
               att, nullptr, MQ, D, D, 0));
        ln_kernel<<<(MQ + 7) / 8, 256>>>(att, nullptr, ln1_g + (size_t)l * D, ln1_b + (size_t)l * D,
                                         q, l1h, MQ);
        mma_gemm_kernel<128><<<dim3(4 * D / 64, MT128), 256, MMASM128>>>(
            GA(l1h, hf + HF_F1 + (size_t)l * 4 * D * D, ff1_b + (size_t)l * 4 * D, nullptr,
               nullptr, fh, MQ, 4 * D, D, 1));
        mma_gemm_kernel<64><<<dim3(D / 64, MT64), 256, MMASM64>>>(
            GA(fh, hf + HF_F2 + (size_t)l * 4 * D * D, ff2_b + (size_t)l * D, q,
               att, nullptr, MQ, D, 4 * D, 0));
        ln_kernel<<<(MQ + 7) / 8, 256>>>(att, nullptr, ln2_g + (size_t)l * D, ln2_b + (size_t)l * D,
                                         q, qh, MQ);
    }

    // ---- Stage C ----
    {
        GArgs gqa = GA(qh, hf + HF_HD, head_b1, nullptr, qproj, nullptr, MQ, HALF, D, 0);
        GArgs gp  = GA(pch, hf + HF_HD, nullptr, nullptr, pproj, nullptr, MP, HALF, D, 0);
        const int splitH = gqa.ntx * MT64;
        const int totH   = splitH + gp.ntx * MTP;
        mma_gemm_dual_kernel<<<totH, 256, MMASM64>>>(gqa, gp, splitH);
    }
    head_kernel<<<dim3(G / 8, B * P), 256>>>(qproj, pproj, out);
}

// round 14
// speedup vs baseline: 1.9547x; 1.0783x over previous
#include <cuda_runtime.h>
#include <cuda_fp16.h>
#include <cstddef>
#include <cstdint>
#include <math.h>

// ---------------------------------------------------------------------------
// SpatialTranscriptomicsDecoder — GB300 sm_103a. Round 14.
// R13 (single-term fp16 mma everywhere + TC fused attention) +
// bp-tiled head epilogue (8x fewer qproj re-reads).
// ---------------------------------------------------------------------------

static constexpr int B = 2, P = 196, FD = 1024, G = 2000, D = 256, H = 8, NL = 4, HALF = 128;
static constexpr float ATT_SCALE = 0.17677669529663687f;
static constexpr int MQ = B * G;   // 4000
static constexpr int MP = B * P;   // 392

// ---------------- fp32 workspace ----------------
static constexpr size_t OFF_PATCH = 0;
static constexpr size_t OFF_TMP   = OFF_PATCH + (size_t)MP * D;
static constexpr size_t OFF_Q     = OFF_TMP   + (size_t)MP * D;
static constexpr size_t OFF_ATT   = OFF_Q     + (size_t)MQ * D;
static constexpr size_t OFF_QP    = OFF_ATT   + (size_t)MQ * D;
static constexpr size_t OFF_PP    = OFF_QP    + (size_t)MQ * HALF;
static constexpr size_t WS_TOTAL  = OFF_PP    + (size_t)MP * HALF;
__device__ float g_ws[WS_TOTAL];

// ---------------- fp16 workspace ----------------
static constexpr size_t BQ  = (size_t)MQ * D;
static constexpr size_t HF_QH  = 0;
static constexpr size_t HF_L1H = HF_QH + BQ;
static constexpr size_t HF_CXH = HF_L1H + BQ;
static constexpr size_t HF_FH  = HF_CXH + BQ;
static constexpr size_t HF_QBH = HF_FH + (size_t)MQ * 4 * D;
static constexpr size_t HF_KVH = HF_QBH + BQ;
static constexpr size_t HF_PFH = HF_KVH + (size_t)MP * 2 * D;
static constexpr size_t HF_PEH = HF_PFH + (size_t)MP * FD;
static constexpr size_t HF_PCH = HF_PEH + (size_t)MP * D;
static constexpr size_t HF_WQ  = HF_PCH + (size_t)MP * D;
static constexpr size_t HF_WO  = HF_WQ  + (size_t)NL * D * D;
static constexpr size_t HF_F1  = HF_WO  + (size_t)NL * D * D;
static constexpr size_t HF_F2  = HF_F1  + (size_t)NL * 4 * D * D;
static constexpr size_t HF_HD  = HF_F2  + (size_t)NL * 4 * D * D;
static constexpr size_t HF_WP  = HF_HD  + (size_t)HALF * D;
static constexpr size_t HF_WE  = HF_WP  + (size_t)D * FD;
static constexpr size_t HF_WK  = HF_WE  + (size_t)D * D;
static constexpr size_t HF_TOTAL = HF_WK + (size_t)NL * 2 * D * D;
__device__ __half g_hf[HF_TOTAL];

// ---------------- helpers ----------------
__device__ __forceinline__ float geluf(float x) {
    return 0.5f * x * (1.0f + erff(x * 0.7071067811865476f));
}
__device__ __forceinline__ float softplusf(float x) {
    return fmaxf(x, 0.0f) + __logf(1.0f + __expf(-fabsf(x)));
}
__device__ __forceinline__ void cpa16(unsigned int dst, const void* src, bool ok) {
    asm volatile("cp.async.ca.shared.global [%0], [%1], 16, %2;"
                 :: "r"(dst), "l"(src), "r"(ok ? 16 : 0) : "memory");
}
__device__ __forceinline__ void cpa_commit() {
    asm volatile("cp.async.commit_group;" ::: "memory");
}
template<int Ng> __device__ __forceinline__ void cpa_waitg() {
    asm volatile("cp.async.wait_group %0;" :: "n"(Ng) : "memory");
}
__device__ __forceinline__ void ldm4(unsigned& r0, unsigned& r1, unsigned& r2, unsigned& r3,
                                     unsigned addr) {
    asm volatile("ldmatrix.sync.aligned.m8n8.x4.shared.b16 {%0,%1,%2,%3}, [%4];"
                 : "=r"(r0), "=r"(r1), "=r"(r2), "=r"(r3) : "r"(addr));
}
__device__ __forceinline__ void ldm4t(unsigned& r0, unsigned& r1, unsigned& r2, unsigned& r3,
                                      unsigned addr) {
    asm volatile("ldmatrix.sync.aligned.m8n8.x4.trans.shared.b16 {%0,%1,%2,%3}, [%4];"
                 : "=r"(r0), "=r"(r1), "=r"(r2), "=r"(r3) : "r"(addr));
}
__device__ __forceinline__ void mma16816(float* d, const unsigned* a, unsigned b0, unsigned b1) {
    asm volatile(
        "mma.sync.aligned.m16n8k16.row.col.f32.f16.f16.f32 "
        "{%0,%1,%2,%3}, {%4,%5,%6,%7}, {%8,%9}, {%0,%1,%2,%3};"
        : "+f"(d[0]), "+f"(d[1]), "+f"(d[2]), "+f"(d[3])
        : "r"(a[0]), "r"(a[1]), "r"(a[2]), "r"(a[3]), "r"(b0), "r"(b1));
}

// ---------------------------------------------------------------------------
// GEMM: C[M,N] = act( A @ W^T + bias + R ); A,W fp16 (rounded), acc fp32.
// ---------------------------------------------------------------------------
struct GArgs {
    const __half* Ah; const __half* Wh;
    const float* bias; const float* R;
    float* Cf; __half* Ch;
    int M, N, K, act, ntx;
};

template<int BM>
__device__ __forceinline__ void mma_gemm_impl(const GArgs& g, int bx, int by)
{
    constexpr int STR = 24;
    constexpr int szA = BM * STR * 2;
    constexpr int szW = 64 * STR * 2;
    constexpr int STG = szA + szW;
    constexpr int MT  = 2;
    constexpr int WMASK  = (BM == 128) ? 3 : 1;
    constexpr int WSHIFT = (BM == 128) ? 2 : 1;
    constexpr int NT8 = (BM == 128) ? 4 : 2;
    constexpr int NP  = NT8 / 2;

    extern __shared__ char smem[];
    const unsigned sb = (unsigned)__cvta_generic_to_shared(smem);

    const int tid = threadIdx.x;
    const int lane = tid & 31, wid = tid >> 5;
    const int wm = wid & WMASK, wn = wid >> WSHIFT;
    const int bm = by * BM;
    const int bn = bx * 64;
    const int NC = g.K >> 4;
    const int M = g.M, N = g.N, K = g.K;

    unsigned off = 0;
    const __half* src = nullptr;
    bool okf = false;
    if (BM == 128) {
        if (tid < 128) {
            const int rowW = tid >> 1, segW = tid & 1;
            off = (unsigned)(szA + (rowW * STR + segW * 8) * 2);
            src = g.Wh + (size_t)(bn + rowW) * K + segW * 8;
            okf = true;
        }
    } else {
        if (tid >= 128) {
            const int rowW = (tid - 128) >> 1, segW = tid & 1;
            off = (unsigned)(szA + (rowW * STR + segW * 8) * 2);
            src = g.Wh + (size_t)(bn + rowW) * K + segW * 8;
            okf = true;
        }
    }
    unsigned offA = 0;
    const __half* srcA = nullptr;
    bool aok = false, doA = false;
    if (BM == 128) {
        const int rowA = tid >> 1, segA = tid & 1;
        doA = true;
        aok = (bm + rowA) < M;
        offA = (unsigned)((rowA * STR + segA * 8) * 2);
        srcA = g.Ah + (size_t)(bm + rowA) * K + segA * 8;
    } else if (tid < 128) {
        const int rowA = tid >> 1, segA = tid & 1;
        doA = true;
        aok = (bm + rowA) < M;
        offA = (unsigned)((rowA * STR + segA * 8) * 2);
        srcA = g.Ah + (size_t)(bm + rowA) * K + segA * 8;
    }

    auto loadChunk = [&](int kc, int s) {
        const int o = kc << 4;
        const unsigned base = sb + s * STG;
        if (doA) cpa16(base + offA, srcA + o, aok);
        if (src) cpa16(base + off, src + o, okf);
        cpa_commit();
    };

    unsigned aoffH[MT], boffH[NP];
    {
        const int ar = wm * 32 + (lane & 15);
        const int ak = (lane >> 4) * 8;
        const int br = wn * (NT8 * 8) + (lane & 7) + ((lane >> 4) << 3);
        const int bk = ((lane >> 3) & 1) * 8;
#pragma unroll
        for (int t = 0; t < MT; t++) aoffH[t] = (unsigned)(((ar + t * 16) * STR + ak) * 2);
#pragma unroll
        for (int p = 0; p < NP; p++) boffH[p] = (unsigned)(szA + ((br + p * 16) * STR + bk) * 2);
    }

    loadChunk(0, 0);
    loadChunk(1, 1);
    loadChunk(2, 2);

    float acc[MT][NT8][4];
#pragma unroll
    for (int i = 0; i < MT; i++)
#pragma unroll
        for (int j = 0; j < NT8; j++)
#pragma unroll
            for (int k = 0; k < 4; k++) acc[i][j][k] = 0.f;

    for (int kc = 0; kc < NC; kc++) {
        cpa_waitg<2>();
        __syncthreads();
        const int s = kc & 3;
        const int nk = kc + 3;
        if (nk < NC) loadChunk(nk, nk & 3);
        else cpa_commit();

        const unsigned stg = sb + s * STG;
        unsigned ah[MT][4], bh[NP][4];
#pragma unroll
        for (int t = 0; t < MT; t++)
            ldm4(ah[t][0], ah[t][1], ah[t][2], ah[t][3], stg + aoffH[t]);
#pragma unroll
        for (int p = 0; p < NP; p++)
            ldm4(bh[p][0], bh[p][1], bh[p][2], bh[p][3], stg + boffH[p]);
#pragma unroll
        for (int mt = 0; mt < MT; mt++) {
#pragma unroll
            for (int nt = 0; nt < NT8; nt++) {
                const int p = nt >> 1, nh = (nt & 1) << 1;
                mma16816(acc[mt][nt], ah[mt], bh[p][nh], bh[p][nh + 1]);
            }
        }
    }

    const int rowb = bm + wm * 32 + (lane >> 2);
    const int colb = bn + wn * (NT8 * 8) + 2 * (lane & 3);
#pragma unroll
    for (int mt = 0; mt < MT; mt++) {
#pragma unroll
        for (int nt = 0; nt < NT8; nt++) {
            const int col = colb + nt * 8;
            float2 b2 = make_float2(0.f, 0.f);
            if (g.bias) b2 = *(const float2*)(g.bias + col);
#pragma unroll
            for (int hh = 0; hh < 2; hh++) {
                const int row = rowb + mt * 16 + hh * 8;
                if (row >= M) continue;
                float v0 = acc[mt][nt][hh * 2 + 0] + b2.x;
                float v1 = acc[mt][nt][hh * 2 + 1] + b2.y;
                if (g.R) {
                    float2 r2 = *(const float2*)(g.R + (size_t)row * N + col);
                    v0 += r2.x; v1 += r2.y;
                }
                if (g.act == 1) { v0 = geluf(v0); v1 = geluf(v1); }
                if (g.Cf) *(float2*)(g.Cf + (size_t)row * N + col) = make_float2(v0, v1);
                if (g.Ch)
                    *(__half2*)(g.Ch + (size_t)row * N + col) =
                        __halves2half2(__float2half_rn(v0), __float2half_rn(v1));
            }
        }
    }
}

template<int BM>
__global__ void __launch_bounds__(256) mma_gemm_kernel(GArgs g)
{
    mma_gemm_impl<BM>(g, blockIdx.x, blockIdx.y);
}

__global__ void __launch_bounds__(256) mma_gemm_dual_kernel(GArgs g0, GArgs g1, int split)
{
    if ((int)blockIdx.x < split) {
        const int local = blockIdx.x;
        mma_gemm_impl<64>(g0, local % g0.ntx, local / g0.ntx);
    } else {
        const int local = blockIdx.x - split;
        mma_gemm_impl<64>(g1, local % g1.ntx, local / g1.ntx);
    }
}

static constexpr int MMASM128 = 4 * (128 * 24 * 2 + 64 * 24 * 2);  // 36864
static constexpr int MMASM64  = 4 * (64 * 24 * 2 + 64 * 24 * 2);   // 24576

// ---------------------------------------------------------------------------
// Fused tensor-core attention (single-term). grid (B*H, 32), 256 thr (4m x 2n).
// ---------------------------------------------------------------------------
static constexpr int A_QH0 = 0;
static constexpr int A_KH0 = 2560;
static constexpr int A_VH0 = A_KH0 + 8960;      // 11520
static constexpr int A_PS0 = A_VH0 + 8960;      // 20480
static constexpr int A_PARTB = (A_PS0 + 13824) * 2;   // 68608 bytes
static constexpr int ATTSM = A_PARTB + 2048;

__global__ void __launch_bounds__(256) attn_mma_kernel(
    const __half* __restrict__ Qh_g, const __half* __restrict__ KVh,
    __half* __restrict__ cxh)
{
    extern __shared__ char smem[];
    __half* sm = (__half*)smem;
    float* pm   = (float*)(smem + A_PARTB);
    float* psum = pm + 128;
    const unsigned sb = (unsigned)__cvta_generic_to_shared(smem);

    const int bh = blockIdx.x;
    const int b = bh >> 3, h = bh & 7;
    const int g0 = blockIdx.y * 64;
    const int tid = threadIdx.x;
    const int lane = tid & 31, wid = tid >> 5;
    const int wm = wid & 3, wn = wid >> 2;

    if (tid < 128) {
        const int row = tid >> 1;
        const int sp = (tid & 1) * 16;
        const bool ok = (g0 + row) < G;
        const __half* src = Qh_g + ((size_t)(b * G + g0 + row) * 256 + h * 32 + sp);
        unsigned dst = sb + (A_QH0 + row * 40 + sp) * 2;
        cpa16(dst, src, ok);
        cpa16(dst + 16, src + 8, ok);
    }
    if (tid < 196) {
        const size_t rb = (size_t)(b * P + tid) * 512 + h * 32;
        const __half* ksrc = KVh + rb;
        unsigned kdst = sb + (A_KH0 + tid * 40) * 2;
        cpa16(kdst,      ksrc,      true);
        cpa16(kdst + 16, ksrc + 8,  true);
        cpa16(kdst + 32, ksrc + 16, true);
        cpa16(kdst + 48, ksrc + 24, true);
        const __half* vh = KVh + rb + 256;
        unsigned vhd = sb + (A_VH0 + tid * 40) * 2;
        cpa16(vhd,      vh,      true);
        cpa16(vhd + 16, vh + 8,  true);
        cpa16(vhd + 32, vh + 16, true);
        cpa16(vhd + 48, vh + 24, true);
    } else if (tid < 224) {
        uint4 z = make_uint4(0, 0, 0, 0);
#pragma unroll
        for (int i = 0; i < 5; i++) {
            *(uint4*)(sm + A_KH0 + tid * 40 + i * 8) = z;
            *(uint4*)(sm + A_VH0 + tid * 40 + i * 8) = z;
        }
    }
    cpa_commit();
    cpa_waitg<0>();
    __syncthreads();

    unsigned aq[2][4];
    {
        const int ar = wm * 16 + (lane & 15);
        const int ak = (lane >> 4) * 8;
#pragma unroll
        for (int ks = 0; ks < 2; ks++)
            ldm4(aq[ks][0], aq[ks][1], aq[ks][2], aq[ks][3],
                 sb + (A_QH0 + ar * 40 + ks * 16 + ak) * 2);
    }
    float sacc[13][4];
#pragma unroll
    for (int i = 0; i < 13; i++)
#pragma unroll
        for (int j = 0; j < 4; j++) sacc[i][j] = 0.f;

    {
        const int brr = wn * 104 + (lane & 7) + ((lane >> 4) << 3);
        const int bko = ((lane >> 3) & 1) * 8;
#pragma unroll
        for (int gph = 0; gph < 7; gph++) {
            unsigned bk0[4], bk1[4];
            ldm4(bk0[0], bk0[1], bk0[2], bk0[3],
                 sb + (A_KH0 + (brr + gph * 16) * 40 + bko) * 2);
            ldm4(bk1[0], bk1[1], bk1[2], bk1[3],
                 sb + (A_KH0 + (brr + gph * 16) * 40 + 16 + bko) * 2);
#pragma unroll
            for (int hf = 0; hf < 2; hf++) {
                const int nt = gph * 2 + hf;
                if (nt >= 13) break;
                mma16816(sacc[nt], aq[0], bk0[hf * 2], bk0[hf * 2 + 1]);
                mma16816(sacc[nt], aq[1], bk1[hf * 2], bk1[hf * 2 + 1]);
            }
        }
    }

#pragma unroll
    for (int nt = 0; nt < 13; nt++)
#pragma unroll
        for (int j = 0; j < 4; j++) sacc[nt][j] *= ATT_SCALE;

    float mx0 = -1e30f, mx1 = -1e30f;
#pragma unroll
    for (int nt = 0; nt < 13; nt++) {
        mx0 = fmaxf(mx0, fmaxf(sacc[nt][0], sacc[nt][1]));
        mx1 = fmaxf(mx1, fmaxf(sacc[nt][2], sacc[nt][3]));
    }
    mx0 = fmaxf(mx0, __shfl_xor_sync(0xffffffffu, mx0, 1));
    mx0 = fmaxf(mx0, __shfl_xor_sync(0xffffffffu, mx0, 2));
    mx1 = fmaxf(mx1, __shfl_xor_sync(0xffffffffu, mx1, 1));
    mx1 = fmaxf(mx1, __shfl_xor_sync(0xffffffffu, mx1, 2));

    float s0 = 0.f, s1 = 0.f;
#pragma unroll
    for (int nt = 0; nt < 13; nt++) {
        const int col = wn * 104 + nt * 8 + 2 * (lane & 3);
        float e0 = (col < 196)     ? __expf(sacc[nt][0] - mx0) : 0.f;
        float e1 = (col + 1 < 196) ? __expf(sacc[nt][1] - mx0) : 0.f;
        float e2 = (col < 196)     ? __expf(sacc[nt][2] - mx1) : 0.f;
        float e3 = (col + 1 < 196) ? __expf(sacc[nt][3] - mx1) : 0.f;
        sacc[nt][0] = e0; sacc[nt][1] = e1; sacc[nt][2] = e2; sacc[nt][3] = e3;
        s0 += e0 + e1; s1 += e2 + e3;
    }
    s0 += __shfl_xor_sync(0xffffffffu, s0, 1);
    s0 += __shfl_xor_sync(0xffffffffu, s0, 2);
    s1 += __shfl_xor_sync(0xffffffffu, s1, 1);
    s1 += __shfl_xor_sync(0xffffffffu, s1, 2);

    const int r0 = wm * 16 + (lane >> 2), r1 = r0 + 8;
    if ((lane & 3) == 0) {
        pm[wn * 64 + r0] = mx0;  pm[wn * 64 + r1] = mx1;
        psum[wn * 64 + r0] = s0; psum[wn * 64 + r1] = s1;
    }
    __syncthreads();

    float f0, f1;
    {
        float ma = pm[r0], mb = pm[64 + r0];
        float mg = fmaxf(ma, mb);
        float sg = psum[r0] * __expf(ma - mg) + psum[64 + r0] * __expf(mb - mg);
        f0 = __expf((wn ? mb : ma) - mg) / sg;
        ma = pm[r1]; mb = pm[64 + r1];
        mg = fmaxf(ma, mb);
        sg = psum[r1] * __expf(ma - mg) + psum[64 + r1] * __expf(mb - mg);
        f1 = __expf((wn ? mb : ma) - mg) / sg;
    }
#pragma unroll
    for (int nt = 0; nt < 13; nt++) {
        const int col = wn * 104 + nt * 8 + 2 * (lane & 3);
        *(__half2*)(sm + A_PS0 + r0 * 216 + col) =
            __halves2half2(__float2half_rn(sacc[nt][0] * f0), __float2half_rn(sacc[nt][1] * f0));
        *(__half2*)(sm + A_PS0 + r1 * 216 + col) =
            __halves2half2(__float2half_rn(sacc[nt][2] * f1), __float2half_rn(sacc[nt][3] * f1));
    }
    __syncthreads();

    float vacc[2][4];
#pragma unroll
    for (int i = 0; i < 2; i++)
#pragma unroll
        for (int j = 0; j < 4; j++) vacc[i][j] = 0.f;
    {
        const int ar = wm * 16 + (lane & 15);
        const int ak = (lane >> 4) * 8;
        const int vr = (lane & 15);
        const int vc = wn * 16 + (lane >> 4) * 8;
#pragma unroll
        for (int ks = 0; ks < 13; ks++) {
            unsigned ap[4], bvh[4];
            ldm4(ap[0], ap[1], ap[2], ap[3],
                 sb + (A_PS0 + ar * 216 + ks * 16 + ak) * 2);
            ldm4t(bvh[0], bvh[1], bvh[2], bvh[3],
                  sb + (A_VH0 + (ks * 16 + vr) * 40 + vc) * 2);
            mma16816(vacc[0], ap, bvh[0], bvh[1]);
            mma16816(vacc[1], ap, bvh[2], bvh[3]);
        }
    }

    {
        const int gr = g0 + wm * 16 + (lane >> 2);
        const int dc = wn * 16 + 2 * (lane & 3);
#pragma unroll
        for (int nt = 0; nt < 2; nt++) {
            const int d = dc + nt * 8;
#pragma unroll
            for (int hh = 0; hh < 2; hh++) {
                const int gene = gr + hh * 8;
                if (gene >= G) continue;
                const size_t off = (size_t)(b * G + gene) * 256 + h * 32 + d;
                *(__half2*)(cxh + off) =
                    __halves2half2(__float2half_rn(vacc[nt][hh * 2 + 0]),
                                   __float2half_rn(vacc[nt][hh * 2 + 1]));
            }
        }
    }
}

// ---------------------------------------------------------------------------
// weight convert: fp32 -> fp16, 23 segments
// ---------------------------------------------------------------------------
struct CSeg { const float* src; __half* h; int blk_off; };
struct CTable { CSeg seg[23]; };
__global__ void __launch_bounds__(256) wconv_kernel(CTable t)
{
    const int bt = blockIdx.x;
    int s = 0;
#pragma unroll
    for (int i = 1; i < 23; i++) if (t.seg[i].blk_off <= bt) s = i;
    const CSeg sg = t.seg[s];
    const int idx = (bt - sg.blk_off) * 1024 + threadIdx.x * 4;
    float4 v = *(const float4*)(sg.src + idx);
    *(__half2*)(sg.h + idx)     = __halves2half2(__float2half_rn(v.x), __float2half_rn(v.y));
    *(__half2*)(sg.h + idx + 2) = __halves2half2(__float2half_rn(v.z), __float2half_rn(v.w));
}

// merged prep
__global__ void __launch_bounds__(256) prep_kernel(
    const float* __restrict__ pf, const int* __restrict__ coords,
    const float* __restrict__ re, const float* __restrict__ ce,
    const float* __restrict__ gq,
    __half* __restrict__ pfh, __half* __restrict__ peh,
    float* __restrict__ q, __half* __restrict__ qh)
{
    const int bid = blockIdx.x;
    if (bid < 392) {
        int idx = (bid * 256 + threadIdx.x) * 4;
        float4 v = *(const float4*)(pf + idx);
        *(__half2*)(pfh + idx)     = __halves2half2(__float2half_rn(v.x), __float2half_rn(v.y));
        *(__half2*)(pfh + idx + 2) = __halves2half2(__float2half_rn(v.z), __float2half_rn(v.w));
    } else if (bid < 784) {
        int idx = (bid - 392) * 256 + threadIdx.x;
        if (idx < B * P * D) {
            int d = idx & 255;
            int bp = idx >> 8;
            int r = coords[bp * 2 + 0];
            int c = coords[bp * 2 + 1];
            r = min(max(r, 0), 255);
            c = min(max(c, 0), 255);
            float v = (d < 128) ? re[r * 128 + d] : ce[c * 128 + (d - 128)];
            peh[idx] = __float2half_rn(v);
        }
    } else {
        int idx = (bid - 784) * 256 + threadIdx.x;
        float v = gq[idx % (G * D)];
        q[idx] = v;
        qh[idx] = __float2half_rn(v);
    }
}

// ---------------------------------------------------------------------------
// LN (+optional fp16 emit)
// ---------------------------------------------------------------------------
__global__ void ln_kernel(const float* __restrict__ x, const float* __restrict__ r,
                          const float* __restrict__ gg, const float* __restrict__ bb,
                          float* __restrict__ y, __half* __restrict__ yh,
                          int rows)
{
    int gid = blockIdx.x * blockDim.x + threadIdx.x;
    int row = gid >> 5;
    int lane = gid & 31;
    if (row >= rows) return;
    const float* xp = x + (size_t)row * 256;
    float4 a = *(const float4*)(xp + lane * 4);
    float4 c = *(const float4*)(xp + 128 + lane * 4);
    if (r) {
        const float* rp = r + (size_t)row * 256;
        float4 ra = *(const float4*)(rp + lane * 4);
        float4 rc = *(const float4*)(rp + 128 + lane * 4);
        a.x += ra.x; a.y += ra.y; a.z += ra.z; a.w += ra.w;
        c.x += rc.x; c.y += rc.y; c.z += rc.z; c.w += rc.w;
    }
    float s = a.x + a.y + a.z + a.w + c.x + c.y + c.z + c.w;
    float q = a.x * a.x + a.y * a.y + a.z * a.z + a.w * a.w
            + c.x * c.x + c.y * c.y + c.z * c.z + c.w * c.w;
#pragma unroll
    for (int o = 16; o; o >>= 1) {
        s += __shfl_xor_sync(0xffffffffu, s, o);
        q += __shfl_xor_sync(0xffffffffu, q, o);
    }
    float mean = s * (1.f / 256.f);
    float var = q * (1.f / 256.f) - mean * mean;
    float rstd = rsqrtf(var + 1e-5f);
    float4 g0 = *(const float4*)(gg + lane * 4);
    float4 g1 = *(const float4*)(gg + 128 + lane * 4);
    float4 b0 = *(const float4*)(bb + lane * 4);
    float4 b1 = *(const float4*)(bb + 128 + lane * 4);
    float4 o0, o1;
    o0.x = (a.x - mean) * rstd * g0.x + b0.x;
    o0.y = (a.y - mean) * rstd * g0.y + b0.y;
    o0.z = (a.z - mean) * rstd * g0.z + b0.z;
    o0.w = (a.w - mean) * rstd * g0.w + b0.w;
    o1.x = (c.x - mean) * rstd * g1.x + b1.x;
    o1.y = (c.y - mean) * rstd * g1.y + b1.y;
    o1.z = (c.z - mean) * rstd * g1.z + b1.z;
    o1.w = (c.w - mean) * rstd * g1.w + b1.w;
    float* yp = y + (size_t)row * 256;
    *(float4*)(yp + lane * 4) = o0;
    *(float4*)(yp + 128 + lane * 4) = o1;
    if (yh) {
        const size_t b0o = (size_t)row * 256 + lane * 4;
        *(__half2*)(yh + b0o)       = __halves2half2(__float2half_rn(o0.x), __float2half_rn(o0.y));
        *(__half2*)(yh + b0o + 2)   = __halves2half2(__float2half_rn(o0.z), __float2half_rn(o0.w));
        *(__half2*)(yh + b0o + 128) = __halves2half2(__float2half_rn(o1.x), __float2half_rn(o1.y));
        *(__half2*)(yh + b0o + 130) = __halves2half2(__float2half_rn(o1.z), __float2half_rn(o1.w));
    }
}

// ---------------------------------------------------------------------------
// head: bp-tiled. grid (G/8, MP/8), block 256. Each warp: 1 gene, 8 bp rows.
// qv loaded once per gene (reload on batch flip); pv broadcast-cached.
// ---------------------------------------------------------------------------
__global__ void __launch_bounds__(256) head_kernel(
    const float* __restrict__ qp, const float* __restrict__ pp, float* __restrict__ out)
{
    const int g = blockIdx.x * 8 + (threadIdx.x >> 5);
    const int col = (threadIdx.x & 31) << 2;
    const int bp0 = blockIdx.y * 8;
    float4 qv;
    int curb = -1;
#pragma unroll
    for (int i = 0; i < 8; i++) {
        const int bp = bp0 + i;
        const int b = (bp >= P) ? 1 : 0;
        if (b != curb) {
            qv = *(const float4*)(qp + (size_t)(b * G + g) * HALF + col);
            curb = b;
        }
        float4 pv = *(const float4*)(pp + (size_t)bp * HALF + col);
        float4 o;
        o.x = softplusf(pv.x + qv.x);
        o.y = softplusf(pv.y + qv.y);
        o.z = softplusf(pv.z + qv.z);
        o.w = softplusf(pv.w + qv.w);
        *(float4*)(out + ((size_t)bp * G + g) * HALF + col) = o;
    }
}

// ---------------------------------------------------------------------------
extern "C" void kernel_launch(void* const* d_in, const int* in_sizes, int n_in,
                              void* d_out, int out_size)
{
    (void)in_sizes; (void)n_in; (void)out_size;
    const float* patch_features = (const float*)d_in[0];
    const int*   patch_coords   = (const int*)d_in[1];
    const float* patch_proj_w   = (const float*)d_in[2];
    const float* patch_proj_b   = (const float*)d_in[3];
    const float* patch_ln_g     = (const float*)d_in[4];
    const float* patch_ln_b     = (const float*)d_in[5];
    const float* row_embed      = (const float*)d_in[6];
    const float* col_embed      = (const float*)d_in[7];
    const float* pe_proj_w      = (const float*)d_in[8];
    const float* pe_proj_b      = (const float*)d_in[9];
    const float* gene_queries   = (const float*)d_in[10];
    const float* in_proj_w      = (const float*)d_in[11];
    const float* in_proj_b      = (const float*)d_in[12];
    const float* out_w          = (const float*)d_in[13];
    const float* out_b          = (const float*)d_in[14];
    const float* ff1_w          = (const float*)d_in[15];
    const float* ff1_b          = (const float*)d_in[16];
    const float* ff2_w          = (const float*)d_in[17];
    const float* ff2_b          = (const float*)d_in[18];
    const float* ln1_g          = (const float*)d_in[19];
    const float* ln1_b          = (const float*)d_in[20];
    const float* ln2_g          = (const float*)d_in[21];
    const float* ln2_b          = (const float*)d_in[22];
    const float* head_w1        = (const float*)d_in[23];
    const float* head_b1        = (const float*)d_in[24];
    float* out = (float*)d_out;

    cudaFuncSetAttribute(mma_gemm_kernel<128>, cudaFuncAttributeMaxDynamicSharedMemorySize, MMASM128);
    cudaFuncSetAttribute(mma_gemm_kernel<64>,  cudaFuncAttributeMaxDynamicSharedMemorySize, MMASM64);
    cudaFuncSetAttribute(mma_gemm_dual_kernel, cudaFuncAttributeMaxDynamicSharedMemorySize, MMASM64);
    cudaFuncSetAttribute(attn_mma_kernel,      cudaFuncAttributeMaxDynamicSharedMemorySize, ATTSM);

    float* ws = nullptr;
    cudaGetSymbolAddress((void**)&ws, g_ws);
    __half* hf = nullptr;
    cudaGetSymbolAddress((void**)&hf, g_hf);

    float* patch_emb = ws + OFF_PATCH;
    float* tmp       = ws + OFF_TMP;
    float* q         = ws + OFF_Q;
    float* att       = ws + OFF_ATT;
    float* qproj     = ws + OFF_QP;
    float* pproj     = ws + OFF_PP;

    __half* qh  = hf + HF_QH;
    __half* l1h = hf + HF_L1H;
    __half* cxh = hf + HF_CXH;
    __half* fh  = hf + HF_FH;
    __half* qbh = hf + HF_QBH;
    __half* kvh = hf + HF_KVH;
    __half* pfh = hf + HF_PFH;
    __half* peh = hf + HF_PEH;
    __half* pch = hf + HF_PCH;

    // ---- one-time weight convert ----
    CTable ct;
    int total_blk;
    {
        int seg = 0, boff = 0;
        auto add = [&](const float* src, size_t ho, int count) {
            ct.seg[seg] = { src, hf + ho, boff };
            boff += count / 1024;
            seg++;
        };
        for (int l = 0; l < NL; l++)
            add(in_proj_w + (size_t)l * 3 * D * D, HF_WQ + (size_t)l * D * D, D * D);
        for (int l = 0; l < NL; l++)
            add(out_w + (size_t)l * D * D, HF_WO + (size_t)l * D * D, D * D);
        for (int l = 0; l < NL; l++)
            add(ff1_w + (size_t)l * 4 * D * D, HF_F1 + (size_t)l * 4 * D * D, 4 * D * D);
        for (int l = 0; l < NL; l++)
            add(ff2_w + (size_t)l * 4 * D * D, HF_F2 + (size_t)l * 4 * D * D, 4 * D * D);
        add(head_w1, HF_HD, HALF * D);
        add(patch_proj_w, HF_WP, D * FD);
        add(pe_proj_w, HF_WE, D * D);
        for (int l = 0; l < NL; l++)
            add(in_proj_w + (size_t)l * 3 * D * D + D * D, HF_WK + (size_t)l * 2 * D * D, 2 * D * D);
        total_blk = boff;
    }
    wconv_kernel<<<total_blk, 256>>>(ct);
    prep_kernel<<<4784, 256>>>(patch_features, patch_coords, row_embed, col_embed,
                               gene_queries, pfh, peh, q, qh);

    const int MT64  = (MQ + 63) / 64;     // 63
    const int MT128 = (MQ + 127) / 128;   // 32
    const int MTP   = (MP + 63) / 64;     // 7

    auto GA = [](const __half* Ah, const __half* Wh,
                 const float* bias, const float* R,
                 float* Cf, __half* Ch,
                 int M, int N, int K, int act) {
        GArgs g;
        g.Ah = Ah; g.Wh = Wh; g.bias = bias; g.R = R;
        g.Cf = Cf; g.Ch = Ch;
        g.M = M; g.N = N; g.K = K; g.act = act; g.ntx = N / 64;
        return g;
    };

    // ---- Stage A ----
    mma_gemm_kernel<64><<<dim3(D / 64, MTP), 256, MMASM64>>>(
        GA(pfh, hf + HF_WP, patch_proj_b, nullptr, tmp, nullptr, MP, D, FD, 0));
    ln_kernel<<<(MP + 7) / 8, 256>>>(tmp, nullptr, patch_ln_g, patch_ln_b, patch_emb,
                                     nullptr, MP);
    mma_gemm_kernel<64><<<dim3(D / 64, MTP), 256, MMASM64>>>(
        GA(peh, hf + HF_WE, pe_proj_b, patch_emb, nullptr, pch, MP, D, D, 0));

    // ---- Stage B ----
    for (int l = 0; l < NL; l++) {
        const float* bq  = in_proj_b + (size_t)l * 3 * D;
        const float* bkv = bq + D;
        GArgs gq = GA(qh, hf + HF_WQ + (size_t)l * D * D, bq, nullptr,
                      nullptr, qbh, MQ, D, D, 0);
        GArgs gk = GA(pch, hf + HF_WK + (size_t)l * 2 * D * D, bkv, nullptr,
                      nullptr, kvh, MP, 2 * D, D, 0);
        const int splitQ = gq.ntx * MT64;
        const int totQ   = splitQ + gk.ntx * MTP;
        mma_gemm_dual_kernel<<<totQ, 256, MMASM64>>>(gq, gk, splitQ);

        attn_mma_kernel<<<dim3(B * H, 32), 256, ATTSM>>>(qbh, kvh, cxh);

        mma_gemm_kernel<64><<<dim3(D / 64, MT64), 256, MMASM64>>>(
            GA(cxh, hf + HF_WO + (size_t)l * D * D, out_b + (size_t)l * D, q,
               att, nullptr, MQ, D, D, 0));
        ln_kernel<<<(MQ + 7) / 8, 256>>>(att, nullptr, ln1_g + (size_t)l * D, ln1_b + (size_t)l * D,
                                         q, l1h, MQ);
        mma_gemm_kernel<128><<<dim3(4 * D / 64, MT128), 256, MMASM128>>>(
            GA(l1h, hf + HF_F1 + (size_t)l * 4 * D * D, ff1_b + (size_t)l * 4 * D, nullptr,
               nullptr, fh, MQ, 4 * D, D, 1));
        mma_gemm_kernel<64><<<dim3(D / 64, MT64), 256, MMASM64>>>(
            GA(fh, hf + HF_F2 + (size_t)l * 4 * D * D, ff2_b + (size_t)l * D, q,
               att, nullptr, MQ, D, 4 * D, 0));
        ln_kernel<<<(MQ + 7) / 8, 256>>>(att, nullptr, ln2_g + (size_t)l * D, ln2_b + (size_t)l * D,
                                         q, qh, MQ);
    }

    // ---- Stage C ----
    {
        GArgs gqa = GA(qh, hf + HF_HD, head_b1, nullptr, qproj, nullptr, MQ, HALF, D, 0);
        GArgs gp  = GA(pch, hf + HF_HD, nullptr, nullptr, pproj, nullptr, MP, HALF, D, 0);
        const int splitH = gqa.ntx * MT64;
        const int totH   = splitH + gp.ntx * MTP;
        mma_gemm_dual_kernel<<<totH, 256, MMASM64>>>(gqa, gp, splitH);
    }
    head_kernel<<<dim3(G / 8, MP / 8), 256>>>(qproj, pproj, out);
}

// round 15
// speedup vs baseline: 2.0331x; 1.0401x over previous
#include <cuda_runtime.h>
#include <cuda_fp16.h>
#include <cstddef>
#include <cstdint>
#include <math.h>

// ---------------------------------------------------------------------------
// SpatialTranscriptomicsDecoder — GB300 sm_103a. Round 15.
// R14 + k-chunk 32 pipeline stages (half the barriers) + all-layer KV
// projection hoisted out of the layer loop (one 392x2048x256 GEMM).
// ---------------------------------------------------------------------------

static constexpr int B = 2, P = 196, FD = 1024, G = 2000, D = 256, H = 8, NL = 4, HALF = 128;
static constexpr float ATT_SCALE = 0.17677669529663687f;
static constexpr int MQ = B * G;   // 4000
static constexpr int MP = B * P;   // 392

// ---------------- fp32 workspace ----------------
static constexpr size_t OFF_PATCH = 0;
static constexpr size_t OFF_TMP   = OFF_PATCH + (size_t)MP * D;
static constexpr size_t OFF_Q     = OFF_TMP   + (size_t)MP * D;
static constexpr size_t OFF_ATT   = OFF_Q     + (size_t)MQ * D;
static constexpr size_t OFF_QP    = OFF_ATT   + (size_t)MQ * D;
static constexpr size_t OFF_PP    = OFF_QP    + (size_t)MQ * HALF;
static constexpr size_t OFF_KVB   = OFF_PP    + (size_t)MP * HALF;   // concat kv bias [2048]
static constexpr size_t WS_TOTAL  = OFF_KVB   + (size_t)NL * 2 * D;
__device__ float g_ws[WS_TOTAL];

// ---------------- fp16 workspace ----------------
static constexpr size_t BQ  = (size_t)MQ * D;
static constexpr size_t HF_QH  = 0;
static constexpr size_t HF_L1H = HF_QH + BQ;
static constexpr size_t HF_CXH = HF_L1H + BQ;
static constexpr size_t HF_FH  = HF_CXH + BQ;
static constexpr size_t HF_QBH = HF_FH + (size_t)MQ * 4 * D;
static constexpr size_t HF_KVA = HF_QBH + BQ;                      // [MP, NL*2*D]
static constexpr size_t HF_PFH = HF_KVA + (size_t)MP * NL * 2 * D;
static constexpr size_t HF_PEH = HF_PFH + (size_t)MP * FD;
static constexpr size_t HF_PCH = HF_PEH + (size_t)MP * D;
static constexpr size_t HF_WQ  = HF_PCH + (size_t)MP * D;
static constexpr size_t HF_WO  = HF_WQ  + (size_t)NL * D * D;
static constexpr size_t HF_F1  = HF_WO  + (size_t)NL * D * D;
static constexpr size_t HF_F2  = HF_F1  + (size_t)NL * 4 * D * D;
static constexpr size_t HF_HD  = HF_F2  + (size_t)NL * 4 * D * D;
static constexpr size_t HF_WP  = HF_HD  + (size_t)HALF * D;
static constexpr size_t HF_WE  = HF_WP  + (size_t)D * FD;
static constexpr size_t HF_WK  = HF_WE  + (size_t)D * D;           // [NL*2*D, D] contiguous
static constexpr size_t HF_TOTAL = HF_WK + (size_t)NL * 2 * D * D;
__device__ __half g_hf[HF_TOTAL];

// ---------------- helpers ----------------
__device__ __forceinline__ float geluf(float x) {
    return 0.5f * x * (1.0f + erff(x * 0.7071067811865476f));
}
__device__ __forceinline__ float softplusf(float x) {
    return fmaxf(x, 0.0f) + __logf(1.0f + __expf(-fabsf(x)));
}
__device__ __forceinline__ void cpa16(unsigned int dst, const void* src, bool ok) {
    asm volatile("cp.async.ca.shared.global [%0], [%1], 16, %2;"
                 :: "r"(dst), "l"(src), "r"(ok ? 16 : 0) : "memory");
}
__device__ __forceinline__ void cpa_commit() {
    asm volatile("cp.async.commit_group;" ::: "memory");
}
template<int Ng> __device__ __forceinline__ void cpa_waitg() {
    asm volatile("cp.async.wait_group %0;" :: "n"(Ng) : "memory");
}
__device__ __forceinline__ void ldm4(unsigned& r0, unsigned& r1, unsigned& r2, unsigned& r3,
                                     unsigned addr) {
    asm volatile("ldmatrix.sync.aligned.m8n8.x4.shared.b16 {%0,%1,%2,%3}, [%4];"
                 : "=r"(r0), "=r"(r1), "=r"(r2), "=r"(r3) : "r"(addr));
}
__device__ __forceinline__ void ldm4t(unsigned& r0, unsigned& r1, unsigned& r2, unsigned& r3,
                                      unsigned addr) {
    asm volatile("ldmatrix.sync.aligned.m8n8.x4.trans.shared.b16 {%0,%1,%2,%3}, [%4];"
                 : "=r"(r0), "=r"(r1), "=r"(r2), "=r"(r3) : "r"(addr));
}
__device__ __forceinline__ void mma16816(float* d, const unsigned* a, unsigned b0, unsigned b1) {
    asm volatile(
        "mma.sync.aligned.m16n8k16.row.col.f32.f16.f16.f32 "
        "{%0,%1,%2,%3}, {%4,%5,%6,%7}, {%8,%9}, {%0,%1,%2,%3};"
        : "+f"(d[0]), "+f"(d[1]), "+f"(d[2]), "+f"(d[3])
        : "r"(a[0]), "r"(a[1]), "r"(a[2]), "r"(a[3]), "r"(b0), "r"(b1));
}

// ---------------------------------------------------------------------------
// GEMM: C[M,N] = act( A @ W^T + bias + R ); fp16 in, fp32 acc.
// k-chunk 32 per pipeline stage (4 stages), row stride 40 halfs.
// ---------------------------------------------------------------------------
struct GArgs {
    const __half* Ah; const __half* Wh;
    const float* bias; const float* R;
    float* Cf; __half* Ch;
    int M, N, K, act, ntx;
};

template<int BM>
__device__ __forceinline__ void mma_gemm_impl(const GArgs& g, int bx, int by)
{
    constexpr int STR = 40;                   // halfs per row (32 + 8 pad)
    constexpr int szA = BM * STR * 2;
    constexpr int szW = 64 * STR * 2;
    constexpr int STG = szA + szW;
    constexpr int MT  = 2;
    constexpr int WMASK  = (BM == 128) ? 3 : 1;
    constexpr int WSHIFT = (BM == 128) ? 2 : 1;
    constexpr int NT8 = (BM == 128) ? 4 : 2;
    constexpr int NP  = NT8 / 2;

    extern __shared__ char smem[];
    const unsigned sb = (unsigned)__cvta_generic_to_shared(smem);

    const int tid = threadIdx.x;
    const int lane = tid & 31, wid = tid >> 5;
    const int wm = wid & WMASK, wn = wid >> WSHIFT;
    const int bm = by * BM;
    const int bn = bx * 64;
    const int NC = g.K >> 5;                  // 32-wide chunks
    const int M = g.M, N = g.N, K = g.K;

    // ---- loaders ----
    // A rows: 2 threads/row, each 2x16B (seg pair). W(BM=64): same on tid>=128.
    // W(BM=128): 1 thread per (row, 16B seg): rowW=tid>>2, segW=tid&3.
    unsigned offA = 0, offW = 0;
    const __half* srcA = nullptr;
    const __half* srcW = nullptr;
    bool aok = false, doA = false, doW = false;
    if (BM == 128) {
        const int rowA = tid >> 1, segA = tid & 1;
        doA = true;
        aok = (bm + rowA) < M;
        offA = (unsigned)((rowA * STR + segA * 16) * 2);
        srcA = g.Ah + (size_t)(bm + rowA) * K + segA * 16;
        const int rowW = tid >> 2, segW = tid & 3;
        doW = true;
        offW = (unsigned)(szA + (rowW * STR + segW * 8) * 2);
        srcW = g.Wh + (size_t)(bn + rowW) * K + segW * 8;
    } else {
        if (tid < 128) {
            const int rowA = tid >> 1, segA = tid & 1;
            doA = true;
            aok = (bm + rowA) < M;
            offA = (unsigned)((rowA * STR + segA * 16) * 2);
            srcA = g.Ah + (size_t)(bm + rowA) * K + segA * 16;
        } else {
            const int rowW = (tid - 128) >> 1, segW = tid & 1;
            doW = true;
            offW = (unsigned)(szA + (rowW * STR + segW * 16) * 2);
            srcW = g.Wh + (size_t)(bn + rowW) * K + segW * 16;
        }
    }

    auto loadChunk = [&](int kc, int s) {
        const int o = kc << 5;
        const unsigned base = sb + s * STG;
        if (doA) {
            cpa16(base + offA, srcA + o, aok);
            cpa16(base + offA + 16, srcA + o + 8, aok);
        }
        if (doW) {
            cpa16(base + offW, srcW + o, true);
            if (BM == 64) cpa16(base + offW + 16, srcW + o + 8, true);
        }
        cpa_commit();
    };

    // ---- ldmatrix offsets (2 k-subchunks per stage) ----
    unsigned aoffH[MT], boffH[NP];
    {
        const int ar = wm * 32 + (lane & 15);
        const int ak = (lane >> 4) * 8;
        const int br = wn * (NT8 * 8) + (lane & 7) + ((lane >> 4) << 3);
        const int bk = ((lane >> 3) & 1) * 8;
#pragma unroll
        for (int t = 0; t < MT; t++) aoffH[t] = (unsigned)(((ar + t * 16) * STR + ak) * 2);
#pragma unroll
        for (int p = 0; p < NP; p++) boffH[p] = (unsigned)(szA + ((br + p * 16) * STR + bk) * 2);
    }

    loadChunk(0, 0);
    loadChunk(1, 1);
    loadChunk(2, 2);

    float acc[MT][NT8][4];
#pragma unroll
    for (int i = 0; i < MT; i++)
#pragma unroll
        for (int j = 0; j < NT8; j++)
#pragma unroll
            for (int k = 0; k < 4; k++) acc[i][j][k] = 0.f;

    for (int kc = 0; kc < NC; kc++) {
        cpa_waitg<2>();
        __syncthreads();
        const int s = kc & 3;
        const int nk = kc + 3;
        if (nk < NC) loadChunk(nk, nk & 3);
        else cpa_commit();

        const unsigned stg = sb + s * STG;
#pragma unroll
        for (int ks = 0; ks < 2; ks++) {
            const unsigned ko = ks * 32;   // 16 halfs
            unsigned ah[MT][4], bh[NP][4];
#pragma unroll
            for (int t = 0; t < MT; t++)
                ldm4(ah[t][0], ah[t][1], ah[t][2], ah[t][3], stg + aoffH[t] + ko);
#pragma unroll
            for (int p = 0; p < NP; p++)
                ldm4(bh[p][0], bh[p][1], bh[p][2], bh[p][3], stg + boffH[p] + ko);
#pragma unroll
            for (int mt = 0; mt < MT; mt++) {
#pragma unroll
                for (int nt = 0; nt < NT8; nt++) {
                    const int p = nt >> 1, nh = (nt & 1) << 1;
                    mma16816(acc[mt][nt], ah[mt], bh[p][nh], bh[p][nh + 1]);
                }
            }
        }
    }

    const int rowb = bm + wm * 32 + (lane >> 2);
    const int colb = bn + wn * (NT8 * 8) + 2 * (lane & 3);
#pragma unroll
    for (int mt = 0; mt < MT; mt++) {
#pragma unroll
        for (int nt = 0; nt < NT8; nt++) {
            const int col = colb + nt * 8;
            float2 b2 = make_float2(0.f, 0.f);
            if (g.bias) b2 = *(const float2*)(g.bias + col);
#pragma unroll
            for (int hh = 0; hh < 2; hh++) {
                const int row = rowb + mt * 16 + hh * 8;
                if (row >= M) continue;
                float v0 = acc[mt][nt][hh * 2 + 0] + b2.x;
                float v1 = acc[mt][nt][hh * 2 + 1] + b2.y;
                if (g.R) {
                    float2 r2 = *(const float2*)(g.R + (size_t)row * N + col);
                    v0 += r2.x; v1 += r2.y;
                }
                if (g.act == 1) { v0 = geluf(v0); v1 = geluf(v1); }
                if (g.Cf) *(float2*)(g.Cf + (size_t)row * N + col) = make_float2(v0, v1);
                if (g.Ch)
                    *(__half2*)(g.Ch + (size_t)row * N + col) =
                        __halves2half2(__float2half_rn(v0), __float2half_rn(v1));
            }
        }
    }
}

template<int BM>
__global__ void __launch_bounds__(256) mma_gemm_kernel(GArgs g)
{
    mma_gemm_impl<BM>(g, blockIdx.x, blockIdx.y);
}

__global__ void __launch_bounds__(256) mma_gemm_dual_kernel(GArgs g0, GArgs g1, int split)
{
    if ((int)blockIdx.x < split) {
        const int local = blockIdx.x;
        mma_gemm_impl<64>(g0, local % g0.ntx, local / g0.ntx);
    } else {
        const int local = blockIdx.x - split;
        mma_gemm_impl<64>(g1, local % g1.ntx, local / g1.ntx);
    }
}

static constexpr int MMASM128 = 4 * (128 * 40 * 2 + 64 * 40 * 2);  // 61440
static constexpr int MMASM64  = 4 * (64 * 40 * 2 + 64 * 40 * 2);   // 40960

// ---------------------------------------------------------------------------
// Fused tensor-core attention (single-term). grid (B*H, 32), 256 thr (4m x 2n).
// KV packed with row stride kvstride (V at +256 within layer block).
// ---------------------------------------------------------------------------
static constexpr int A_QH0 = 0;
static constexpr int A_KH0 = 2560;
static constexpr int A_VH0 = A_KH0 + 8960;      // 11520
static constexpr int A_PS0 = A_VH0 + 8960;      // 20480
static constexpr int A_PARTB = (A_PS0 + 13824) * 2;   // 68608 bytes
static constexpr int ATTSM = A_PARTB + 2048;

__global__ void __launch_bounds__(256) attn_mma_kernel(
    const __half* __restrict__ Qh_g, const __half* __restrict__ KVh,
    __half* __restrict__ cxh, int kvstride)
{
    extern __shared__ char smem[];
    __half* sm = (__half*)smem;
    float* pm   = (float*)(smem + A_PARTB);
    float* psum = pm + 128;
    const unsigned sb = (unsigned)__cvta_generic_to_shared(smem);

    const int bh = blockIdx.x;
    const int b = bh >> 3, h = bh & 7;
    const int g0 = blockIdx.y * 64;
    const int tid = threadIdx.x;
    const int lane = tid & 31, wid = tid >> 5;
    const int wm = wid & 3, wn = wid >> 2;

    if (tid < 128) {
        const int row = tid >> 1;
        const int sp = (tid & 1) * 16;
        const bool ok = (g0 + row) < G;
        const __half* src = Qh_g + ((size_t)(b * G + g0 + row) * 256 + h * 32 + sp);
        unsigned dst = sb + (A_QH0 + row * 40 + sp) * 2;
        cpa16(dst, src, ok);
        cpa16(dst + 16, src + 8, ok);
    }
    if (tid < 196) {
        const size_t rb = (size_t)(b * P + tid) * kvstride + h * 32;
        const __half* ksrc = KVh + rb;
        unsigned kdst = sb + (A_KH0 + tid * 40) * 2;
        cpa16(kdst,      ksrc,      true);
        cpa16(kdst + 16, ksrc + 8,  true);
        cpa16(kdst + 32, ksrc + 16, true);
        cpa16(kdst + 48, ksrc + 24, true);
        const __half* vh = KVh + rb + 256;
        unsigned vhd = sb + (A_VH0 + tid * 40) * 2;
        cpa16(vhd,      vh,      true);
        cpa16(vhd + 16, vh + 8,  true);
        cpa16(vhd + 32, vh + 16, true);
        cpa16(vhd + 48, vh + 24, true);
    } else if (tid < 224) {
        uint4 z = make_uint4(0, 0, 0, 0);
#pragma unroll
        for (int i = 0; i < 5; i++) {
            *(uint4*)(sm + A_KH0 + tid * 40 + i * 8) = z;
            *(uint4*)(sm + A_VH0 + tid * 40 + i * 8) = z;
        }
    }
    cpa_commit();
    cpa_waitg<0>();
    __syncthreads();

    unsigned aq[2][4];
    {
        const int ar = wm * 16 + (lane & 15);
        const int ak = (lane >> 4) * 8;
#pragma unroll
        for (int ks = 0; ks < 2; ks++)
            ldm4(aq[ks][0], aq[ks][1], aq[ks][2], aq[ks][3],
                 sb + (A_QH0 + ar * 40 + ks * 16 + ak) * 2);
    }
    float sacc[13][4];
#pragma unroll
    for (int i = 0; i < 13; i++)
#pragma unroll
        for (int j = 0; j < 4; j++) sacc[i][j] = 0.f;

    {
        const int brr = wn * 104 + (lane & 7) + ((lane >> 4) << 3);
        const int bko = ((lane >> 3) & 1) * 8;
#pragma unroll
        for (int gph = 0; gph < 7; gph++) {
            unsigned bk0[4], bk1[4];
            ldm4(bk0[0], bk0[1], bk0[2], bk0[3],
                 sb + (A_KH0 + (brr + gph * 16) * 40 + bko) * 2);
            ldm4(bk1[0], bk1[1], bk1[2], bk1[3],
                 sb + (A_KH0 + (brr + gph * 16) * 40 + 16 + bko) * 2);
#pragma unroll
            for (int hf = 0; hf < 2; hf++) {
                const int nt = gph * 2 + hf;
                if (nt >= 13) break;
                mma16816(sacc[nt], aq[0], bk0[hf * 2], bk0[hf * 2 + 1]);
                mma16816(sacc[nt], aq[1], bk1[hf * 2], bk1[hf * 2 + 1]);
            }
        }
    }

#pragma unroll
    for (int nt = 0; nt < 13; nt++)
#pragma unroll
        for (int j = 0; j < 4; j++) sacc[nt][j] *= ATT_SCALE;

    float mx0 = -1e30f, mx1 = -1e30f;
#pragma unroll
    for (int nt = 0; nt < 13; nt++) {
        mx0 = fmaxf(mx0, fmaxf(sacc[nt][0], sacc[nt][1]));
        mx1 = fmaxf(mx1, fmaxf(sacc[nt][2], sacc[nt][3]));
    }
    mx0 = fmaxf(mx0, __shfl_xor_sync(0xffffffffu, mx0, 1));
    mx0 = fmaxf(mx0, __shfl_xor_sync(0xffffffffu, mx0, 2));
    mx1 = fmaxf(mx1, __shfl_xor_sync(0xffffffffu, mx1, 1));
    mx1 = fmaxf(mx1, __shfl_xor_sync(0xffffffffu, mx1, 2));

    float s0 = 0.f, s1 = 0.f;
#pragma unroll
    for (int nt = 0; nt < 13; nt++) {
        const int col = wn * 104 + nt * 8 + 2 * (lane & 3);
        float e0 = (col < 196)     ? __expf(sacc[nt][0] - mx0) : 0.f;
        float e1 = (col + 1 < 196) ? __expf(sacc[nt][1] - mx0) : 0.f;
        float e2 = (col < 196)     ? __expf(sacc[nt][2] - mx1) : 0.f;
        float e3 = (col + 1 < 196) ? __expf(sacc[nt][3] - mx1) : 0.f;
        sacc[nt][0] = e0; sacc[nt][1] = e1; sacc[nt][2] = e2; sacc[nt][3] = e3;
        s0 += e0 + e1; s1 += e2 + e3;
    }
    s0 += __shfl_xor_sync(0xffffffffu, s0, 1);
    s0 += __shfl_xor_sync(0xffffffffu, s0, 2);
    s1 += __shfl_xor_sync(0xffffffffu, s1, 1);
    s1 += __shfl_xor_sync(0xffffffffu, s1, 2);

    const int r0 = wm * 16 + (lane >> 2), r1 = r0 + 8;
    if ((lane & 3) == 0) {
        pm[wn * 64 + r0] = mx0;  pm[wn * 64 + r1] = mx1;
        psum[wn * 64 + r0] = s0; psum[wn * 64 + r1] = s1;
    }
    __syncthreads();

    float f0, f1;
    {
        float ma = pm[r0], mb = pm[64 + r0];
        float mg = fmaxf(ma, mb);
        float sg = psum[r0] * __expf(ma - mg) + psum[64 + r0] * __expf(mb - mg);
        f0 = __expf((wn ? mb : ma) - mg) / sg;
        ma = pm[r1]; mb = pm[64 + r1];
        mg = fmaxf(ma, mb);
        sg = psum[r1] * __expf(ma - mg) + psum[64 + r1] * __expf(mb - mg);
        f1 = __expf((wn ? mb : ma) - mg) / sg;
    }
#pragma unroll
    for (int nt = 0; nt < 13; nt++) {
        const int col = wn * 104 + nt * 8 + 2 * (lane & 3);
        *(__half2*)(sm + A_PS0 + r0 * 216 + col) =
            __halves2half2(__float2half_rn(sacc[nt][0] * f0), __float2half_rn(sacc[nt][1] * f0));
        *(__half2*)(sm + A_PS0 + r1 * 216 + col) =
            __halves2half2(__float2half_rn(sacc[nt][2] * f1), __float2half_rn(sacc[nt][3] * f1));
    }
    __syncthreads();

    float vacc[2][4];
#pragma unroll
    for (int i = 0; i < 2; i++)
#pragma unroll
        for (int j = 0; j < 4; j++) vacc[i][j] = 0.f;
    {
        const int ar = wm * 16 + (lane & 15);
        const int ak = (lane >> 4) * 8;
        const int vr = (lane & 15);
        const int vc = wn * 16 + (lane >> 4) * 8;
#pragma unroll
        for (int ks = 0; ks < 13; ks++) {
            unsigned ap[4], bvh[4];
            ldm4(ap[0], ap[1], ap[2], ap[3],
                 sb + (A_PS0 + ar * 216 + ks * 16 + ak) * 2);
            ldm4t(bvh[0], bvh[1], bvh[2], bvh[3],
                  sb + (A_VH0 + (ks * 16 + vr) * 40 + vc) * 2);
            mma16816(vacc[0], ap, bvh[0], bvh[1]);
            mma16816(vacc[1], ap, bvh[2], bvh[3]);
        }
    }

    {
        const int gr = g0 + wm * 16 + (lane >> 2);
        const int dc = wn * 16 + 2 * (lane & 3);
#pragma unroll
        for (int nt = 0; nt < 2; nt++) {
            const int d = dc + nt * 8;
#pragma unroll
            for (int hh = 0; hh < 2; hh++) {
                const int gene = gr + hh * 8;
                if (gene >= G) continue;
                const size_t off = (size_t)(b * G + gene) * 256 + h * 32 + d;
                *(__half2*)(cxh + off) =
                    __halves2half2(__float2half_rn(vacc[nt][hh * 2 + 0]),
                                   __float2half_rn(vacc[nt][hh * 2 + 1]));
            }
        }
    }
}

// ---------------------------------------------------------------------------
// weight convert: fp32 -> fp16, 23 segments
// ---------------------------------------------------------------------------
struct CSeg { const float* src; __half* h; int blk_off; };
struct CTable { CSeg seg[23]; };
__global__ void __launch_bounds__(256) wconv_kernel(CTable t)
{
    const int bt = blockIdx.x;
    int s = 0;
#pragma unroll
    for (int i = 1; i < 23; i++) if (t.seg[i].blk_off <= bt) s = i;
    const CSeg sg = t.seg[s];
    const int idx = (bt - sg.blk_off) * 1024 + threadIdx.x * 4;
    float4 v = *(const float4*)(sg.src + idx);
    *(__half2*)(sg.h + idx)     = __halves2half2(__float2half_rn(v.x), __float2half_rn(v.y));
    *(__half2*)(sg.h + idx + 2) = __halves2half2(__float2half_rn(v.z), __float2half_rn(v.w));
}

// merged prep (+ concat kv bias build)
__global__ void __launch_bounds__(256) prep_kernel(
    const float* __restrict__ pf, const int* __restrict__ coords,
    const float* __restrict__ re, const float* __restrict__ ce,
    const float* __restrict__ gq, const float* __restrict__ in_proj_b,
    __half* __restrict__ pfh, __half* __restrict__ peh,
    float* __restrict__ q, __half* __restrict__ qh, float* __restrict__ kvb)
{
    const int bid = blockIdx.x;
    if (bid < 392) {
        int idx = (bid * 256 + threadIdx.x) * 4;
        float4 v = *(const float4*)(pf + idx);
        *(__half2*)(pfh + idx)     = __halves2half2(__float2half_rn(v.x), __float2half_rn(v.y));
        *(__half2*)(pfh + idx + 2) = __halves2half2(__float2half_rn(v.z), __float2half_rn(v.w));
    } else if (bid < 784) {
        int idx = (bid - 392) * 256 + threadIdx.x;
        if (idx < B * P * D) {
            int d = idx & 255;
            int bp = idx >> 8;
            int r = coords[bp * 2 + 0];
            int c = coords[bp * 2 + 1];
            r = min(max(r, 0), 255);
            c = min(max(c, 0), 255);
            float v = (d < 128) ? re[r * 128 + d] : ce[c * 128 + (d - 128)];
            peh[idx] = __float2half_rn(v);
        }
    } else if (bid < 4784) {
        int idx = (bid - 784) * 256 + threadIdx.x;
        float v = gq[idx % (G * D)];
        q[idx] = v;
        qh[idx] = __float2half_rn(v);
    } else {
        // kv bias concat: [NL*512]
        int idx = (bid - 4784) * 256 + threadIdx.x;
        if (idx < NL * 2 * D) {
            int l = idx >> 9, j = idx & 511;
            kvb[idx] = in_proj_b[l * 3 * D + D + j];
        }
    }
}

// ---------------------------------------------------------------------------
// LN (+optional fp16 emit)
// ---------------------------------------------------------------------------
__global__ void ln_kernel(const float* __restrict__ x, const float* __restrict__ r,
                          const float* __restrict__ gg, const float* __restrict__ bb,
                          float* __restrict__ y, __half* __restrict__ yh,
                          int rows)
{
    int gid = blockIdx.x * blockDim.x + threadIdx.x;
    int row = gid >> 5;
    int lane = gid & 31;
    if (row >= rows) return;
    const float* xp = x + (size_t)row * 256;
    float4 a = *(const float4*)(xp + lane * 4);
    float4 c = *(const float4*)(xp + 128 + lane * 4);
    if (r) {
        const float* rp = r + (size_t)row * 256;
        float4 ra = *(const float4*)(rp + lane * 4);
        float4 rc = *(const float4*)(rp + 128 + lane * 4);
        a.x += ra.x; a.y += ra.y; a.z += ra.z; a.w += ra.w;
        c.x += rc.x; c.y += rc.y; c.z += rc.z; c.w += rc.w;
    }
    float s = a.x + a.y + a.z + a.w + c.x + c.y + c.z + c.w;
    float q = a.x * a.x + a.y * a.y + a.z * a.z + a.w * a.w
            + c.x * c.x + c.y * c.y + c.z * c.z + c.w * c.w;
#pragma unroll
    for (int o = 16; o; o >>= 1) {
        s += __shfl_xor_sync(0xffffffffu, s, o);
        q += __shfl_xor_sync(0xffffffffu, q, o);
    }
    float mean = s * (1.f / 256.f);
    float var = q * (1.f / 256.f) - mean * mean;
    float rstd = rsqrtf(var + 1e-5f);
    float4 g0 = *(const float4*)(gg + lane * 4);
    float4 g1 = *(const float4*)(gg + 128 + lane * 4);
    float4 b0 = *(const float4*)(bb + lane * 4);
    float4 b1 = *(const float4*)(bb + 128 + lane * 4);
    float4 o0, o1;
    o0.x = (a.x - mean) * rstd * g0.x + b0.x;
    o0.y = (a.y - mean) * rstd * g0.y + b0.y;
    o0.z = (a.z - mean) * rstd * g0.z + b0.z;
    o0.w = (a.w - mean) * rstd * g0.w + b0.w;
    o1.x = (c.x - mean) * rstd * g1.x + b1.x;
    o1.y = (c.y - mean) * rstd * g1.y + b1.y;
    o1.z = (c.z - mean) * rstd * g1.z + b1.z;
    o1.w = (c.w - mean) * rstd * g1.w + b1.w;
    float* yp = y + (size_t)row * 256;
    *(float4*)(yp + lane * 4) = o0;
    *(float4*)(yp + 128 + lane * 4) = o1;
    if (yh) {
        const size_t b0o = (size_t)row * 256 + lane * 4;
        *(__half2*)(yh + b0o)       = __halves2half2(__float2half_rn(o0.x), __float2half_rn(o0.y));
        *(__half2*)(yh + b0o + 2)   = __halves2half2(__float2half_rn(o0.z), __float2half_rn(o0.w));
        *(__half2*)(yh + b0o + 128) = __halves2half2(__float2half_rn(o1.x), __float2half_rn(o1.y));
        *(__half2*)(yh + b0o + 130) = __halves2half2(__float2half_rn(o1.z), __float2half_rn(o1.w));
    }
}

// ---------------------------------------------------------------------------
// head: bp-tiled. grid (G/8, MP/8), block 256.
// ---------------------------------------------------------------------------
__global__ void __launch_bounds__(256) head_kernel(
    const float* __restrict__ qp, const float* __restrict__ pp, float* __restrict__ out)
{
    const int g = blockIdx.x * 8 + (threadIdx.x >> 5);
    const int col = (threadIdx.x & 31) << 2;
    const int bp0 = blockIdx.y * 8;
    float4 qv;
    int curb = -1;
#pragma unroll
    for (int i = 0; i < 8; i++) {
        const int bp = bp0 + i;
        const int b = (bp >= P) ? 1 : 0;
        if (b != curb) {
            qv = *(const float4*)(qp + (size_t)(b * G + g) * HALF + col);
            curb = b;
        }
        float4 pv = *(const float4*)(pp + (size_t)bp * HALF + col);
        float4 o;
        o.x = softplusf(pv.x + qv.x);
        o.y = softplusf(pv.y + qv.y);
        o.z = softplusf(pv.z + qv.z);
        o.w = softplusf(pv.w + qv.w);
        *(float4*)(out + ((size_t)bp * G + g) * HALF + col) = o;
    }
}

// ---------------------------------------------------------------------------
extern "C" void kernel_launch(void* const* d_in, const int* in_sizes, int n_in,
                              void* d_out, int out_size)
{
    (void)in_sizes; (void)n_in; (void)out_size;
    const float* patch_features = (const float*)d_in[0];
    const int*   patch_coords   = (const int*)d_in[1];
    const float* patch_proj_w   = (const float*)d_in[2];
    const float* patch_proj_b   = (const float*)d_in[3];
    const float* patch_ln_g     = (const float*)d_in[4];
    const float* patch_ln_b     = (const float*)d_in[5];
    const float* row_embed      = (const float*)d_in[6];
    const float* col_embed      = (const float*)d_in[7];
    const float* pe_proj_w      = (const float*)d_in[8];
    const float* pe_proj_b      = (const float*)d_in[9];
    const float* gene_queries   = (const float*)d_in[10];
    const float* in_proj_w      = (const float*)d_in[11];
    const float* in_proj_b      = (const float*)d_in[12];
    const float* out_w          = (const float*)d_in[13];
    const float* out_b          = (const float*)d_in[14];
    const float* ff1_w          = (const float*)d_in[15];
    const float* ff1_b          = (const float*)d_in[16];
    const float* ff2_w          = (const float*)d_in[17];
    const float* ff2_b          = (const float*)d_in[18];
    const float* ln1_g          = (const float*)d_in[19];
    const float* ln1_b          = (const float*)d_in[20];
    const float* ln2_g          = (const float*)d_in[21];
    const float* ln2_b          = (const float*)d_in[22];
    const float* head_w1        = (const float*)d_in[23];
    const float* head_b1        = (const float*)d_in[24];
    float* out = (float*)d_out;

    cudaFuncSetAttribute(mma_gemm_kernel<128>, cudaFuncAttributeMaxDynamicSharedMemorySize, MMASM128);
    cudaFuncSetAttribute(mma_gemm_kernel<64>,  cudaFuncAttributeMaxDynamicSharedMemorySize, MMASM64);
    cudaFuncSetAttribute(mma_gemm_dual_kernel, cudaFuncAttributeMaxDynamicSharedMemorySize, MMASM64);
    cudaFuncSetAttribute(attn_mma_kernel,      cudaFuncAttributeMaxDynamicSharedMemorySize, ATTSM);

    float* ws = nullptr;
    cudaGetSymbolAddress((void**)&ws, g_ws);
    __half* hf = nullptr;
    cudaGetSymbolAddress((void**)&hf, g_hf);

    float* patch_emb = ws + OFF_PATCH;
    float* tmp       = ws + OFF_TMP;
    float* q         = ws + OFF_Q;
    float* att       = ws + OFF_ATT;
    float* qproj     = ws + OFF_QP;
    float* pproj     = ws + OFF_PP;
    float* kvb       = ws + OFF_KVB;

    __half* qh  = hf + HF_QH;
    __half* l1h = hf + HF_L1H;
    __half* cxh = hf + HF_CXH;
    __half* fh  = hf + HF_FH;
    __half* qbh = hf + HF_QBH;
    __half* kva = hf + HF_KVA;
    __half* pfh = hf + HF_PFH;
    __half* peh = hf + HF_PEH;
    __half* pch = hf + HF_PCH;

    // ---- one-time weight convert ----
    CTable ct;
    int total_blk;
    {
        int seg = 0, boff = 0;
        auto add = [&](const float* src, size_t ho, int count) {
            ct.seg[seg] = { src, hf + ho, boff };
            boff += count / 1024;
            seg++;
        };
        for (int l = 0; l < NL; l++)
            add(in_proj_w + (size_t)l * 3 * D * D, HF_WQ + (size_t)l * D * D, D * D);
        for (int l = 0; l < NL; l++)
            add(out_w + (size_t)l * D * D, HF_WO + (size_t)l * D * D, D * D);
        for (int l = 0; l < NL; l++)
            add(ff1_w + (size_t)l * 4 * D * D, HF_F1 + (size_t)l * 4 * D * D, 4 * D * D);
        for (int l = 0; l < NL; l++)
            add(ff2_w + (size_t)l * 4 * D * D, HF_F2 + (size_t)l * 4 * D * D, 4 * D * D);
        add(head_w1, HF_HD, HALF * D);
        add(patch_proj_w, HF_WP, D * FD);
        add(pe_proj_w, HF_WE, D * D);
        for (int l = 0; l < NL; l++)
            add(in_proj_w + (size_t)l * 3 * D * D + D * D, HF_WK + (size_t)l * 2 * D * D, 2 * D * D);
        total_blk = boff;
    }
    wconv_kernel<<<total_blk, 256>>>(ct);
    prep_kernel<<<4792, 256>>>(patch_features, patch_coords, row_embed, col_embed,
                               gene_queries, in_proj_b, pfh, peh, q, qh, kvb);

    const int MT64  = (MQ + 63) / 64;     // 63
    const int MT128 = (MQ + 127) / 128;   // 32
    const int MTP   = (MP + 63) / 64;     // 7

    auto GA = [](const __half* Ah, const __half* Wh,
                 const float* bias, const float* R,
                 float* Cf, __half* Ch,
                 int M, int N, int K, int act) {
        GArgs g;
        g.Ah = Ah; g.Wh = Wh; g.bias = bias; g.R = R;
        g.Cf = Cf; g.Ch = Ch;
        g.M = M; g.N = N; g.K = K; g.act = act; g.ntx = N / 64;
        return g;
    };

    // ---- Stage A ----
    mma_gemm_kernel<64><<<dim3(D / 64, MTP), 256, MMASM64>>>(
        GA(pfh, hf + HF_WP, patch_proj_b, nullptr, tmp, nullptr, MP, D, FD, 0));
    ln_kernel<<<(MP + 7) / 8, 256>>>(tmp, nullptr, patch_ln_g, patch_ln_b, patch_emb,
                                     nullptr, MP);
    mma_gemm_kernel<64><<<dim3(D / 64, MTP), 256, MMASM64>>>(
        GA(peh, hf + HF_WE, pe_proj_b, patch_emb, nullptr, pch, MP, D, D, 0));

    // ---- KV for all layers + patch-side head projection (both depend only on pch) ----
    {
        GArgs gkva = GA(pch, hf + HF_WK, kvb, nullptr, nullptr, kva, MP, NL * 2 * D, D, 0);
        GArgs gpp  = GA(pch, hf + HF_HD, nullptr, nullptr, pproj, nullptr, MP, HALF, D, 0);
        const int split = gkva.ntx * MTP;            // 32*7 = 224
        const int tot   = split + gpp.ntx * MTP;     // + 2*7 = 238
        mma_gemm_dual_kernel<<<tot, 256, MMASM64>>>(gkva, gpp, split);
    }

    // ---- Stage B ----
    for (int l = 0; l < NL; l++) {
        const float* bq = in_proj_b + (size_t)l * 3 * D;
        mma_gemm_kernel<64><<<dim3(D / 64, MT64), 256, MMASM64>>>(
            GA(qh, hf + HF_WQ + (size_t)l * D * D, bq, nullptr,
               nullptr, qbh, MQ, D, D, 0));
        attn_mma_kernel<<<dim3(B * H, 32), 256, ATTSM>>>(
            qbh, kva + l * 2 * D, cxh, NL * 2 * D);
        mma_gemm_kernel<64><<<dim3(D / 64, MT64), 256, MMASM64>>>(
            GA(cxh, hf + HF_WO + (size_t)l * D * D, out_b + (size_t)l * D, q,
               att, nullptr, MQ, D, D, 0));
        ln_kernel<<<(MQ + 7) / 8, 256>>>(att, nullptr, ln1_g + (size_t)l * D, ln1_b + (size_t)l * D,
                                         q, l1h, MQ);
        mma_gemm_kernel<128><<<dim3(4 * D / 64, MT128), 256, MMASM128>>>(
            GA(l1h, hf + HF_F1 + (size_t)l * 4 * D * D, ff1_b + (size_t)l * 4 * D, nullptr,
               nullptr, fh, MQ, 4 * D, D, 1));
        mma_gemm_kernel<64><<<dim3(D / 64, MT64), 256, MMASM64>>>(
            GA(fh, hf + HF_F2 + (size_t)l * 4 * D * D, ff2_b + (size_t)l * D, q,
               att, nullptr, MQ, D, 4 * D, 0));
        ln_kernel<<<(MQ + 7) / 8, 256>>>(att, nullptr, ln2_g + (size_t)l * D, ln2_b + (size_t)l * D,
                                         q, qh, MQ);
    }

    // ---- Stage C ----
    mma_gemm_kernel<64><<<dim3(HALF / 64, MT64), 256, MMASM64>>>(
        GA(qh, hf + HF_HD, head_b1, nullptr, qproj, nullptr, MQ, HALF, D, 0));
    head_kernel<<<dim3(G / 8, MP / 8), 256>>>(qproj, pproj, out);
}

// round 16
// speedup vs baseline: 2.1242x; 1.0448x over previous
#include <cuda_runtime.h>
#include <cuda_fp16.h>
#include <cstddef>
#include <cstdint>
#include <math.h>

// ---------------------------------------------------------------------------
// SpatialTranscriptomicsDecoder — GB300 sm_103a. Round 16.
// R15 + BM=128 tiling for all M=4000 GEMMs (Qproj/out/ff2/head-q): fewer,
// fatter CTAs, 25% fewer ldmatrix per mma, half the pipeline fills.
// ---------------------------------------------------------------------------

static constexpr int B = 2, P = 196, FD = 1024, G = 2000, D = 256, H = 8, NL = 4, HALF = 128;
static constexpr float ATT_SCALE = 0.17677669529663687f;
static constexpr int MQ = B * G;   // 4000
static constexpr int MP = B * P;   // 392

// ---------------- fp32 workspace ----------------
static constexpr size_t OFF_PATCH = 0;
static constexpr size_t OFF_TMP   = OFF_PATCH + (size_t)MP * D;
static constexpr size_t OFF_Q     = OFF_TMP   + (size_t)MP * D;
static constexpr size_t OFF_ATT   = OFF_Q     + (size_t)MQ * D;
static constexpr size_t OFF_QP    = OFF_ATT   + (size_t)MQ * D;
static constexpr size_t OFF_PP    = OFF_QP    + (size_t)MQ * HALF;
static constexpr size_t OFF_KVB   = OFF_PP    + (size_t)MP * HALF;
static constexpr size_t WS_TOTAL  = OFF_KVB   + (size_t)NL * 2 * D;
__device__ float g_ws[WS_TOTAL];

// ---------------- fp16 workspace ----------------
static constexpr size_t BQ  = (size_t)MQ * D;
static constexpr size_t HF_QH  = 0;
static constexpr size_t HF_L1H = HF_QH + BQ;
static constexpr size_t HF_CXH = HF_L1H + BQ;
static constexpr size_t HF_FH  = HF_CXH + BQ;
static constexpr size_t HF_QBH = HF_FH + (size_t)MQ * 4 * D;
static constexpr size_t HF_KVA = HF_QBH + BQ;
static constexpr size_t HF_PFH = HF_KVA + (size_t)MP * NL * 2 * D;
static constexpr size_t HF_PEH = HF_PFH + (size_t)MP * FD;
static constexpr size_t HF_PCH = HF_PEH + (size_t)MP * D;
static constexpr size_t HF_WQ  = HF_PCH + (size_t)MP * D;
static constexpr size_t HF_WO  = HF_WQ  + (size_t)NL * D * D;
static constexpr size_t HF_F1  = HF_WO  + (size_t)NL * D * D;
static constexpr size_t HF_F2  = HF_F1  + (size_t)NL * 4 * D * D;
static constexpr size_t HF_HD  = HF_F2  + (size_t)NL * 4 * D * D;
static constexpr size_t HF_WP  = HF_HD  + (size_t)HALF * D;
static constexpr size_t HF_WE  = HF_WP  + (size_t)D * FD;
static constexpr size_t HF_WK  = HF_WE  + (size_t)D * D;
static constexpr size_t HF_TOTAL = HF_WK + (size_t)NL * 2 * D * D;
__device__ __half g_hf[HF_TOTAL];

// ---------------- helpers ----------------
__device__ __forceinline__ float geluf(float x) {
    return 0.5f * x * (1.0f + erff(x * 0.7071067811865476f));
}
__device__ __forceinline__ float softplusf(float x) {
    return fmaxf(x, 0.0f) + __logf(1.0f + __expf(-fabsf(x)));
}
__device__ __forceinline__ void cpa16(unsigned int dst, const void* src, bool ok) {
    asm volatile("cp.async.ca.shared.global [%0], [%1], 16, %2;"
                 :: "r"(dst), "l"(src), "r"(ok ? 16 : 0) : "memory");
}
__device__ __forceinline__ void cpa_commit() {
    asm volatile("cp.async.commit_group;" ::: "memory");
}
template<int Ng> __device__ __forceinline__ void cpa_waitg() {
    asm volatile("cp.async.wait_group %0;" :: "n"(Ng) : "memory");
}
__device__ __forceinline__ void ldm4(unsigned& r0, unsigned& r1, unsigned& r2, unsigned& r3,
                                     unsigned addr) {
    asm volatile("ldmatrix.sync.aligned.m8n8.x4.shared.b16 {%0,%1,%2,%3}, [%4];"
                 : "=r"(r0), "=r"(r1), "=r"(r2), "=r"(r3) : "r"(addr));
}
__device__ __forceinline__ void ldm4t(unsigned& r0, unsigned& r1, unsigned& r2, unsigned& r3,
                                      unsigned addr) {
    asm volatile("ldmatrix.sync.aligned.m8n8.x4.trans.shared.b16 {%0,%1,%2,%3}, [%4];"
                 : "=r"(r0), "=r"(r1), "=r"(r2), "=r"(r3) : "r"(addr));
}
__device__ __forceinline__ void mma16816(float* d, const unsigned* a, unsigned b0, unsigned b1) {
    asm volatile(
        "mma.sync.aligned.m16n8k16.row.col.f32.f16.f16.f32 "
        "{%0,%1,%2,%3}, {%4,%5,%6,%7}, {%8,%9}, {%0,%1,%2,%3};"
        : "+f"(d[0]), "+f"(d[1]), "+f"(d[2]), "+f"(d[3])
        : "r"(a[0]), "r"(a[1]), "r"(a[2]), "r"(a[3]), "r"(b0), "r"(b1));
}

// ---------------------------------------------------------------------------
// GEMM: C[M,N] = act( A @ W^T + bias + R ); fp16 in, fp32 acc, k-chunk 32.
// ---------------------------------------------------------------------------
struct GArgs {
    const __half* Ah; const __half* Wh;
    const float* bias; const float* R;
    float* Cf; __half* Ch;
    int M, N, K, act, ntx;
};

template<int BM>
__device__ __forceinline__ void mma_gemm_impl(const GArgs& g, int bx, int by)
{
    constexpr int STR = 40;
    constexpr int szA = BM * STR * 2;
    constexpr int szW = 64 * STR * 2;
    constexpr int STG = szA + szW;
    constexpr int MT  = 2;
    constexpr int WMASK  = (BM == 128) ? 3 : 1;
    constexpr int WSHIFT = (BM == 128) ? 2 : 1;
    constexpr int NT8 = (BM == 128) ? 4 : 2;
    constexpr int NP  = NT8 / 2;

    extern __shared__ char smem[];
    const unsigned sb = (unsigned)__cvta_generic_to_shared(smem);

    const int tid = threadIdx.x;
    const int lane = tid & 31, wid = tid >> 5;
    const int wm = wid & WMASK, wn = wid >> WSHIFT;
    const int bm = by * BM;
    const int bn = bx * 64;
    const int NC = g.K >> 5;
    const int M = g.M, N = g.N, K = g.K;

    unsigned offA = 0, offW = 0;
    const __half* srcA = nullptr;
    const __half* srcW = nullptr;
    bool aok = false, doA = false, doW = false;
    if (BM == 128) {
        const int rowA = tid >> 1, segA = tid & 1;
        doA = true;
        aok = (bm + rowA) < M;
        offA = (unsigned)((rowA * STR + segA * 16) * 2);
        srcA = g.Ah + (size_t)(bm + rowA) * K + segA * 16;
        const int rowW = tid >> 2, segW = tid & 3;
        doW = true;
        offW = (unsigned)(szA + (rowW * STR + segW * 8) * 2);
        srcW = g.Wh + (size_t)(bn + rowW) * K + segW * 8;
    } else {
        if (tid < 128) {
            const int rowA = tid >> 1, segA = tid & 1;
            doA = true;
            aok = (bm + rowA) < M;
            offA = (unsigned)((rowA * STR + segA * 16) * 2);
            srcA = g.Ah + (size_t)(bm + rowA) * K + segA * 16;
        } else {
            const int rowW = (tid - 128) >> 1, segW = tid & 1;
            doW = true;
            offW = (unsigned)(szA + (rowW * STR + segW * 16) * 2);
            srcW = g.Wh + (size_t)(bn + rowW) * K + segW * 16;
        }
    }

    auto loadChunk = [&](int kc, int s) {
        const int o = kc << 5;
        const unsigned base = sb + s * STG;
        if (doA) {
            cpa16(base + offA, srcA + o, aok);
            cpa16(base + offA + 16, srcA + o + 8, aok);
        }
        if (doW) {
            cpa16(base + offW, srcW + o, true);
            if (BM == 64) cpa16(base + offW + 16, srcW + o + 8, true);
        }
        cpa_commit();
    };

    unsigned aoffH[MT], boffH[NP];
    {
        const int ar = wm * 32 + (lane & 15);
        const int ak = (lane >> 4) * 8;
        const int br = wn * (NT8 * 8) + (lane & 7) + ((lane >> 4) << 3);
        const int bk = ((lane >> 3) & 1) * 8;
#pragma unroll
        for (int t = 0; t < MT; t++) aoffH[t] = (unsigned)(((ar + t * 16) * STR + ak) * 2);
#pragma unroll
        for (int p = 0; p < NP; p++) boffH[p] = (unsigned)(szA + ((br + p * 16) * STR + bk) * 2);
    }

    loadChunk(0, 0);
    loadChunk(1, 1);
    loadChunk(2, 2);

    float acc[MT][NT8][4];
#pragma unroll
    for (int i = 0; i < MT; i++)
#pragma unroll
        for (int j = 0; j < NT8; j++)
#pragma unroll
            for (int k = 0; k < 4; k++) acc[i][j][k] = 0.f;

    for (int kc = 0; kc < NC; kc++) {
        cpa_waitg<2>();
        __syncthreads();
        const int s = kc & 3;
        const int nk = kc + 3;
        if (nk < NC) loadChunk(nk, nk & 3);
        else cpa_commit();

        const unsigned stg = sb + s * STG;
#pragma unroll
        for (int ks = 0; ks < 2; ks++) {
            const unsigned ko = ks * 32;
            unsigned ah[MT][4], bh[NP][4];
#pragma unroll
            for (int t = 0; t < MT; t++)
                ldm4(ah[t][0], ah[t][1], ah[t][2], ah[t][3], stg + aoffH[t] + ko);
#pragma unroll
            for (int p = 0; p < NP; p++)
                ldm4(bh[p][0], bh[p][1], bh[p][2], bh[p][3], stg + boffH[p] + ko);
#pragma unroll
            for (int mt = 0; mt < MT; mt++) {
#pragma unroll
                for (int nt = 0; nt < NT8; nt++) {
                    const int p = nt >> 1, nh = (nt & 1) << 1;
                    mma16816(acc[mt][nt], ah[mt], bh[p][nh], bh[p][nh + 1]);
                }
            }
        }
    }

    const int rowb = bm + wm * 32 + (lane >> 2);
    const int colb = bn + wn * (NT8 * 8) + 2 * (lane & 3);
#pragma unroll
    for (int mt = 0; mt < MT; mt++) {
#pragma unroll
        for (int nt = 0; nt < NT8; nt++) {
            const int col = colb + nt * 8;
            float2 b2 = make_float2(0.f, 0.f);
            if (g.bias) b2 = *(const float2*)(g.bias + col);
#pragma unroll
            for (int hh = 0; hh < 2; hh++) {
                const int row = rowb + mt * 16 + hh * 8;
                if (row >= M) continue;
                float v0 = acc[mt][nt][hh * 2 + 0] + b2.x;
                float v1 = acc[mt][nt][hh * 2 + 1] + b2.y;
                if (g.R) {
                    float2 r2 = *(const float2*)(g.R + (size_t)row * N + col);
                    v0 += r2.x; v1 += r2.y;
                }
                if (g.act == 1) { v0 = geluf(v0); v1 = geluf(v1); }
                if (g.Cf) *(float2*)(g.Cf + (size_t)row * N + col) = make_float2(v0, v1);
                if (g.Ch)
                    *(__half2*)(g.Ch + (size_t)row * N + col) =
                        __halves2half2(__float2half_rn(v0), __float2half_rn(v1));
            }
        }
    }
}

template<int BM>
__global__ void __launch_bounds__(256) mma_gemm_kernel(GArgs g)
{
    mma_gemm_impl<BM>(g, blockIdx.x, blockIdx.y);
}

__global__ void __launch_bounds__(256) mma_gemm_dual_kernel(GArgs g0, GArgs g1, int split)
{
    if ((int)blockIdx.x < split) {
        const int local = blockIdx.x;
        mma_gemm_impl<64>(g0, local % g0.ntx, local / g0.ntx);
    } else {
        const int local = blockIdx.x - split;
        mma_gemm_impl<64>(g1, local % g1.ntx, local / g1.ntx);
    }
}

static constexpr int MMASM128 = 4 * (128 * 40 * 2 + 64 * 40 * 2);  // 61440
static constexpr int MMASM64  = 4 * (64 * 40 * 2 + 64 * 40 * 2);   // 40960

// ---------------------------------------------------------------------------
// Fused tensor-core attention (single-term). grid (B*H, 32), 256 thr.
// ---------------------------------------------------------------------------
static constexpr int A_QH0 = 0;
static constexpr int A_KH0 = 2560;
static constexpr int A_VH0 = A_KH0 + 8960;
static constexpr int A_PS0 = A_VH0 + 8960;
static constexpr int A_PARTB = (A_PS0 + 13824) * 2;
static constexpr int ATTSM = A_PARTB + 2048;

__global__ void __launch_bounds__(256) attn_mma_kernel(
    const __half* __restrict__ Qh_g, const __half* __restrict__ KVh,
    __half* __restrict__ cxh, int kvstride)
{
    extern __shared__ char smem[];
    __half* sm = (__half*)smem;
    float* pm   = (float*)(smem + A_PARTB);
    float* psum = pm + 128;
    const unsigned sb = (unsigned)__cvta_generic_to_shared(smem);

    const int bh = blockIdx.x;
    const int b = bh >> 3, h = bh & 7;
    const int g0 = blockIdx.y * 64;
    const int tid = threadIdx.x;
    const int lane = tid & 31, wid = tid >> 5;
    const int wm = wid & 3, wn = wid >> 2;

    if (tid < 128) {
        const int row = tid >> 1;
        const int sp = (tid & 1) * 16;
        const bool ok = (g0 + row) < G;
        const __half* src = Qh_g + ((size_t)(b * G + g0 + row) * 256 + h * 32 + sp);
        unsigned dst = sb + (A_QH0 + row * 40 + sp) * 2;
        cpa16(dst, src, ok);
        cpa16(dst + 16, src + 8, ok);
    }
    if (tid < 196) {
        const size_t rb = (size_t)(b * P + tid) * kvstride + h * 32;
        const __half* ksrc = KVh + rb;
        unsigned kdst = sb + (A_KH0 + tid * 40) * 2;
        cpa16(kdst,      ksrc,      true);
        cpa16(kdst + 16, ksrc + 8,  true);
        cpa16(kdst + 32, ksrc + 16, true);
        cpa16(kdst + 48, ksrc + 24, true);
        const __half* vh = KVh + rb + 256;
        unsigned vhd = sb + (A_VH0 + tid * 40) * 2;
        cpa16(vhd,      vh,      true);
        cpa16(vhd + 16, vh + 8,  true);
        cpa16(vhd + 32, vh + 16, true);
        cpa16(vhd + 48, vh + 24, true);
    } else if (tid < 224) {
        uint4 z = make_uint4(0, 0, 0, 0);
#pragma unroll
        for (int i = 0; i < 5; i++) {
            *(uint4*)(sm + A_KH0 + tid * 40 + i * 8) = z;
            *(uint4*)(sm + A_VH0 + tid * 40 + i * 8) = z;
        }
    }
    cpa_commit();
    cpa_waitg<0>();
    __syncthreads();

    unsigned aq[2][4];
    {
        const int ar = wm * 16 + (lane & 15);
        const int ak = (lane >> 4) * 8;
#pragma unroll
        for (int ks = 0; ks < 2; ks++)
            ldm4(aq[ks][0], aq[ks][1], aq[ks][2], aq[ks][3],
                 sb + (A_QH0 + ar * 40 + ks * 16 + ak) * 2);
    }
    float sacc[13][4];
#pragma unroll
    for (int i = 0; i < 13; i++)
#pragma unroll
        for (int j = 0; j < 4; j++) sacc[i][j] = 0.f;

    {
        const int brr = wn * 104 + (lane & 7) + ((lane >> 4) << 3);
        const int bko = ((lane >> 3) & 1) * 8;
#pragma unroll
        for (int gph = 0; gph < 7; gph++) {
            unsigned bk0[4], bk1[4];
            ldm4(bk0[0], bk0[1], bk0[2], bk0[3],
                 sb + (A_KH0 + (brr + gph * 16) * 40 + bko) * 2);
            ldm4(bk1[0], bk1[1], bk1[2], bk1[3],
                 sb + (A_KH0 + (brr + gph * 16) * 40 + 16 + bko) * 2);
#pragma unroll
            for (int hf = 0; hf < 2; hf++) {
                const int nt = gph * 2 + hf;
                if (nt >= 13) break;
                mma16816(sacc[nt], aq[0], bk0[hf * 2], bk0[hf * 2 + 1]);
                mma16816(sacc[nt], aq[1], bk1[hf * 2], bk1[hf * 2 + 1]);
            }
        }
    }

#pragma unroll
    for (int nt = 0; nt < 13; nt++)
#pragma unroll
        for (int j = 0; j < 4; j++) sacc[nt][j] *= ATT_SCALE;

    float mx0 = -1e30f, mx1 = -1e30f;
#pragma unroll
    for (int nt = 0; nt < 13; nt++) {
        mx0 = fmaxf(mx0, fmaxf(sacc[nt][0], sacc[nt][1]));
        mx1 = fmaxf(mx1, fmaxf(sacc[nt][2], sacc[nt][3]));
    }
    mx0 = fmaxf(mx0, __shfl_xor_sync(0xffffffffu, mx0, 1));
    mx0 = fmaxf(mx0, __shfl_xor_sync(0xffffffffu, mx0, 2));
    mx1 = fmaxf(mx1, __shfl_xor_sync(0xffffffffu, mx1, 1));
    mx1 = fmaxf(mx1, __shfl_xor_sync(0xffffffffu, mx1, 2));

    float s0 = 0.f, s1 = 0.f;
#pragma unroll
    for (int nt = 0; nt < 13; nt++) {
        const int col = wn * 104 + nt * 8 + 2 * (lane & 3);
        float e0 = (col < 196)     ? __expf(sacc[nt][0] - mx0) : 0.f;
        float e1 = (col + 1 < 196) ? __expf(sacc[nt][1] - mx0) : 0.f;
        float e2 = (col < 196)     ? __expf(sacc[nt][2] - mx1) : 0.f;
        float e3 = (col + 1 < 196) ? __expf(sacc[nt][3] - mx1) : 0.f;
        sacc[nt][0] = e0; sacc[nt][1] = e1; sacc[nt][2] = e2; sacc[nt][3] = e3;
        s0 += e0 + e1; s1 += e2 + e3;
    }
    s0 += __shfl_xor_sync(0xffffffffu, s0, 1);
    s0 += __shfl_xor_sync(0xffffffffu, s0, 2);
    s1 += __shfl_xor_sync(0xffffffffu, s1, 1);
    s1 += __shfl_xor_sync(0xffffffffu, s1, 2);

    const int r0 = wm * 16 + (lane >> 2), r1 = r0 + 8;
    if ((lane & 3) == 0) {
        pm[wn * 64 + r0] = mx0;  pm[wn * 64 + r1] = mx1;
        psum[wn * 64 + r0] = s0; psum[wn * 64 + r1] = s1;
    }
    __syncthreads();

    float f0, f1;
    {
        float ma = pm[r0], mb = pm[64 + r0];
        float mg = fmaxf(ma, mb);
        float sg = psum[r0] * __expf(ma - mg) + psum[64 + r0] * __expf(mb - mg);
        f0 = __expf((wn ? mb : ma) - mg) / sg;
        ma = pm[r1]; mb = pm[64 + r1];
        mg = fmaxf(ma, mb);
        sg = psum[r1] * __expf(ma - mg) + psum[64 + r1] * __expf(mb - mg);
        f1 = __expf((wn ? mb : ma) - mg) / sg;
    }
#pragma unroll
    for (int nt = 0; nt < 13; nt++) {
        const int col = wn * 104 + nt * 8 + 2 * (lane & 3);
        *(__half2*)(sm + A_PS0 + r0 * 216 + col) =
            __halves2half2(__float2half_rn(sacc[nt][0] * f0), __float2half_rn(sacc[nt][1] * f0));
        *(__half2*)(sm + A_PS0 + r1 * 216 + col) =
            __halves2half2(__float2half_rn(sacc[nt][2] * f1), __float2half_rn(sacc[nt][3] * f1));
    }
    __syncthreads();

    float vacc[2][4];
#pragma unroll
    for (int i = 0; i < 2; i++)
#pragma unroll
        for (int j = 0; j < 4; j++) vacc[i][j] = 0.f;
    {
        const int ar = wm * 16 + (lane & 15);
        const int ak = (lane >> 4) * 8;
        const int vr = (lane & 15);
        const int vc = wn * 16 + (lane >> 4) * 8;
#pragma unroll
        for (int ks = 0; ks < 13; ks++) {
            unsigned ap[4], bvh[4];
            ldm4(ap[0], ap[1], ap[2], ap[3],
                 sb + (A_PS0 + ar * 216 + ks * 16 + ak) * 2);
            ldm4t(bvh[0], bvh[1], bvh[2], bvh[3],
                  sb + (A_VH0 + (ks * 16 + vr) * 40 + vc) * 2);
            mma16816(vacc[0], ap, bvh[0], bvh[1]);
            mma16816(vacc[1], ap, bvh[2], bvh[3]);
        }
    }

    {
        const int gr = g0 + wm * 16 + (lane >> 2);
        const int dc = wn * 16 + 2 * (lane & 3);
#pragma unroll
        for (int nt = 0; nt < 2; nt++) {
            const int d = dc + nt * 8;
#pragma unroll
            for (int hh = 0; hh < 2; hh++) {
                const int gene = gr + hh * 8;
                if (gene >= G) continue;
                const size_t off = (size_t)(b * G + gene) * 256 + h * 32 + d;
                *(__half2*)(cxh + off) =
                    __halves2half2(__float2half_rn(vacc[nt][hh * 2 + 0]),
                                   __float2half_rn(vacc[nt][hh * 2 + 1]));
            }
        }
    }
}

// ---------------------------------------------------------------------------
// weight convert: fp32 -> fp16, 23 segments
// ---------------------------------------------------------------------------
struct CSeg { const float* src; __half* h; int blk_off; };
struct CTable { CSeg seg[23]; };
__global__ void __launch_bounds__(256) wconv_kernel(CTable t)
{
    const int bt = blockIdx.x;
    int s = 0;
#pragma unroll
    for (int i = 1; i < 23; i++) if (t.seg[i].blk_off <= bt) s = i;
    const CSeg sg = t.seg[s];
    const int idx = (bt - sg.blk_off) * 1024 + threadIdx.x * 4;
    float4 v = *(const float4*)(sg.src + idx);
    *(__half2*)(sg.h + idx)     = __halves2half2(__float2half_rn(v.x), __float2half_rn(v.y));
    *(__half2*)(sg.h + idx + 2) = __halves2half2(__float2half_rn(v.z), __float2half_rn(v.w));
}

// merged prep (+ concat kv bias)
__global__ void __launch_bounds__(256) prep_kernel(
    const float* __restrict__ pf, const int* __restrict__ coords,
    const float* __restrict__ re, const float* __restrict__ ce,
    const float* __restrict__ gq, const float* __restrict__ in_proj_b,
    __half* __restrict__ pfh, __half* __restrict__ peh,
    float* __restrict__ q, __half* __restrict__ qh, float* __restrict__ kvb)
{
    const int bid = blockIdx.x;
    if (bid < 392) {
        int idx = (bid * 256 + threadIdx.x) * 4;
        float4 v = *(const float4*)(pf + idx);
        *(__half2*)(pfh + idx)     = __halves2half2(__float2half_rn(v.x), __float2half_rn(v.y));
        *(__half2*)(pfh + idx + 2) = __halves2half2(__float2half_rn(v.z), __float2half_rn(v.w));
    } else if (bid < 784) {
        int idx = (bid - 392) * 256 + threadIdx.x;
        if (idx < B * P * D) {
            int d = idx & 255;
            int bp = idx >> 8;
            int r = coords[bp * 2 + 0];
            int c = coords[bp * 2 + 1];
            r = min(max(r, 0), 255);
            c = min(max(c, 0), 255);
            float v = (d < 128) ? re[r * 128 + d] : ce[c * 128 + (d - 128)];
            peh[idx] = __float2half_rn(v);
        }
    } else if (bid < 4784) {
        int idx = (bid - 784) * 256 + threadIdx.x;
        float v = gq[idx % (G * D)];
        q[idx] = v;
        qh[idx] = __float2half_rn(v);
    } else {
        int idx = (bid - 4784) * 256 + threadIdx.x;
        if (idx < NL * 2 * D) {
            int l = idx >> 9, j = idx & 511;
            kvb[idx] = in_proj_b[l * 3 * D + D + j];
        }
    }
}

// ---------------------------------------------------------------------------
// LN (+optional fp16 emit)
// ---------------------------------------------------------------------------
__global__ void ln_kernel(const float* __restrict__ x, const float* __restrict__ r,
                          const float* __restrict__ gg, const float* __restrict__ bb,
                          float* __restrict__ y, __half* __restrict__ yh,
                          int rows)
{
    int gid = blockIdx.x * blockDim.x + threadIdx.x;
    int row = gid >> 5;
    int lane = gid & 31;
    if (row >= rows) return;
    const float* xp = x + (size_t)row * 256;
    float4 a = *(const float4*)(xp + lane * 4);
    float4 c = *(const float4*)(xp + 128 + lane * 4);
    if (r) {
        const float* rp = r + (size_t)row * 256;
        float4 ra = *(const float4*)(rp + lane * 4);
        float4 rc = *(const float4*)(rp + 128 + lane * 4);
        a.x += ra.x; a.y += ra.y; a.z += ra.z; a.w += ra.w;
        c.x += rc.x; c.y += rc.y; c.z += rc.z; c.w += rc.w;
    }
    float s = a.x + a.y + a.z + a.w + c.x + c.y + c.z + c.w;
    float q = a.x * a.x + a.y * a.y + a.z * a.z + a.w * a.w
            + c.x * c.x + c.y * c.y + c.z * c.z + c.w * c.w;
#pragma unroll
    for (int o = 16; o; o >>= 1) {
        s += __shfl_xor_sync(0xffffffffu, s, o);
        q += __shfl_xor_sync(0xffffffffu, q, o);
    }
    float mean = s * (1.f / 256.f);
    float var = q * (1.f / 256.f) - mean * mean;
    float rstd = rsqrtf(var + 1e-5f);
    float4 g0 = *(const float4*)(gg + lane * 4);
    float4 g1 = *(const float4*)(gg + 128 + lane * 4);
    float4 b0 = *(const float4*)(bb + lane * 4);
    float4 b1 = *(const float4*)(bb + 128 + lane * 4);
    float4 o0, o1;
    o0.x = (a.x - mean) * rstd * g0.x + b0.x;
    o0.y = (a.y - mean) * rstd * g0.y + b0.y;
    o0.z = (a.z - mean) * rstd * g0.z + b0.z;
    o0.w = (a.w - mean) * rstd * g0.w + b0.w;
    o1.x = (c.x - mean) * rstd * g1.x + b1.x;
    o1.y = (c.y - mean) * rstd * g1.y + b1.y;
    o1.z = (c.z - mean) * rstd * g1.z + b1.z;
    o1.w = (c.w - mean) * rstd * g1.w + b1.w;
    float* yp = y + (size_t)row * 256;
    *(float4*)(yp + lane * 4) = o0;
    *(float4*)(yp + 128 + lane * 4) = o1;
    if (yh) {
        const size_t b0o = (size_t)row * 256 + lane * 4;
        *(__half2*)(yh + b0o)       = __halves2half2(__float2half_rn(o0.x), __float2half_rn(o0.y));
        *(__half2*)(yh + b0o + 2)   = __halves2half2(__float2half_rn(o0.z), __float2half_rn(o0.w));
        *(__half2*)(yh + b0o + 128) = __halves2half2(__float2half_rn(o1.x), __float2half_rn(o1.y));
        *(__half2*)(yh + b0o + 130) = __halves2half2(__float2half_rn(o1.z), __float2half_rn(o1.w));
    }
}

// ---------------------------------------------------------------------------
// head: bp-tiled. grid (G/8, MP/8), block 256.
// ---------------------------------------------------------------------------
__global__ void __launch_bounds__(256) head_kernel(
    const float* __restrict__ qp, const float* __restrict__ pp, float* __restrict__ out)
{
    const int g = blockIdx.x * 8 + (threadIdx.x >> 5);
    const int col = (threadIdx.x & 31) << 2;
    const int bp0 = blockIdx.y * 8;
    float4 qv;
    int curb = -1;
#pragma unroll
    for (int i = 0; i < 8; i++) {
        const int bp = bp0 + i;
        const int b = (bp >= P) ? 1 : 0;
        if (b != curb) {
            qv = *(const float4*)(qp + (size_t)(b * G + g) * HALF + col);
            curb = b;
        }
        float4 pv = *(const float4*)(pp + (size_t)bp * HALF + col);
        float4 o;
        o.x = softplusf(pv.x + qv.x);
        o.y = softplusf(pv.y + qv.y);
        o.z = softplusf(pv.z + qv.z);
        o.w = softplusf(pv.w + qv.w);
        *(float4*)(out + ((size_t)bp * G + g) * HALF + col) = o;
    }
}

// ---------------------------------------------------------------------------
extern "C" void kernel_launch(void* const* d_in, const int* in_sizes, int n_in,
                              void* d_out, int out_size)
{
    (void)in_sizes; (void)n_in; (void)out_size;
    const float* patch_features = (const float*)d_in[0];
    const int*   patch_coords   = (const int*)d_in[1];
    const float* patch_proj_w   = (const float*)d_in[2];
    const float* patch_proj_b   = (const float*)d_in[3];
    const float* patch_ln_g     = (const float*)d_in[4];
    const float* patch_ln_b     = (const float*)d_in[5];
    const float* row_embed      = (const float*)d_in[6];
    const float* col_embed      = (const float*)d_in[7];
    const float* pe_proj_w      = (const float*)d_in[8];
    const float* pe_proj_b      = (const float*)d_in[9];
    const float* gene_queries   = (const float*)d_in[10];
    const float* in_proj_w      = (const float*)d_in[11];
    const float* in_proj_b      = (const float*)d_in[12];
    const float* out_w          = (const float*)d_in[13];
    const float* out_b          = (const float*)d_in[14];
    const float* ff1_w          = (const float*)d_in[15];
    const float* ff1_b          = (const float*)d_in[16];
    const float* ff2_w          = (const float*)d_in[17];
    const float* ff2_b          = (const float*)d_in[18];
    const float* ln1_g          = (const float*)d_in[19];
    const float* ln1_b          = (const float*)d_in[20];
    const float* ln2_g          = (const float*)d_in[21];
    const float* ln2_b          = (const float*)d_in[22];
    const float* head_w1        = (const float*)d_in[23];
    const float* head_b1        = (const float*)d_in[24];
    float* out = (float*)d_out;

    cudaFuncSetAttribute(mma_gemm_kernel<128>, cudaFuncAttributeMaxDynamicSharedMemorySize, MMASM128);
    cudaFuncSetAttribute(mma_gemm_kernel<64>,  cudaFuncAttributeMaxDynamicSharedMemorySize, MMASM64);
    cudaFuncSetAttribute(mma_gemm_dual_kernel, cudaFuncAttributeMaxDynamicSharedMemorySize, MMASM64);
    cudaFuncSetAttribute(attn_mma_kernel,      cudaFuncAttributeMaxDynamicSharedMemorySize, ATTSM);

    float* ws = nullptr;
    cudaGetSymbolAddress((void**)&ws, g_ws);
    __half* hf = nullptr;
    cudaGetSymbolAddress((void**)&hf, g_hf);

    float* patch_emb = ws + OFF_PATCH;
    float* tmp       = ws + OFF_TMP;
    float* q         = ws + OFF_Q;
    float* att       = ws + OFF_ATT;
    float* qproj     = ws + OFF_QP;
    float* pproj     = ws + OFF_PP;
    float* kvb       = ws + OFF_KVB;

    __half* qh  = hf + HF_QH;
    __half* l1h = hf + HF_L1H;
    __half* cxh = hf + HF_CXH;
    __half* fh  = hf + HF_FH;
    __half* qbh = hf + HF_QBH;
    __half* kva = hf + HF_KVA;
    __half* pfh = hf + HF_PFH;
    __half* peh = hf + HF_PEH;
    __half* pch = hf + HF_PCH;

    // ---- one-time weight convert ----
    CTable ct;
    int total_blk;
    {
        int seg = 0, boff = 0;
        auto add = [&](const float* src, size_t ho, int count) {
            ct.seg[seg] = { src, hf + ho, boff };
            boff += count / 1024;
            seg++;
        };
        for (int l = 0; l < NL; l++)
            add(in_proj_w + (size_t)l * 3 * D * D, HF_WQ + (size_t)l * D * D, D * D);
        for (int l = 0; l < NL; l++)
            add(out_w + (size_t)l * D * D, HF_WO + (size_t)l * D * D, D * D);
        for (int l = 0; l < NL; l++)
            add(ff1_w + (size_t)l * 4 * D * D, HF_F1 + (size_t)l * 4 * D * D, 4 * D * D);
        for (int l = 0; l < NL; l++)
            add(ff2_w + (size_t)l * 4 * D * D, HF_F2 + (size_t)l * 4 * D * D, 4 * D * D);
        add(head_w1, HF_HD, HALF * D);
        add(patch_proj_w, HF_WP, D * FD);
        add(pe_proj_w, HF_WE, D * D);
        for (int l = 0; l < NL; l++)
            add(in_proj_w + (size_t)l * 3 * D * D + D * D, HF_WK + (size_t)l * 2 * D * D, 2 * D * D);
        total_blk = boff;
    }
    wconv_kernel<<<total_blk, 256>>>(ct);
    prep_kernel<<<4792, 256>>>(patch_features, patch_coords, row_embed, col_embed,
                               gene_queries, in_proj_b, pfh, peh, q, qh, kvb);

    const int MT128 = (MQ + 127) / 128;   // 32
    const int MTP   = (MP + 63) / 64;     // 7

    auto GA = [](const __half* Ah, const __half* Wh,
                 const float* bias, const float* R,
                 float* Cf, __half* Ch,
                 int M, int N, int K, int act) {
        GArgs g;
        g.Ah = Ah; g.Wh = Wh; g.bias = bias; g.R = R;
        g.Cf = Cf; g.Ch = Ch;
        g.M = M; g.N = N; g.K = K; g.act = act; g.ntx = N / 64;
        return g;
    };

    // ---- Stage A ----
    mma_gemm_kernel<64><<<dim3(D / 64, MTP), 256, MMASM64>>>(
        GA(pfh, hf + HF_WP, patch_proj_b, nullptr, tmp, nullptr, MP, D, FD, 0));
    ln_kernel<<<(MP + 7) / 8, 256>>>(tmp, nullptr, patch_ln_g, patch_ln_b, patch_emb,
                                     nullptr, MP);
    mma_gemm_kernel<64><<<dim3(D / 64, MTP), 256, MMASM64>>>(
        GA(peh, hf + HF_WE, pe_proj_b, patch_emb, nullptr, pch, MP, D, D, 0));

    // ---- KV for all layers + patch-side head projection ----
    {
        GArgs gkva = GA(pch, hf + HF_WK, kvb, nullptr, nullptr, kva, MP, NL * 2 * D, D, 0);
        GArgs gpp  = GA(pch, hf + HF_HD, nullptr, nullptr, pproj, nullptr, MP, HALF, D, 0);
        const int split = gkva.ntx * MTP;
        const int tot   = split + gpp.ntx * MTP;
        mma_gemm_dual_kernel<<<tot, 256, MMASM64>>>(gkva, gpp, split);
    }

    // ---- Stage B (all M=4000 GEMMs at BM=128) ----
    for (int l = 0; l < NL; l++) {
        const float* bq = in_proj_b + (size_t)l * 3 * D;
        mma_gemm_kernel<128><<<dim3(D / 64, MT128), 256, MMASM128>>>(
            GA(qh, hf + HF_WQ + (size_t)l * D * D, bq, nullptr,
               nullptr, qbh, MQ, D, D, 0));
        attn_mma_kernel<<<dim3(B * H, 32), 256, ATTSM>>>(
            qbh, kva + l * 2 * D, cxh, NL * 2 * D);
        mma_gemm_kernel<128><<<dim3(D / 64, MT128), 256, MMASM128>>>(
            GA(cxh, hf + HF_WO + (size_t)l * D * D, out_b + (size_t)l * D, q,
               att, nullptr, MQ, D, D, 0));
        ln_kernel<<<(MQ + 7) / 8, 256>>>(att, nullptr, ln1_g + (size_t)l * D, ln1_b + (size_t)l * D,
                                         q, l1h, MQ);
        mma_gemm_kernel<128><<<dim3(4 * D / 64, MT128), 256, MMASM128>>>(
            GA(l1h, hf + HF_F1 + (size_t)l * 4 * D * D, ff1_b + (size_t)l * 4 * D, nullptr,
               nullptr, fh, MQ, 4 * D, D, 1));
        mma_gemm_kernel<128><<<dim3(D / 64, MT128), 256, MMASM128>>>(
            GA(fh, hf + HF_F2 + (size_t)l * 4 * D * D, ff2_b + (size_t)l * D, q,
               att, nullptr, MQ, D, 4 * D, 0));
        ln_kernel<<<(MQ + 7) / 8, 256>>>(att, nullptr, ln2_g + (size_t)l * D, ln2_b + (size_t)l * D,
                                         q, qh, MQ);
    }

    // ---- Stage C ----
    mma_gemm_kernel<128><<<dim3(HALF / 64, MT128), 256, MMASM128>>>(
        GA(qh, hf + HF_HD, head_b1, nullptr, qproj, nullptr, MQ, HALF, D, 0));
    head_kernel<<<dim3(G / 8, MP / 8), 256>>>(qproj, pproj, out);
}

// round 17
// speedup vs baseline: 2.1937x; 1.0327x over previous
#include <cuda_runtime.h>
#include <cuda_fp16.h>
#include <cstddef>
#include <cstdint>
#include <math.h>

// ---------------------------------------------------------------------------
// SpatialTranscriptomicsDecoder — GB300 sm_103a. Round 17.
// R16 + 6-stage cp.async pipeline, merged wconv+prep, streaming head stores.
// ---------------------------------------------------------------------------

static constexpr int B = 2, P = 196, FD = 1024, G = 2000, D = 256, H = 8, NL = 4, HALF = 128;
static constexpr float ATT_SCALE = 0.17677669529663687f;
static constexpr int MQ = B * G;   // 4000
static constexpr int MP = B * P;   // 392

// ---------------- fp32 workspace ----------------
static constexpr size_t OFF_PATCH = 0;
static constexpr size_t OFF_TMP   = OFF_PATCH + (size_t)MP * D;
static constexpr size_t OFF_Q     = OFF_TMP   + (size_t)MP * D;
static constexpr size_t OFF_ATT   = OFF_Q     + (size_t)MQ * D;
static constexpr size_t OFF_QP    = OFF_ATT   + (size_t)MQ * D;
static constexpr size_t OFF_PP    = OFF_QP    + (size_t)MQ * HALF;
static constexpr size_t OFF_KVB   = OFF_PP    + (size_t)MP * HALF;
static constexpr size_t WS_TOTAL  = OFF_KVB   + (size_t)NL * 2 * D;
__device__ float g_ws[WS_TOTAL];

// ---------------- fp16 workspace ----------------
static constexpr size_t BQ  = (size_t)MQ * D;
static constexpr size_t HF_QH  = 0;
static constexpr size_t HF_L1H = HF_QH + BQ;
static constexpr size_t HF_CXH = HF_L1H + BQ;
static constexpr size_t HF_FH  = HF_CXH + BQ;
static constexpr size_t HF_QBH = HF_FH + (size_t)MQ * 4 * D;
static constexpr size_t HF_KVA = HF_QBH + BQ;
static constexpr size_t HF_PFH = HF_KVA + (size_t)MP * NL * 2 * D;
static constexpr size_t HF_PEH = HF_PFH + (size_t)MP * FD;
static constexpr size_t HF_PCH = HF_PEH + (size_t)MP * D;
static constexpr size_t HF_WQ  = HF_PCH + (size_t)MP * D;
static constexpr size_t HF_WO  = HF_WQ  + (size_t)NL * D * D;
static constexpr size_t HF_F1  = HF_WO  + (size_t)NL * D * D;
static constexpr size_t HF_F2  = HF_F1  + (size_t)NL * 4 * D * D;
static constexpr size_t HF_HD  = HF_F2  + (size_t)NL * 4 * D * D;
static constexpr size_t HF_WP  = HF_HD  + (size_t)HALF * D;
static constexpr size_t HF_WE  = HF_WP  + (size_t)D * FD;
static constexpr size_t HF_WK  = HF_WE  + (size_t)D * D;
static constexpr size_t HF_TOTAL = HF_WK + (size_t)NL * 2 * D * D;
__device__ __half g_hf[HF_TOTAL];

// ---------------- helpers ----------------
__device__ __forceinline__ float geluf(float x) {
    return 0.5f * x * (1.0f + erff(x * 0.7071067811865476f));
}
__device__ __forceinline__ float softplusf(float x) {
    return fmaxf(x, 0.0f) + __logf(1.0f + __expf(-fabsf(x)));
}
__device__ __forceinline__ void cpa16(unsigned int dst, const void* src, bool ok) {
    asm volatile("cp.async.ca.shared.global [%0], [%1], 16, %2;"
                 :: "r"(dst), "l"(src), "r"(ok ? 16 : 0) : "memory");
}
__device__ __forceinline__ void cpa_commit() {
    asm volatile("cp.async.commit_group;" ::: "memory");
}
template<int Ng> __device__ __forceinline__ void cpa_waitg() {
    asm volatile("cp.async.wait_group %0;" :: "n"(Ng) : "memory");
}
__device__ __forceinline__ void ldm4(unsigned& r0, unsigned& r1, unsigned& r2, unsigned& r3,
                                     unsigned addr) {
    asm volatile("ldmatrix.sync.aligned.m8n8.x4.shared.b16 {%0,%1,%2,%3}, [%4];"
                 : "=r"(r0), "=r"(r1), "=r"(r2), "=r"(r3) : "r"(addr));
}
__device__ __forceinline__ void ldm4t(unsigned& r0, unsigned& r1, unsigned& r2, unsigned& r3,
                                      unsigned addr) {
    asm volatile("ldmatrix.sync.aligned.m8n8.x4.trans.shared.b16 {%0,%1,%2,%3}, [%4];"
                 : "=r"(r0), "=r"(r1), "=r"(r2), "=r"(r3) : "r"(addr));
}
__device__ __forceinline__ void mma16816(float* d, const unsigned* a, unsigned b0, unsigned b1) {
    asm volatile(
        "mma.sync.aligned.m16n8k16.row.col.f32.f16.f16.f32 "
        "{%0,%1,%2,%3}, {%4,%5,%6,%7}, {%8,%9}, {%0,%1,%2,%3};"
        : "+f"(d[0]), "+f"(d[1]), "+f"(d[2]), "+f"(d[3])
        : "r"(a[0]), "r"(a[1]), "r"(a[2]), "r"(a[3]), "r"(b0), "r"(b1));
}

// ---------------------------------------------------------------------------
// GEMM: C[M,N] = act( A @ W^T + bias + R ); fp16 in, fp32 acc.
// 6-stage cp.async pipeline, k-chunk 32, row stride 40 halfs.
// ---------------------------------------------------------------------------
static constexpr int NST = 6;

struct GArgs {
    const __half* Ah; const __half* Wh;
    const float* bias; const float* R;
    float* Cf; __half* Ch;
    int M, N, K, act, ntx;
};

template<int BM>
__device__ __forceinline__ void mma_gemm_impl(const GArgs& g, int bx, int by)
{
    constexpr int STR = 40;
    constexpr int szA = BM * STR * 2;
    constexpr int szW = 64 * STR * 2;
    constexpr int STG = szA + szW;
    constexpr int MT  = 2;
    constexpr int WMASK  = (BM == 128) ? 3 : 1;
    constexpr int WSHIFT = (BM == 128) ? 2 : 1;
    constexpr int NT8 = (BM == 128) ? 4 : 2;
    constexpr int NP  = NT8 / 2;

    extern __shared__ char smem[];
    const unsigned sb = (unsigned)__cvta_generic_to_shared(smem);

    const int tid = threadIdx.x;
    const int lane = tid & 31, wid = tid >> 5;
    const int wm = wid & WMASK, wn = wid >> WSHIFT;
    const int bm = by * BM;
    const int bn = bx * 64;
    const int NC = g.K >> 5;
    const int M = g.M, N = g.N, K = g.K;

    unsigned offA = 0, offW = 0;
    const __half* srcA = nullptr;
    const __half* srcW = nullptr;
    bool aok = false, doA = false, doW = false;
    if (BM == 128) {
        const int rowA = tid >> 1, segA = tid & 1;
        doA = true;
        aok = (bm + rowA) < M;
        offA = (unsigned)((rowA * STR + segA * 16) * 2);
        srcA = g.Ah + (size_t)(bm + rowA) * K + segA * 16;
        const int rowW = tid >> 2, segW = tid & 3;
        doW = true;
        offW = (unsigned)(szA + (rowW * STR + segW * 8) * 2);
        srcW = g.Wh + (size_t)(bn + rowW) * K + segW * 8;
    } else {
        if (tid < 128) {
            const int rowA = tid >> 1, segA = tid & 1;
            doA = true;
            aok = (bm + rowA) < M;
            offA = (unsigned)((rowA * STR + segA * 16) * 2);
            srcA = g.Ah + (size_t)(bm + rowA) * K + segA * 16;
        } else {
            const int rowW = (tid - 128) >> 1, segW = tid & 1;
            doW = true;
            offW = (unsigned)(szA + (rowW * STR + segW * 16) * 2);
            srcW = g.Wh + (size_t)(bn + rowW) * K + segW * 16;
        }
    }

    auto loadChunk = [&](int kc, int s) {
        const int o = kc << 5;
        const unsigned base = sb + s * STG;
        if (doA) {
            cpa16(base + offA, srcA + o, aok);
            cpa16(base + offA + 16, srcA + o + 8, aok);
        }
        if (doW) {
            cpa16(base + offW, srcW + o, true);
            if (BM == 64) cpa16(base + offW + 16, srcW + o + 8, true);
        }
        cpa_commit();
    };

    unsigned aoffH[MT], boffH[NP];
    {
        const int ar = wm * 32 + (lane & 15);
        const int ak = (lane >> 4) * 8;
        const int br = wn * (NT8 * 8) + (lane & 7) + ((lane >> 4) << 3);
        const int bk = ((lane >> 3) & 1) * 8;
#pragma unroll
        for (int t = 0; t < MT; t++) aoffH[t] = (unsigned)(((ar + t * 16) * STR + ak) * 2);
#pragma unroll
        for (int p = 0; p < NP; p++) boffH[p] = (unsigned)(szA + ((br + p * 16) * STR + bk) * 2);
    }

    // prologue: NST-1 stages (clamped to NC)
#pragma unroll
    for (int s = 0; s < NST - 1; s++)
        if (s < NC) loadChunk(s, s);
        else cpa_commit();

    float acc[MT][NT8][4];
#pragma unroll
    for (int i = 0; i < MT; i++)
#pragma unroll
        for (int j = 0; j < NT8; j++)
#pragma unroll
            for (int k = 0; k < 4; k++) acc[i][j][k] = 0.f;

    int s = 0, ns = NST - 1;
    for (int kc = 0; kc < NC; kc++) {
        cpa_waitg<NST - 2>();
        __syncthreads();
        const int nk = kc + NST - 1;
        if (nk < NC) loadChunk(nk, ns);
        else cpa_commit();
        if (++ns == NST) ns = 0;

        const unsigned stg = sb + s * STG;
        if (++s == NST) s = 0;
#pragma unroll
        for (int ks = 0; ks < 2; ks++) {
            const unsigned ko = ks * 32;
            unsigned ah[MT][4], bh[NP][4];
#pragma unroll
            for (int t = 0; t < MT; t++)
                ldm4(ah[t][0], ah[t][1], ah[t][2], ah[t][3], stg + aoffH[t] + ko);
#pragma unroll
            for (int p = 0; p < NP; p++)
                ldm4(bh[p][0], bh[p][1], bh[p][2], bh[p][3], stg + boffH[p] + ko);
#pragma unroll
            for (int mt = 0; mt < MT; mt++) {
#pragma unroll
                for (int nt = 0; nt < NT8; nt++) {
                    const int p = nt >> 1, nh = (nt & 1) << 1;
                    mma16816(acc[mt][nt], ah[mt], bh[p][nh], bh[p][nh + 1]);
                }
            }
        }
    }

    const int rowb = bm + wm * 32 + (lane >> 2);
    const int colb = bn + wn * (NT8 * 8) + 2 * (lane & 3);
#pragma unroll
    for (int mt = 0; mt < MT; mt++) {
#pragma unroll
        for (int nt = 0; nt < NT8; nt++) {
            const int col = colb + nt * 8;
            float2 b2 = make_float2(0.f, 0.f);
            if (g.bias) b2 = *(const float2*)(g.bias + col);
#pragma unroll
            for (int hh = 0; hh < 2; hh++) {
                const int row = rowb + mt * 16 + hh * 8;
                if (row >= M) continue;
                float v0 = acc[mt][nt][hh * 2 + 0] + b2.x;
                float v1 = acc[mt][nt][hh * 2 + 1] + b2.y;
                if (g.R) {
                    float2 r2 = *(const float2*)(g.R + (size_t)row * N + col);
                    v0 += r2.x; v1 += r2.y;
                }
                if (g.act == 1) { v0 = geluf(v0); v1 = geluf(v1); }
                if (g.Cf) *(float2*)(g.Cf + (size_t)row * N + col) = make_float2(v0, v1);
                if (g.Ch)
                    *(__half2*)(g.Ch + (size_t)row * N + col) =
                        __halves2half2(__float2half_rn(v0), __float2half_rn(v1));
            }
        }
    }
}

template<int BM>
__global__ void __launch_bounds__(256) mma_gemm_kernel(GArgs g)
{
    mma_gemm_impl<BM>(g, blockIdx.x, blockIdx.y);
}

__global__ void __launch_bounds__(256) mma_gemm_dual_kernel(GArgs g0, GArgs g1, int split)
{
    if ((int)blockIdx.x < split) {
        const int local = blockIdx.x;
        mma_gemm_impl<64>(g0, local % g0.ntx, local / g0.ntx);
    } else {
        const int local = blockIdx.x - split;
        mma_gemm_impl<64>(g1, local % g1.ntx, local / g1.ntx);
    }
}

static constexpr int MMASM128 = NST * (128 * 40 * 2 + 64 * 40 * 2);  // 92160
static constexpr int MMASM64  = NST * (64 * 40 * 2 + 64 * 40 * 2);   // 61440

// ---------------------------------------------------------------------------
// Fused tensor-core attention (single-term). grid (B*H, 32), 256 thr.
// ---------------------------------------------------------------------------
static constexpr int A_QH0 = 0;
static constexpr int A_KH0 = 2560;
static constexpr int A_VH0 = A_KH0 + 8960;
static constexpr int A_PS0 = A_VH0 + 8960;
static constexpr int A_PARTB = (A_PS0 + 13824) * 2;
static constexpr int ATTSM = A_PARTB + 2048;

__global__ void __launch_bounds__(256) attn_mma_kernel(
    const __half* __restrict__ Qh_g, const __half* __restrict__ KVh,
    __half* __restrict__ cxh, int kvstride)
{
    extern __shared__ char smem[];
    __half* sm = (__half*)smem;
    float* pm   = (float*)(smem + A_PARTB);
    float* psum = pm + 128;
    const unsigned sb = (unsigned)__cvta_generic_to_shared(smem);

    const int bh = blockIdx.x;
    const int b = bh >> 3, h = bh & 7;
    const int g0 = blockIdx.y * 64;
    const int tid = threadIdx.x;
    const int lane = tid & 31, wid = tid >> 5;
    const int wm = wid & 3, wn = wid >> 2;

    if (tid < 128) {
        const int row = tid >> 1;
        const int sp = (tid & 1) * 16;
        const bool ok = (g0 + row) < G;
        const __half* src = Qh_g + ((size_t)(b * G + g0 + row) * 256 + h * 32 + sp);
        unsigned dst = sb + (A_QH0 + row * 40 + sp) * 2;
        cpa16(dst, src, ok);
        cpa16(dst + 16, src + 8, ok);
    }
    if (tid < 196) {
        const size_t rb = (size_t)(b * P + tid) * kvstride + h * 32;
        const __half* ksrc = KVh + rb;
        unsigned kdst = sb + (A_KH0 + tid * 40) * 2;
        cpa16(kdst,      ksrc,      true);
        cpa16(kdst + 16, ksrc + 8,  true);
        cpa16(kdst + 32, ksrc + 16, true);
        cpa16(kdst + 48, ksrc + 24, true);
        const __half* vh = KVh + rb + 256;
        unsigned vhd = sb + (A_VH0 + tid * 40) * 2;
        cpa16(vhd,      vh,      true);
        cpa16(vhd + 16, vh + 8,  true);
        cpa16(vhd + 32, vh + 16, true);
        cpa16(vhd + 48, vh + 24, true);
    } else if (tid < 224) {
        uint4 z = make_uint4(0, 0, 0, 0);
#pragma unroll
        for (int i = 0; i < 5; i++) {
            *(uint4*)(sm + A_KH0 + tid * 40 + i * 8) = z;
            *(uint4*)(sm + A_VH0 + tid * 40 + i * 8) = z;
        }
    }
    cpa_commit();
    cpa_waitg<0>();
    __syncthreads();

    unsigned aq[2][4];
    {
        const int ar = wm * 16 + (lane & 15);
        const int ak = (lane >> 4) * 8;
#pragma unroll
        for (int ks = 0; ks < 2; ks++)
            ldm4(aq[ks][0], aq[ks][1], aq[ks][2], aq[ks][3],
                 sb + (A_QH0 + ar * 40 + ks * 16 + ak) * 2);
    }
    float sacc[13][4];
#pragma unroll
    for (int i = 0; i < 13; i++)
#pragma unroll
        for (int j = 0; j < 4; j++) sacc[i][j] = 0.f;

    {
        const int brr = wn * 104 + (lane & 7) + ((lane >> 4) << 3);
        const int bko = ((lane >> 3) & 1) * 8;
#pragma unroll
        for (int gph = 0; gph < 7; gph++) {
            unsigned bk0[4], bk1[4];
            ldm4(bk0[0], bk0[1], bk0[2], bk0[3],
                 sb + (A_KH0 + (brr + gph * 16) * 40 + bko) * 2);
            ldm4(bk1[0], bk1[1], bk1[2], bk1[3],
                 sb + (A_KH0 + (brr + gph * 16) * 40 + 16 + bko) * 2);
#pragma unroll
            for (int hf = 0; hf < 2; hf++) {
                const int nt = gph * 2 + hf;
                if (nt >= 13) break;
                mma16816(sacc[nt], aq[0], bk0[hf * 2], bk0[hf * 2 + 1]);
                mma16816(sacc[nt], aq[1], bk1[hf * 2], bk1[hf * 2 + 1]);
            }
        }
    }

#pragma unroll
    for (int nt = 0; nt < 13; nt++)
#pragma unroll
        for (int j = 0; j < 4; j++) sacc[nt][j] *= ATT_SCALE;

    float mx0 = -1e30f, mx1 = -1e30f;
#pragma unroll
    for (int nt = 0; nt < 13; nt++) {
        mx0 = fmaxf(mx0, fmaxf(sacc[nt][0], sacc[nt][1]));
        mx1 = fmaxf(mx1, fmaxf(sacc[nt][2], sacc[nt][3]));
    }
    mx0 = fmaxf(mx0, __shfl_xor_sync(0xffffffffu, mx0, 1));
    mx0 = fmaxf(mx0, __shfl_xor_sync(0xffffffffu, mx0, 2));
    mx1 = fmaxf(mx1, __shfl_xor_sync(0xffffffffu, mx1, 1));
    mx1 = fmaxf(mx1, __shfl_xor_sync(0xffffffffu, mx1, 2));

    float s0 = 0.f, s1 = 0.f;
#pragma unroll
    for (int nt = 0; nt < 13; nt++) {
        const int col = wn * 104 + nt * 8 + 2 * (lane & 3);
        float e0 = (col < 196)     ? __expf(sacc[nt][0] - mx0) : 0.f;
        float e1 = (col + 1 < 196) ? __expf(sacc[nt][1] - mx0) : 0.f;
        float e2 = (col < 196)     ? __expf(sacc[nt][2] - mx1) : 0.f;
        float e3 = (col + 1 < 196) ? __expf(sacc[nt][3] - mx1) : 0.f;
        sacc[nt][0] = e0; sacc[nt][1] = e1; sacc[nt][2] = e2; sacc[nt][3] = e3;
        s0 += e0 + e1; s1 += e2 + e3;
    }
    s0 += __shfl_xor_sync(0xffffffffu, s0, 1);
    s0 += __shfl_xor_sync(0xffffffffu, s0, 2);
    s1 += __shfl_xor_sync(0xffffffffu, s1, 1);
    s1 += __shfl_xor_sync(0xffffffffu, s1, 2);

    const int r0 = wm * 16 + (lane >> 2), r1 = r0 + 8;
    if ((lane & 3) == 0) {
        pm[wn * 64 + r0] = mx0;  pm[wn * 64 + r1] = mx1;
        psum[wn * 64 + r0] = s0; psum[wn * 64 + r1] = s1;
    }
    __syncthreads();

    float f0, f1;
    {
        float ma = pm[r0], mb = pm[64 + r0];
        float mg = fmaxf(ma, mb);
        float sg = psum[r0] * __expf(ma - mg) + psum[64 + r0] * __expf(mb - mg);
        f0 = __expf((wn ? mb : ma) - mg) / sg;
        ma = pm[r1]; mb = pm[64 + r1];
        mg = fmaxf(ma, mb);
        sg = psum[r1] * __expf(ma - mg) + psum[64 + r1] * __expf(mb - mg);
        f1 = __expf((wn ? mb : ma) - mg) / sg;
    }
#pragma unroll
    for (int nt = 0; nt < 13; nt++) {
        const int col = wn * 104 + nt * 8 + 2 * (lane & 3);
        *(__half2*)(sm + A_PS0 + r0 * 216 + col) =
            __halves2half2(__float2half_rn(sacc[nt][0] * f0), __float2half_rn(sacc[nt][1] * f0));
        *(__half2*)(sm + A_PS0 + r1 * 216 + col) =
            __halves2half2(__float2half_rn(sacc[nt][2] * f1), __float2half_rn(sacc[nt][3] * f1));
    }
    __syncthreads();

    float vacc[2][4];
#pragma unroll
    for (int i = 0; i < 2; i++)
#pragma unroll
        for (int j = 0; j < 4; j++) vacc[i][j] = 0.f;
    {
        const int ar = wm * 16 + (lane & 15);
        const int ak = (lane >> 4) * 8;
        const int vr = (lane & 15);
        const int vc = wn * 16 + (lane >> 4) * 8;
#pragma unroll
        for (int ks = 0; ks < 13; ks++) {
            unsigned ap[4], bvh[4];
            ldm4(ap[0], ap[1], ap[2], ap[3],
                 sb + (A_PS0 + ar * 216 + ks * 16 + ak) * 2);
            ldm4t(bvh[0], bvh[1], bvh[2], bvh[3],
                  sb + (A_VH0 + (ks * 16 + vr) * 40 + vc) * 2);
            mma16816(vacc[0], ap, bvh[0], bvh[1]);
            mma16816(vacc[1], ap, bvh[2], bvh[3]);
        }
    }

    {
        const int gr = g0 + wm * 16 + (lane >> 2);
        const int dc = wn * 16 + 2 * (lane & 3);
#pragma unroll
        for (int nt = 0; nt < 2; nt++) {
            const int d = dc + nt * 8;
#pragma unroll
            for (int hh = 0; hh < 2; hh++) {
                const int gene = gr + hh * 8;
                if (gene >= G) continue;
                const size_t off = (size_t)(b * G + gene) * 256 + h * 32 + d;
                *(__half2*)(cxh + off) =
                    __halves2half2(__float2half_rn(vacc[nt][hh * 2 + 0]),
                                   __float2half_rn(vacc[nt][hh * 2 + 1]));
            }
        }
    }
}

// ---------------------------------------------------------------------------
// merged wconv (fp32->fp16 weights, 23 segments) + prep, by block range
// ---------------------------------------------------------------------------
struct CSeg { const float* src; __half* h; int blk_off; };
struct CTable { CSeg seg[23]; };

__global__ void __launch_bounds__(256) wprep_kernel(
    CTable t, int wblk,
    const float* __restrict__ pf, const int* __restrict__ coords,
    const float* __restrict__ re, const float* __restrict__ ce,
    const float* __restrict__ gq, const float* __restrict__ in_proj_b,
    __half* __restrict__ pfh, __half* __restrict__ peh,
    float* __restrict__ q, __half* __restrict__ qh, float* __restrict__ kvb)
{
    int bid = blockIdx.x;
    if (bid < wblk) {
        int s = 0;
#pragma unroll
        for (int i = 1; i < 23; i++) if (t.seg[i].blk_off <= bid) s = i;
        const CSeg sg = t.seg[s];
        const int idx = (bid - sg.blk_off) * 1024 + threadIdx.x * 4;
        float4 v = *(const float4*)(sg.src + idx);
        *(__half2*)(sg.h + idx)     = __halves2half2(__float2half_rn(v.x), __float2half_rn(v.y));
        *(__half2*)(sg.h + idx + 2) = __halves2half2(__float2half_rn(v.z), __float2half_rn(v.w));
        return;
    }
    bid -= wblk;
    if (bid < 392) {
        int idx = (bid * 256 + threadIdx.x) * 4;
        float4 v = *(const float4*)(pf + idx);
        *(__half2*)(pfh + idx)     = __halves2half2(__float2half_rn(v.x), __float2half_rn(v.y));
        *(__half2*)(pfh + idx + 2) = __halves2half2(__float2half_rn(v.z), __float2half_rn(v.w));
    } else if (bid < 784) {
        int idx = (bid - 392) * 256 + threadIdx.x;
        if (idx < B * P * D) {
            int d = idx & 255;
            int bp = idx >> 8;
            int r = coords[bp * 2 + 0];
            int c = coords[bp * 2 + 1];
            r = min(max(r, 0), 255);
            c = min(max(c, 0), 255);
            float v = (d < 128) ? re[r * 128 + d] : ce[c * 128 + (d - 128)];
            peh[idx] = __float2half_rn(v);
        }
    } else if (bid < 4784) {
        int idx = (bid - 784) * 256 + threadIdx.x;
        float v = gq[idx % (G * D)];
        q[idx] = v;
        qh[idx] = __float2half_rn(v);
    } else {
        int idx = (bid - 4784) * 256 + threadIdx.x;
        if (idx < NL * 2 * D) {
            int l = idx >> 9, j = idx & 511;
            kvb[idx] = in_proj_b[l * 3 * D + D + j];
        }
    }
}

// ---------------------------------------------------------------------------
// LN (+optional fp16 emit)
// ---------------------------------------------------------------------------
__global__ void ln_kernel(const float* __restrict__ x, const float* __restrict__ r,
                          const float* __restrict__ gg, const float* __restrict__ bb,
                          float* __restrict__ y, __half* __restrict__ yh,
                          int rows)
{
    int gid = blockIdx.x * blockDim.x + threadIdx.x;
    int row = gid >> 5;
    int lane = gid & 31;
    if (row >= rows) return;
    const float* xp = x + (size_t)row * 256;
    float4 a = *(const float4*)(xp + lane * 4);
    float4 c = *(const float4*)(xp + 128 + lane * 4);
    if (r) {
        const float* rp = r + (size_t)row * 256;
        float4 ra = *(const float4*)(rp + lane * 4);
        float4 rc = *(const float4*)(rp + 128 + lane * 4);
        a.x += ra.x; a.y += ra.y; a.z += ra.z; a.w += ra.w;
        c.x += rc.x; c.y += rc.y; c.z += rc.z; c.w += rc.w;
    }
    float s = a.x + a.y + a.z + a.w + c.x + c.y + c.z + c.w;
    float q = a.x * a.x + a.y * a.y + a.z * a.z + a.w * a.w
            + c.x * c.x + c.y * c.y + c.z * c.z + c.w * c.w;
#pragma unroll
    for (int o = 16; o; o >>= 1) {
        s += __shfl_xor_sync(0xffffffffu, s, o);
        q += __shfl_xor_sync(0xffffffffu, q, o);
    }
    float mean = s * (1.f / 256.f);
    float var = q * (1.f / 256.f) - mean * mean;
    float rstd = rsqrtf(var + 1e-5f);
    float4 g0 = *(const float4*)(gg + lane * 4);
    float4 g1 = *(const float4*)(gg + 128 + lane * 4);
    float4 b0 = *(const float4*)(bb + lane * 4);
    float4 b1 = *(const float4*)(bb + 128 + lane * 4);
    float4 o0, o1;
    o0.x = (a.x - mean) * rstd * g0.x + b0.x;
    o0.y = (a.y - mean) * rstd * g0.y + b0.y;
    o0.z = (a.z - mean) * rstd * g0.z + b0.z;
    o0.w = (a.w - mean) * rstd * g0.w + b0.w;
    o1.x = (c.x - mean) * rstd * g1.x + b1.x;
    o1.y = (c.y - mean) * rstd * g1.y + b1.y;
    o1.z = (c.z - mean) * rstd * g1.z + b1.z;
    o1.w = (c.w - mean) * rstd * g1.w + b1.w;
    float* yp = y + (size_t)row * 256;
    *(float4*)(yp + lane * 4) = o0;
    *(float4*)(yp + 128 + lane * 4) = o1;
    if (yh) {
        const size_t b0o = (size_t)row * 256 + lane * 4;
        *(__half2*)(yh + b0o)       = __halves2half2(__float2half_rn(o0.x), __float2half_rn(o0.y));
        *(__half2*)(yh + b0o + 2)   = __halves2half2(__float2half_rn(o0.z), __float2half_rn(o0.w));
        *(__half2*)(yh + b0o + 128) = __halves2half2(__float2half_rn(o1.x), __float2half_rn(o1.y));
        *(__half2*)(yh + b0o + 130) = __halves2half2(__float2half_rn(o1.z), __float2half_rn(o1.w));
    }
}

// ---------------------------------------------------------------------------
// head: bp-tiled, streaming stores. grid (G/8, MP/8), block 256.
// ---------------------------------------------------------------------------
__global__ void __launch_bounds__(256) head_kernel(
    const float* __restrict__ qp, const float* __restrict__ pp, float* __restrict__ out)
{
    const int g = blockIdx.x * 8 + (threadIdx.x >> 5);
    const int col = (threadIdx.x & 31) << 2;
    const int bp0 = blockIdx.y * 8;
    float4 qv;
    int curb = -1;
#pragma unroll
    for (int i = 0; i < 8; i++) {
        const int bp = bp0 + i;
        const int b = (bp >= P) ? 1 : 0;
        if (b != curb) {
            qv = *(const float4*)(qp + (size_t)(b * G + g) * HALF + col);
            curb = b;
        }
        float4 pv = *(const float4*)(pp + (size_t)bp * HALF + col);
        float4 o;
        o.x = softplusf(pv.x + qv.x);
        o.y = softplusf(pv.y + qv.y);
        o.z = softplusf(pv.z + qv.z);
        o.w = softplusf(pv.w + qv.w);
        __stcs((float4*)(out + ((size_t)bp * G + g) * HALF + col), o);
    }
}

// ---------------------------------------------------------------------------
extern "C" void kernel_launch(void* const* d_in, const int* in_sizes, int n_in,
                              void* d_out, int out_size)
{
    (void)in_sizes; (void)n_in; (void)out_size;
    const float* patch_features = (const float*)d_in[0];
    const int*   patch_coords   = (const int*)d_in[1];
    const float* patch_proj_w   = (const float*)d_in[2];
    const float* patch_proj_b   = (const float*)d_in[3];
    const float* patch_ln_g     = (const float*)d_in[4];
    const float* patch_ln_b     = (const float*)d_in[5];
    const float* row_embed      = (const float*)d_in[6];
    const float* col_embed      = (const float*)d_in[7];
    const float* pe_proj_w      = (const float*)d_in[8];
    const float* pe_proj_b      = (const float*)d_in[9];
    const float* gene_queries   = (const float*)d_in[10];
    const float* in_proj_w      = (const float*)d_in[11];
    const float* in_proj_b      = (const float*)d_in[12];
    const float* out_w          = (const float*)d_in[13];
    const float* out_b          = (const float*)d_in[14];
    const float* ff1_w          = (const float*)d_in[15];
    const float* ff1_b          = (const float*)d_in[16];
    const float* ff2_w          = (const float*)d_in[17];
    const float* ff2_b          = (const float*)d_in[18];
    const float* ln1_g          = (const float*)d_in[19];
    const float* ln1_b          = (const float*)d_in[20];
    const float* ln2_g          = (const float*)d_in[21];
    const float* ln2_b          = (const float*)d_in[22];
    const float* head_w1        = (const float*)d_in[23];
    const float* head_b1        = (const float*)d_in[24];
    float* out = (float*)d_out;

    cudaFuncSetAttribute(mma_gemm_kernel<128>, cudaFuncAttributeMaxDynamicSharedMemorySize, MMASM128);
    cudaFuncSetAttribute(mma_gemm_kernel<64>,  cudaFuncAttributeMaxDynamicSharedMemorySize, MMASM64);
    cudaFuncSetAttribute(mma_gemm_dual_kernel, cudaFuncAttributeMaxDynamicSharedMemorySize, MMASM64);
    cudaFuncSetAttribute(attn_mma_kernel,      cudaFuncAttributeMaxDynamicSharedMemorySize, ATTSM);

    float* ws = nullptr;
    cudaGetSymbolAddress((void**)&ws, g_ws);
    __half* hf = nullptr;
    cudaGetSymbolAddress((void**)&hf, g_hf);

    float* patch_emb = ws + OFF_PATCH;
    float* tmp       = ws + OFF_TMP;
    float* q         = ws + OFF_Q;
    float* att       = ws + OFF_ATT;
    float* qproj     = ws + OFF_QP;
    float* pproj     = ws + OFF_PP;
    float* kvb       = ws + OFF_KVB;

    __half* qh  = hf + HF_QH;
    __half* l1h = hf + HF_L1H;
    __half* cxh = hf + HF_CXH;
    __half* fh  = hf + HF_FH;
    __half* qbh = hf + HF_QBH;
    __half* kva = hf + HF_KVA;
    __half* pfh = hf + HF_PFH;
    __half* peh = hf + HF_PEH;
    __half* pch = hf + HF_PCH;

    // ---- merged weight-convert + prep ----
    CTable ct;
    int wblk;
    {
        int seg = 0, boff = 0;
        auto add = [&](const float* src, size_t ho, int count) {
            ct.seg[seg] = { src, hf + ho, boff };
            boff += count / 1024;
            seg++;
        };
        for (int l = 0; l < NL; l++)
            add(in_proj_w + (size_t)l * 3 * D * D, HF_WQ + (size_t)l * D * D, D * D);
        for (int l = 0; l < NL; l++)
            add(out_w + (size_t)l * D * D, HF_WO + (size_t)l * D * D, D * D);
        for (int l = 0; l < NL; l++)
            add(ff1_w + (size_t)l * 4 * D * D, HF_F1 + (size_t)l * 4 * D * D, 4 * D * D);
        for (int l = 0; l < NL; l++)
            add(ff2_w + (size_t)l * 4 * D * D, HF_F2 + (size_t)l * 4 * D * D, 4 * D * D);
        add(head_w1, HF_HD, HALF * D);
        add(patch_proj_w, HF_WP, D * FD);
        add(pe_proj_w, HF_WE, D * D);
        for (int l = 0; l < NL; l++)
            add(in_proj_w + (size_t)l * 3 * D * D + D * D, HF_WK + (size_t)l * 2 * D * D, 2 * D * D);
        wblk = boff;
    }
    wprep_kernel<<<wblk + 4792, 256>>>(ct, wblk, patch_features, patch_coords,
                                       row_embed, col_embed, gene_queries, in_proj_b,
                                       pfh, peh, q, qh, kvb);

    const int MT128 = (MQ + 127) / 128;   // 32
    const int MTP   = (MP + 63) / 64;     // 7

    auto GA = [](const __half* Ah, const __half* Wh,
                 const float* bias, const float* R,
                 float* Cf, __half* Ch,
                 int M, int N, int K, int act) {
        GArgs g;
        g.Ah = Ah; g.Wh = Wh; g.bias = bias; g.R = R;
        g.Cf = Cf; g.Ch = Ch;
        g.M = M; g.N = N; g.K = K; g.act = act; g.ntx = N / 64;
        return g;
    };

    // ---- Stage A ----
    mma_gemm_kernel<64><<<dim3(D / 64, MTP), 256, MMASM64>>>(
        GA(pfh, hf + HF_WP, patch_proj_b, nullptr, tmp, nullptr, MP, D, FD, 0));
    ln_kernel<<<(MP + 7) / 8, 256>>>(tmp, nullptr, patch_ln_g, patch_ln_b, patch_emb,
                                     nullptr, MP);
    mma_gemm_kernel<64><<<dim3(D / 64, MTP), 256, MMASM64>>>(
        GA(peh, hf + HF_WE, pe_proj_b, patch_emb, nullptr, pch, MP, D, D, 0));

    // ---- KV for all layers + patch-side head projection ----
    {
        GArgs gkva = GA(pch, hf + HF_WK, kvb, nullptr, nullptr, kva, MP, NL * 2 * D, D, 0);
        GArgs gpp  = GA(pch, hf + HF_HD, nullptr, nullptr, pproj, nullptr, MP, HALF, D, 0);
        const int split = gkva.ntx * MTP;
        const int tot   = split + gpp.ntx * MTP;
        mma_gemm_dual_kernel<<<tot, 256, MMASM64>>>(gkva, gpp, split);
    }

    // ---- Stage B ----
    for (int l = 0; l < NL; l++) {
        const float* bq = in_proj_b + (size_t)l * 3 * D;
        mma_gemm_kernel<128><<<dim3(D / 64, MT128), 256, MMASM128>>>(
            GA(qh, hf + HF_WQ + (size_t)l * D * D, bq, nullptr,
               nullptr, qbh, MQ, D, D, 0));
        attn_mma_kernel<<<dim3(B * H, 32), 256, ATTSM>>>(
            qbh, kva + l * 2 * D, cxh, NL * 2 * D);
        mma_gemm_kernel<128><<<dim3(D / 64, MT128), 256, MMASM128>>>(
            GA(cxh, hf + HF_WO + (size_t)l * D * D, out_b + (size_t)l * D, q,
               att, nullptr, MQ, D, D, 0));
        ln_kernel<<<(MQ + 7) / 8, 256>>>(att, nullptr, ln1_g + (size_t)l * D, ln1_b + (size_t)l * D,
                                         q, l1h, MQ);
        mma_gemm_kernel<128><<<dim3(4 * D / 64, MT128), 256, MMASM128>>>(
            GA(l1h, hf + HF_F1 + (size_t)l * 4 * D * D, ff1_b + (size_t)l * 4 * D, nullptr,
               nullptr, fh, MQ, 4 * D, D, 1));
        mma_gemm_kernel<128><<<dim3(D / 64, MT128), 256, MMASM128>>>(
            GA(fh, hf + HF_F2 + (size_t)l * 4 * D * D, ff2_b + (size_t)l * D, q,
               att, nullptr, MQ, D, 4 * D, 0));
        ln_kernel<<<(MQ + 7) / 8, 256>>>(att, nullptr, ln2_g + (size_t)l * D, ln2_b + (size_t)l * D,
                                         q, qh, MQ);
    }

    // ---- Stage C ----
    mma_gemm_kernel<128><<<dim3(HALF / 64, MT128), 256, MMASM128>>>(
        GA(qh, hf + HF_HD, head_b1, nullptr, qproj, nullptr, MQ, HALF, D, 0));
    head_kernel<<<dim3(G / 8, MP / 8), 256>>>(qproj, pproj, out);
}